// round 1
// baseline (speedup 1.0000x reference)
#include <cuda_runtime.h>

// Problem constants
#define B_ 2
#define T_ 4096
#define C_ 2048
#define H_ 16
#define D_ 32

// Scratch (no allocations allowed -> __device__ globals)
__device__ float g_q[(size_t)B_ * T_ * H_ * D_];   // [B,T,H,D]  16.8 MB
__device__ float g_k[(size_t)B_ * T_ * D_];        // [B,T,D]
__device__ float g_w[(size_t)B_ * T_ * H_];        // [B,T,H]

// ---------------------------------------------------------------------------
// Projection GEMM: out[M,N] = X[M,C] @ W[N,C]^T      (M = B_*T_ = 8192, C = 2048)
// BM=128 rows, BN columns per block, 256 threads, TM=8 x TN per thread.
// Smem tiles stored k-major ([k][m]) with +4 padding for conflict-free LDS.128.
// ---------------------------------------------------------------------------
template <int BN, int TN>
__global__ __launch_bounds__(256)
void proj_kernel(const float* __restrict__ X, const float* __restrict__ W,
                 float* __restrict__ out, int N)
{
    constexpr int BM = 128;
    constexpr int BK = 16;
    __shared__ float Xs[BK][BM + 4];
    __shared__ float Ws[BK][BN + 4];

    const int tid = threadIdx.x;
    const int tx  = tid & 15;
    const int ty  = tid >> 4;
    const int m0  = blockIdx.y * BM;
    const int n0  = blockIdx.x * BN;

    float acc[8][TN];
#pragma unroll
    for (int i = 0; i < 8; i++) {
#pragma unroll
        for (int j = 0; j < TN; j++) acc[i][j] = 0.f;
    }

    // X loader mapping: each thread loads 8 consecutive k for one m-row
    const int xrow = tid >> 1;
    const int xk   = (tid & 1) * 8;

#pragma unroll 1
    for (int k0 = 0; k0 < C_; k0 += BK) {
        // --- load X tile (128 x 16), transpose into Xs[k][m] ---
        {
            const float* xp = X + (size_t)(m0 + xrow) * C_ + k0 + xk;
            float4 xa = *(const float4*)(xp);
            float4 xb = *(const float4*)(xp + 4);
            Xs[xk + 0][xrow] = xa.x; Xs[xk + 1][xrow] = xa.y;
            Xs[xk + 2][xrow] = xa.z; Xs[xk + 3][xrow] = xa.w;
            Xs[xk + 4][xrow] = xb.x; Xs[xk + 5][xrow] = xb.y;
            Xs[xk + 6][xrow] = xb.z; Xs[xk + 7][xrow] = xb.w;
        }
        // --- load W tile (BN x 16), transpose into Ws[k][n] ---
#pragma unroll
        for (int e = tid; e < BN * BK; e += 256) {
            int wr = e >> 4;
            int wk = e & 15;
            Ws[wk][wr] = W[(size_t)(n0 + wr) * C_ + k0 + wk];
        }
        __syncthreads();

#pragma unroll 4
        for (int kk = 0; kk < BK; kk++) {
            float4 a0 = *(const float4*)&Xs[kk][ty * 4];
            float4 a1 = *(const float4*)&Xs[kk][64 + ty * 4];
            float av[8] = {a0.x, a0.y, a0.z, a0.w, a1.x, a1.y, a1.z, a1.w};
            float bv[TN];
            if constexpr (TN == 8) {
                float4 b0 = *(const float4*)&Ws[kk][tx * 4];
                float4 b1 = *(const float4*)&Ws[kk][64 + tx * 4];
                bv[0] = b0.x; bv[1] = b0.y; bv[2] = b0.z; bv[3] = b0.w;
                bv[4] = b1.x; bv[5] = b1.y; bv[6] = b1.z; bv[7] = b1.w;
            } else if constexpr (TN == 2) {
                bv[0] = Ws[kk][tx];
                bv[1] = Ws[kk][16 + tx];
            } else {
                bv[0] = Ws[kk][tx];
            }
#pragma unroll
            for (int i = 0; i < 8; i++) {
#pragma unroll
                for (int j = 0; j < TN; j++) acc[i][j] += av[i] * bv[j];
            }
        }
        __syncthreads();
    }

#pragma unroll
    for (int i = 0; i < 8; i++) {
        int mr = (i < 4) ? (ty * 4 + i) : (64 + ty * 4 + i - 4);
#pragma unroll
        for (int j = 0; j < TN; j++) {
            int nc;
            if constexpr (TN == 8)      nc = (j < 4) ? (tx * 4 + j) : (64 + tx * 4 + j - 4);
            else if constexpr (TN == 2) nc = (j == 0) ? tx : (16 + tx);
            else                        nc = tx;
            out[(size_t)(m0 + mr) * N + n0 + nc] = acc[i][j];
        }
    }
}

// ---------------------------------------------------------------------------
// Fused scores + importance:
//   out[b,q,k] = sum_h w[b,q,h] * relu( dot_d(q[b,q,h,d], k[b,k,d]) )
// Block computes a 128x128 (q,k) tile for one batch. K tile + w tile loaded
// once; Q_h tile reloaded per head (16 heads). 8x8 register blocking.
// ---------------------------------------------------------------------------
__global__ __launch_bounds__(256)
void fused_kernel(const float* __restrict__ qg, const float* __restrict__ kg,
                  const float* __restrict__ wg, float* __restrict__ out)
{
    __shared__ float Qs[D_][132];   // [d][q-row]
    __shared__ float Ks[D_][132];   // [d][k-row]
    __shared__ float Wsm[H_][132];  // [h][q-row]

    const int tid = threadIdx.x;
    const int tx  = tid & 15;
    const int ty  = tid >> 4;
    const int b   = blockIdx.z;
    const int q0  = blockIdx.y * 128;
    const int k0  = blockIdx.x * 128;

    const int lrow = tid >> 1;        // 0..127
    const int ld   = (tid & 1) * 16;  // 0 or 16

    // --- K tile: 128 rows x 32 d ---
    {
        const float* kp = kg + (size_t)(b * T_ + k0 + lrow) * D_ + ld;
        float4 v0 = *(const float4*)(kp);
        float4 v1 = *(const float4*)(kp + 4);
        float4 v2 = *(const float4*)(kp + 8);
        float4 v3 = *(const float4*)(kp + 12);
        Ks[ld + 0][lrow] = v0.x;  Ks[ld + 1][lrow] = v0.y;
        Ks[ld + 2][lrow] = v0.z;  Ks[ld + 3][lrow] = v0.w;
        Ks[ld + 4][lrow] = v1.x;  Ks[ld + 5][lrow] = v1.y;
        Ks[ld + 6][lrow] = v1.z;  Ks[ld + 7][lrow] = v1.w;
        Ks[ld + 8][lrow] = v2.x;  Ks[ld + 9][lrow] = v2.y;
        Ks[ld + 10][lrow] = v2.z; Ks[ld + 11][lrow] = v2.w;
        Ks[ld + 12][lrow] = v3.x; Ks[ld + 13][lrow] = v3.y;
        Ks[ld + 14][lrow] = v3.z; Ks[ld + 15][lrow] = v3.w;
    }
    // --- w tile: 128 rows x 16 heads ---
#pragma unroll
    for (int e = tid; e < 128 * H_; e += 256) {
        int r = e >> 4;
        int h = e & 15;
        Wsm[h][r] = wg[(size_t)(b * T_ + q0 + r) * H_ + h];
    }

    float acc[8][8];
#pragma unroll
    for (int i = 0; i < 8; i++) {
#pragma unroll
        for (int j = 0; j < 8; j++) acc[i][j] = 0.f;
    }

    __syncthreads();

#pragma unroll 1
    for (int h = 0; h < H_; h++) {
        // --- load Q_h tile: 128 rows x 32 d ---
        {
            const float* qp = qg + ((size_t)(b * T_ + q0 + lrow) * H_ + h) * D_ + ld;
            float4 v0 = *(const float4*)(qp);
            float4 v1 = *(const float4*)(qp + 4);
            float4 v2 = *(const float4*)(qp + 8);
            float4 v3 = *(const float4*)(qp + 12);
            Qs[ld + 0][lrow] = v0.x;  Qs[ld + 1][lrow] = v0.y;
            Qs[ld + 2][lrow] = v0.z;  Qs[ld + 3][lrow] = v0.w;
            Qs[ld + 4][lrow] = v1.x;  Qs[ld + 5][lrow] = v1.y;
            Qs[ld + 6][lrow] = v1.z;  Qs[ld + 7][lrow] = v1.w;
            Qs[ld + 8][lrow] = v2.x;  Qs[ld + 9][lrow] = v2.y;
            Qs[ld + 10][lrow] = v2.z; Qs[ld + 11][lrow] = v2.w;
            Qs[ld + 12][lrow] = v3.x; Qs[ld + 13][lrow] = v3.y;
            Qs[ld + 14][lrow] = v3.z; Qs[ld + 15][lrow] = v3.w;
        }
        __syncthreads();

        float s[8][8];
#pragma unroll
        for (int i = 0; i < 8; i++) {
#pragma unroll
            for (int j = 0; j < 8; j++) s[i][j] = 0.f;
        }

#pragma unroll 8
        for (int d = 0; d < D_; d++) {
            float4 a0 = *(const float4*)&Qs[d][ty * 4];
            float4 a1 = *(const float4*)&Qs[d][64 + ty * 4];
            float4 b0 = *(const float4*)&Ks[d][tx * 4];
            float4 b1 = *(const float4*)&Ks[d][64 + tx * 4];
            float av[8] = {a0.x, a0.y, a0.z, a0.w, a1.x, a1.y, a1.z, a1.w};
            float bv[8] = {b0.x, b0.y, b0.z, b0.w, b1.x, b1.y, b1.z, b1.w};
#pragma unroll
            for (int i = 0; i < 8; i++) {
#pragma unroll
                for (int j = 0; j < 8; j++) s[i][j] += av[i] * bv[j];
            }
        }

#pragma unroll
        for (int i = 0; i < 8; i++) {
            int qr = (i < 4) ? (ty * 4 + i) : (64 + ty * 4 + i - 4);
            float wv = Wsm[h][qr];
#pragma unroll
            for (int j = 0; j < 8; j++)
                acc[i][j] += wv * fmaxf(s[i][j], 0.f);
        }
        __syncthreads();  // Qs free for next head
    }

    // --- epilogue: write 128x128 tile ---
#pragma unroll
    for (int i = 0; i < 8; i++) {
        int qr = (i < 4) ? (ty * 4 + i) : (64 + ty * 4 + i - 4);
        float* op = out + (size_t)(b * T_ + q0 + qr) * T_ + k0;
        float4 o0 = make_float4(acc[i][0], acc[i][1], acc[i][2], acc[i][3]);
        float4 o1 = make_float4(acc[i][4], acc[i][5], acc[i][6], acc[i][7]);
        *(float4*)(op + tx * 4) = o0;
        *(float4*)(op + 64 + tx * 4) = o1;
    }
}

// ---------------------------------------------------------------------------
extern "C" void kernel_launch(void* const* d_in, const int* in_sizes, int n_in,
                              void* d_out, int out_size)
{
    (void)in_sizes; (void)n_in; (void)out_size;
    const float* x  = (const float*)d_in[0];
    const float* Wq = (const float*)d_in[1];
    const float* Wk = (const float*)d_in[2];
    const float* Ww = (const float*)d_in[3];
    float* out = (float*)d_out;

    float *qp = nullptr, *kp = nullptr, *wp = nullptr;
    cudaGetSymbolAddress((void**)&qp, g_q);
    cudaGetSymbolAddress((void**)&kp, g_k);
    cudaGetSymbolAddress((void**)&wp, g_w);

    // Projections: M = 8192 rows
    proj_kernel<128, 8><<<dim3(512 / 128, (B_ * T_) / 128), 256>>>(x, Wq, qp, H_ * D_);
    proj_kernel<32, 2><<<dim3(1, (B_ * T_) / 128), 256>>>(x, Wk, kp, D_);
    proj_kernel<16, 1><<<dim3(1, (B_ * T_) / 128), 256>>>(x, Ww, wp, H_);

    // Fused scores + importance
    fused_kernel<<<dim3(T_ / 128, T_ / 128, B_), 256>>>(qp, kp, wp, out);
}

// round 4
// speedup vs baseline: 2.1722x; 2.1722x over previous
#include <cuda_runtime.h>
#include <cuda_bf16.h>
#include <cstdint>

// Problem constants
#define B_ 2
#define T_ 4096
#define C_ 2048
#define H_ 16
#define D_ 32

// Scratch (no allocations allowed -> __device__ globals)
__device__ float g_q[(size_t)B_ * T_ * H_ * D_];   // [B,T,H,D] == [8192][512]
__device__ float g_k[(size_t)B_ * T_ * D_];        // [B,T,D]   == [8192][32]
__device__ float g_w[(size_t)B_ * T_ * H_];        // [B,T,H]   == [8192][16]

// ===========================================================================
// Helpers (base sm_103-safe: ldmatrix + mma.sync only, NO tcgen05)
// ===========================================================================
__device__ __forceinline__ uint32_t smem_u32(const void* p) {
    uint32_t a;
    asm("{ .reg .u64 t; cvta.to.shared.u64 t, %1; cvt.u32.u64 %0, t; }"
        : "=r"(a) : "l"(p));
    return a;
}

__device__ __forceinline__ uint32_t sw128(uint32_t o) { return o ^ ((o >> 3) & 0x70); }

__device__ __forceinline__ void ldsm4(uint32_t* r, uint32_t a) {
    asm volatile("ldmatrix.sync.aligned.m8n8.x4.shared.b16 {%0,%1,%2,%3}, [%4];"
                 : "=r"(r[0]), "=r"(r[1]), "=r"(r[2]), "=r"(r[3]) : "r"(a));
}

__device__ __forceinline__ void mma_bf16(float* d, const uint32_t* a, const uint32_t* b) {
    asm volatile(
        "mma.sync.aligned.m16n8k16.row.col.f32.bf16.bf16.f32 "
        "{%0,%1,%2,%3}, {%4,%5,%6,%7}, {%8,%9}, {%0,%1,%2,%3};"
        : "+f"(d[0]), "+f"(d[1]), "+f"(d[2]), "+f"(d[3])
        : "r"(a[0]), "r"(a[1]), "r"(a[2]), "r"(a[3]), "r"(b[0]), "r"(b[1]));
}

__device__ __forceinline__ uint32_t pack2bf(float x, float y) {
    __nv_bfloat16 bx = __float2bfloat16_rn(x), by = __float2bfloat16_rn(y);
    return ((uint32_t)__bfloat16_as_ushort(by) << 16) | (uint32_t)__bfloat16_as_ushort(bx);
}

// 4 f32 -> [hi | lo] split-bf16 into a 128B-per-row SW128 tile.
// Row layout (64 bf16): elements 0-31 = hi, 32-63 = lo (bytes 0-63 / 64-127).
__device__ __forceinline__ void cvt_store4(char* tile, uint32_t base_off, float4 v) {
    __nv_bfloat16 bx = __float2bfloat16_rn(v.x);
    __nv_bfloat16 by = __float2bfloat16_rn(v.y);
    __nv_bfloat16 bz = __float2bfloat16_rn(v.z);
    __nv_bfloat16 bw = __float2bfloat16_rn(v.w);
    uint32_t hi0 = ((uint32_t)__bfloat16_as_ushort(by) << 16) | __bfloat16_as_ushort(bx);
    uint32_t hi1 = ((uint32_t)__bfloat16_as_ushort(bw) << 16) | __bfloat16_as_ushort(bz);
    uint32_t lo0 = pack2bf(v.x - __bfloat162float(bx), v.y - __bfloat162float(by));
    uint32_t lo1 = pack2bf(v.z - __bfloat162float(bz), v.w - __bfloat162float(bw));
    *(uint2*)(tile + sw128(base_off))      = make_uint2(hi0, hi1);
    *(uint2*)(tile + sw128(base_off + 64)) = make_uint2(lo0, lo1);
}

// 3-term split product schedule: frag index 0,1 = hi k-steps; 2,3 = lo k-steps.
//   s = a_hi*b_hi + a_hi*b_lo + a_lo*b_hi
__device__ __forceinline__ void mma_split3_n16(float* s0, float* s1,
                                               const uint32_t af[4][4],
                                               const uint32_t bf[4][4]) {
    const int PA[6] = {0, 1, 0, 1, 2, 3};
    const int PB[6] = {0, 1, 2, 3, 0, 1};
#pragma unroll
    for (int p = 0; p < 6; p++) {
        mma_bf16(s0, af[PA[p]], &bf[PB[p]][0]);
        mma_bf16(s1, af[PA[p]], &bf[PB[p]][2]);
    }
}

// ===========================================================================
// Fused scores+importance on mma.sync:
//   out[b,q,k] = sum_h w[b,q,h] * relu( dot_d(q,k) )
// CTA = 128(q) x 128(k), 8 warps in 4(m) x 2(n).
// K fragments (hi+lo) register-resident across all 16 heads.
// ===========================================================================
__global__ void __launch_bounds__(256, 1)
fused_mma_kernel(const float* __restrict__ qg, const float* __restrict__ kg,
                 const float* __restrict__ wg, float* __restrict__ out)
{
    __shared__ __align__(1024) char Ks[128 * 128];   // 16KB
    __shared__ __align__(1024) char Qs[128 * 128];   // 16KB
    __shared__ float w_s[128 * H_];                  // 8KB

    const int tid  = threadIdx.x;
    const int wid  = tid >> 5;
    const int lane = tid & 31;
    const int b  = blockIdx.z;
    const int q0 = blockIdx.y * 128;
    const int k0 = blockIdx.x * 128;
    const int m0 = (wid & 3) * 32;
    const int n0 = (wid >> 2) * 64;

    const int r  = tid >> 1;          // loader row 0..127
    const int ce = (tid & 1) * 16;    // loader col base (f32 elements)

    // --- K tile: 128 rows x 32 f32 -> split-bf16 ext tile ---
    {
        const float* kp = kg + (size_t)(b * T_ + k0 + r) * D_ + ce;
#pragma unroll
        for (int i = 0; i < 4; i++) {
            float4 v = *(const float4*)(kp + 4 * i);
            cvt_store4(Ks, (uint32_t)(r * 128 + (ce + 4 * i) * 2), v);
        }
    }
    // --- w tile ---
    {
        const float4* wp = (const float4*)(wg + (size_t)(b * T_ + q0) * H_);
        ((float4*)w_s)[tid * 2 + 0] = wp[tid * 2 + 0];
        ((float4*)w_s)[tid * 2 + 1] = wp[tid * 2 + 1];
    }
    __syncthreads();

    // --- K fragments resident in registers: bfr[ntPair][seg][4]
    //     seg 0,1 = hi k-steps; 2,3 = lo k-steps ---
    uint32_t bfr[4][4][4];
    {
        const uint32_t ksb  = smem_u32(Ks);
        const int brow = (lane & 7) + ((lane & 16) >> 1);
        const int bseg = (lane >> 3) & 1;
#pragma unroll
        for (int ntp = 0; ntp < 4; ntp++)
#pragma unroll
            for (int ks = 0; ks < 4; ks++) {
                uint32_t ad = ksb + sw128((uint32_t)((n0 + ntp * 16 + brow) * 128 +
                                                     ks * 32 + bseg * 16));
                ldsm4(bfr[ntp][ks], ad);
            }
    }

    // --- A (Q) ldmatrix addresses, fixed across heads ---
    uint32_t aaddr[2][4];
    {
        const uint32_t qsb = smem_u32(Qs);
        const int arow = lane & 15;
        const int aseg = lane >> 4;
#pragma unroll
        for (int mt = 0; mt < 2; mt++)
#pragma unroll
            for (int ks = 0; ks < 4; ks++)
                aaddr[mt][ks] = qsb + sw128((uint32_t)((m0 + mt * 16 + arow) * 128 +
                                                       ks * 32 + aseg * 16));
    }

    float acc[2][8][4];
#pragma unroll
    for (int mt = 0; mt < 2; mt++)
#pragma unroll
        for (int nt = 0; nt < 8; nt++)
#pragma unroll
            for (int c = 0; c < 4; c++) acc[mt][nt][c] = 0.f;

    // --- prefetch Q head 0 ---
    const float* qp0 = qg + ((size_t)(b * T_ + q0 + r) * H_ + 0) * D_ + ce;
    float4 qv[4];
#pragma unroll
    for (int i = 0; i < 4; i++) qv[i] = *(const float4*)(qp0 + 4 * i);

    const int wrow0 = m0 + (lane >> 2);

#pragma unroll 1
    for (int h = 0; h < H_; h++) {
        // store Q_h ext tile
#pragma unroll
        for (int i = 0; i < 4; i++)
            cvt_store4(Qs, (uint32_t)(r * 128 + (ce + 4 * i) * 2), qv[i]);
        __syncthreads();

        // prefetch next head
        if (h < H_ - 1) {
            const float* qp = qp0 + (size_t)(h + 1) * D_;
#pragma unroll
            for (int i = 0; i < 4; i++) qv[i] = *(const float4*)(qp + 4 * i);
        }

#pragma unroll
        for (int mt = 0; mt < 2; mt++) {
            uint32_t af[4][4];
#pragma unroll
            for (int ks = 0; ks < 4; ks++) ldsm4(af[ks], aaddr[mt][ks]);

            const float wv0 = w_s[(wrow0 + mt * 16) * H_ + h];
            const float wv1 = w_s[(wrow0 + mt * 16 + 8) * H_ + h];

#pragma unroll
            for (int ntp = 0; ntp < 4; ntp++) {
                float s0[4] = {0.f, 0.f, 0.f, 0.f};
                float s1[4] = {0.f, 0.f, 0.f, 0.f};
                mma_split3_n16(s0, s1, af, bfr[ntp]);
                acc[mt][ntp * 2][0] += wv0 * fmaxf(s0[0], 0.f);
                acc[mt][ntp * 2][1] += wv0 * fmaxf(s0[1], 0.f);
                acc[mt][ntp * 2][2] += wv1 * fmaxf(s0[2], 0.f);
                acc[mt][ntp * 2][3] += wv1 * fmaxf(s0[3], 0.f);
                acc[mt][ntp * 2 + 1][0] += wv0 * fmaxf(s1[0], 0.f);
                acc[mt][ntp * 2 + 1][1] += wv0 * fmaxf(s1[1], 0.f);
                acc[mt][ntp * 2 + 1][2] += wv1 * fmaxf(s1[2], 0.f);
                acc[mt][ntp * 2 + 1][3] += wv1 * fmaxf(s1[3], 0.f);
            }
        }
        __syncthreads();
    }

    // --- epilogue ---
#pragma unroll
    for (int mt = 0; mt < 2; mt++)
#pragma unroll
        for (int rp = 0; rp < 2; rp++) {
            const int row = q0 + m0 + mt * 16 + (lane >> 2) + rp * 8;
            float* op = out + (size_t)(b * T_ + row) * T_ + k0 + n0 + (lane & 3) * 2;
#pragma unroll
            for (int nt = 0; nt < 8; nt++)
                *(float2*)(op + nt * 8) =
                    make_float2(acc[mt][nt][rp * 2], acc[mt][nt][rp * 2 + 1]);
        }
}

// ===========================================================================
// Q projection on mma.sync: out[8192,512] = X[8192,2048] @ Wq[512,2048]^T
// CTA = 128x128, 8 warps 4x2, 64 k-iters of real-k 32.
// ===========================================================================
__global__ void __launch_bounds__(256, 1)
qproj_mma_kernel(const float* __restrict__ X, const float* __restrict__ W,
                 float* __restrict__ out)
{
    __shared__ __align__(1024) char Xs[128 * 128];
    __shared__ __align__(1024) char Wsm[128 * 128];

    const int tid  = threadIdx.x;
    const int wid  = tid >> 5;
    const int lane = tid & 31;
    const int m0c = blockIdx.y * 128;
    const int n0c = blockIdx.x * 128;
    const int m0  = (wid & 3) * 32;
    const int n0  = (wid >> 2) * 64;
    const int r   = tid >> 1;
    const int ce  = (tid & 1) * 16;

    float acc[2][8][4];
#pragma unroll
    for (int mt = 0; mt < 2; mt++)
#pragma unroll
        for (int nt = 0; nt < 8; nt++)
#pragma unroll
            for (int c = 0; c < 4; c++) acc[mt][nt][c] = 0.f;

    const float* xp0 = X + (size_t)(m0c + r) * C_ + ce;
    const float* wp0 = W + (size_t)(n0c + r) * C_ + ce;
    float4 xv[4], wv[4];
#pragma unroll
    for (int i = 0; i < 4; i++) {
        xv[i] = *(const float4*)(xp0 + 4 * i);
        wv[i] = *(const float4*)(wp0 + 4 * i);
    }

    uint32_t aaddr[2][4], baddr[4][4];
    {
        const uint32_t xsb = smem_u32(Xs), wsb = smem_u32(Wsm);
        const int arow = lane & 15, aseg = lane >> 4;
        const int brow = (lane & 7) + ((lane & 16) >> 1);
        const int bseg = (lane >> 3) & 1;
#pragma unroll
        for (int t = 0; t < 4; t++) {
#pragma unroll
            for (int ks = 0; ks < 4; ks++) {
                if (t < 2)
                    aaddr[t][ks] = xsb + sw128((uint32_t)((m0 + t * 16 + arow) * 128 +
                                                          ks * 32 + aseg * 16));
                baddr[t][ks] = wsb + sw128((uint32_t)((n0 + t * 16 + brow) * 128 +
                                                      ks * 32 + bseg * 16));
            }
        }
    }

#pragma unroll 1
    for (int it = 0; it < 64; it++) {
#pragma unroll
        for (int i = 0; i < 4; i++) {
            cvt_store4(Xs, (uint32_t)(r * 128 + (ce + 4 * i) * 2), xv[i]);
            cvt_store4(Wsm, (uint32_t)(r * 128 + (ce + 4 * i) * 2), wv[i]);
        }
        __syncthreads();

        if (it < 63) {
            const float* xp = xp0 + (size_t)(it + 1) * 32;
            const float* wp = wp0 + (size_t)(it + 1) * 32;
#pragma unroll
            for (int i = 0; i < 4; i++) {
                xv[i] = *(const float4*)(xp + 4 * i);
                wv[i] = *(const float4*)(wp + 4 * i);
            }
        }

        uint32_t bfr[4][4][4];
#pragma unroll
        for (int ntp = 0; ntp < 4; ntp++)
#pragma unroll
            for (int ks = 0; ks < 4; ks++) ldsm4(bfr[ntp][ks], baddr[ntp][ks]);

#pragma unroll
        for (int mt = 0; mt < 2; mt++) {
            uint32_t af[4][4];
#pragma unroll
            for (int ks = 0; ks < 4; ks++) ldsm4(af[ks], aaddr[mt][ks]);
#pragma unroll
            for (int ntp = 0; ntp < 4; ntp++)
                mma_split3_n16(acc[mt][ntp * 2], acc[mt][ntp * 2 + 1], af, bfr[ntp]);
        }
        __syncthreads();
    }

#pragma unroll
    for (int mt = 0; mt < 2; mt++)
#pragma unroll
        for (int rp = 0; rp < 2; rp++) {
            const int row = m0c + m0 + mt * 16 + (lane >> 2) + rp * 8;
            float* op = out + (size_t)row * (H_ * D_) + n0c + n0 + (lane & 3) * 2;
#pragma unroll
            for (int nt = 0; nt < 8; nt++)
                *(float2*)(op + nt * 8) =
                    make_float2(acc[mt][nt][rp * 2], acc[mt][nt][rp * 2 + 1]);
        }
}

// ===========================================================================
// K + W projections combined: [8192,32] and [8192,16]  (48 output cols)
// CTA = 128 rows, 8 warps each 16(m) x 48(n). 64 k-iters.
// ===========================================================================
__global__ void __launch_bounds__(256, 1)
kwproj_mma_kernel(const float* __restrict__ X, const float* __restrict__ Wk,
                  const float* __restrict__ Ww, float* __restrict__ kout,
                  float* __restrict__ wout)
{
    __shared__ __align__(1024) char Xs[128 * 128];
    __shared__ __align__(1024) char Wsm[48 * 128];

    const int tid  = threadIdx.x;
    const int wid  = tid >> 5;
    const int lane = tid & 31;
    const int m0c = blockIdx.x * 128;
    const int m0  = wid * 16;
    const int r   = tid >> 1;
    const int ce  = (tid & 1) * 16;

    float acc[6][4];
#pragma unroll
    for (int nt = 0; nt < 6; nt++)
#pragma unroll
        for (int c = 0; c < 4; c++) acc[nt][c] = 0.f;

    const float* xp0 = X + (size_t)(m0c + r) * C_ + ce;
    const bool wvalid = (tid < 96);
    const float* wp0 = wvalid ? ((r < 32) ? (Wk + (size_t)r * C_ + ce)
                                          : (Ww + (size_t)(r - 32) * C_ + ce))
                              : nullptr;

    float4 xv[4], wv[4];
#pragma unroll
    for (int i = 0; i < 4; i++) {
        xv[i] = *(const float4*)(xp0 + 4 * i);
        wv[i] = wvalid ? *(const float4*)(wp0 + 4 * i) : make_float4(0, 0, 0, 0);
    }

    uint32_t aaddr[4], baddr[3][4];
    {
        const uint32_t xsb = smem_u32(Xs), wsb = smem_u32(Wsm);
        const int arow = lane & 15, aseg = lane >> 4;
        const int brow = (lane & 7) + ((lane & 16) >> 1);
        const int bseg = (lane >> 3) & 1;
#pragma unroll
        for (int ks = 0; ks < 4; ks++) {
            aaddr[ks] = xsb + sw128((uint32_t)((m0 + arow) * 128 + ks * 32 + aseg * 16));
#pragma unroll
            for (int ntp = 0; ntp < 3; ntp++)
                baddr[ntp][ks] = wsb + sw128((uint32_t)((ntp * 16 + brow) * 128 +
                                                        ks * 32 + bseg * 16));
        }
    }

#pragma unroll 1
    for (int it = 0; it < 64; it++) {
#pragma unroll
        for (int i = 0; i < 4; i++)
            cvt_store4(Xs, (uint32_t)(r * 128 + (ce + 4 * i) * 2), xv[i]);
        if (wvalid) {
#pragma unroll
            for (int i = 0; i < 4; i++)
                cvt_store4(Wsm, (uint32_t)(r * 128 + (ce + 4 * i) * 2), wv[i]);
        }
        __syncthreads();

        if (it < 63) {
            const float* xp = xp0 + (size_t)(it + 1) * 32;
#pragma unroll
            for (int i = 0; i < 4; i++) xv[i] = *(const float4*)(xp + 4 * i);
            if (wvalid) {
                const float* wp = wp0 + (size_t)(it + 1) * 32;
#pragma unroll
                for (int i = 0; i < 4; i++) wv[i] = *(const float4*)(wp + 4 * i);
            }
        }

        uint32_t af[4][4];
#pragma unroll
        for (int ks = 0; ks < 4; ks++) ldsm4(af[ks], aaddr[ks]);

#pragma unroll
        for (int ntp = 0; ntp < 3; ntp++) {
            uint32_t bfr[4][4];
#pragma unroll
            for (int ks = 0; ks < 4; ks++) ldsm4(bfr[ks], baddr[ntp][ks]);
            mma_split3_n16(acc[ntp * 2], acc[ntp * 2 + 1], af, bfr);
        }
        __syncthreads();
    }

#pragma unroll
    for (int rp = 0; rp < 2; rp++) {
        const int row = m0c + m0 + (lane >> 2) + rp * 8;
#pragma unroll
        for (int nt = 0; nt < 6; nt++) {
            const int col = nt * 8 + (lane & 3) * 2;
            float2 v = make_float2(acc[nt][rp * 2], acc[nt][rp * 2 + 1]);
            if (nt < 4)
                *(float2*)(kout + (size_t)row * D_ + col) = v;
            else
                *(float2*)(wout + (size_t)row * H_ + (col - 32)) = v;
        }
    }
}

// ===========================================================================
extern "C" void kernel_launch(void* const* d_in, const int* in_sizes, int n_in,
                              void* d_out, int out_size)
{
    (void)in_sizes; (void)n_in; (void)out_size;
    const float* x  = (const float*)d_in[0];
    const float* Wq = (const float*)d_in[1];
    const float* Wk = (const float*)d_in[2];
    const float* Ww = (const float*)d_in[3];
    float* out = (float*)d_out;

    float *qp = nullptr, *kp = nullptr, *wp = nullptr;
    cudaGetSymbolAddress((void**)&qp, g_q);
    cudaGetSymbolAddress((void**)&kp, g_k);
    cudaGetSymbolAddress((void**)&wp, g_w);

    qproj_mma_kernel<<<dim3(4, 64), 256>>>(x, Wq, qp);
    kwproj_mma_kernel<<<64, 256>>>(x, Wk, Ww, kp, wp);
    fused_mma_kernel<<<dim3(T_ / 128, T_ / 128, B_), 256>>>(qp, kp, wp, out);
}

// round 5
// speedup vs baseline: 2.7441x; 1.2633x over previous
#include <cuda_runtime.h>
#include <cuda_bf16.h>
#include <cstdint>

// Problem constants
#define B_ 2
#define T_ 4096
#define C_ 2048
#define H_ 16
#define D_ 32

// ---------------------------------------------------------------------------
// Ext-bf16 tile format: a 128-row x 32-f32-col operand block is stored as
// 16384 bytes; logical (row r, ext col c in [0,64): c<32 = hi of d=c,
// c>=32 = lo of d=c-32) lives at byte offset sw128(r*128 + c*2).
// Gmem byte order == smem byte order -> plain 16B cp.async copies.
// ---------------------------------------------------------------------------
__device__ __align__(1024) char g_xext [(size_t)64 * 64 * 16384];  // [rowTile][kStep]
__device__ __align__(1024) char g_wqext[(size_t)4  * 64 * 16384];  // [nTile][kStep]
__device__ __align__(1024) char g_kwext[(size_t)64 * 6144];        // [kStep] 48 rows
__device__ __align__(1024) char g_qext [(size_t)64 * 16 * 16384];  // [qTile][head]
__device__ __align__(1024) char g_kext [(size_t)64 * 16384];       // [kTile]
__device__ __align__(1024) float g_w[(size_t)B_ * T_ * H_];        // [8192][16]

// ===========================================================================
// Helpers (base sm_103-safe: ldmatrix + mma.sync + cp.async)
// ===========================================================================
__device__ __forceinline__ uint32_t smem_u32(const void* p) {
    uint32_t a;
    asm("{ .reg .u64 t; cvta.to.shared.u64 t, %1; cvt.u32.u64 %0, t; }"
        : "=r"(a) : "l"(p));
    return a;
}

__device__ __forceinline__ uint32_t sw128(uint32_t o) { return o ^ ((o >> 3) & 0x70); }

__device__ __forceinline__ void ldsm4(uint32_t* r, uint32_t a) {
    asm volatile("ldmatrix.sync.aligned.m8n8.x4.shared.b16 {%0,%1,%2,%3}, [%4];"
                 : "=r"(r[0]), "=r"(r[1]), "=r"(r[2]), "=r"(r[3]) : "r"(a));
}

__device__ __forceinline__ void mma_bf16(float* d, const uint32_t* a, const uint32_t* b) {
    asm volatile(
        "mma.sync.aligned.m16n8k16.row.col.f32.bf16.bf16.f32 "
        "{%0,%1,%2,%3}, {%4,%5,%6,%7}, {%8,%9}, {%0,%1,%2,%3};"
        : "+f"(d[0]), "+f"(d[1]), "+f"(d[2]), "+f"(d[3])
        : "r"(a[0]), "r"(a[1]), "r"(a[2]), "r"(a[3]), "r"(b[0]), "r"(b[1]));
}

__device__ __forceinline__ void cp16(uint32_t s, const void* g) {
    asm volatile("cp.async.cg.shared.global [%0], [%1], 16;" :: "r"(s), "l"(g));
}
#define CP_COMMIT() asm volatile("cp.async.commit_group;" ::: "memory")
#define CP_WAIT(n)  asm volatile("cp.async.wait_group %0;" :: "n"(n) : "memory")

__device__ __forceinline__ uint32_t pack2bf(float x, float y) {
    __nv_bfloat16 bx = __float2bfloat16_rn(x), by = __float2bfloat16_rn(y);
    return ((uint32_t)__bfloat16_as_ushort(by) << 16) | (uint32_t)__bfloat16_as_ushort(bx);
}

// split two f32 into packed hi-pair and lo-pair
__device__ __forceinline__ void split2(float v0, float v1, uint32_t& hi, uint32_t& lo) {
    __nv_bfloat16 h0 = __float2bfloat16_rn(v0), h1 = __float2bfloat16_rn(v1);
    hi = ((uint32_t)__bfloat16_as_ushort(h1) << 16) | (uint32_t)__bfloat16_as_ushort(h0);
    lo = pack2bf(v0 - __bfloat162float(h0), v1 - __bfloat162float(h1));
}

// 4 f32 -> [hi | lo] split-bf16 into a tile (works for gmem or smem char*).
__device__ __forceinline__ void cvt_store4(char* tile, uint32_t base_off, float4 v) {
    uint32_t hi0, lo0, hi1, lo1;
    split2(v.x, v.y, hi0, lo0);
    split2(v.z, v.w, hi1, lo1);
    *(uint2*)(tile + sw128(base_off))      = make_uint2(hi0, hi1);
    *(uint2*)(tile + sw128(base_off + 64)) = make_uint2(lo0, lo1);
}

// 3-term split product: frag 0,1 = hi k-steps; 2,3 = lo k-steps.
//   s = a_hi*b_hi + a_hi*b_lo + a_lo*b_hi
__device__ __forceinline__ void mma_split3_n16(float* s0, float* s1,
                                               const uint32_t af[4][4],
                                               const uint32_t bf[4][4]) {
    const int PA[6] = {0, 1, 0, 1, 2, 3};
    const int PB[6] = {0, 1, 2, 3, 0, 1};
#pragma unroll
    for (int p = 0; p < 6; p++) {
        mma_bf16(s0, af[PA[p]], &bf[PB[p]][0]);
        mma_bf16(s1, af[PA[p]], &bf[PB[p]][2]);
    }
}

// ===========================================================================
// Conversion passes: f32 row-major -> ext-bf16 swizzled tiles in gmem
// ===========================================================================
__global__ void __launch_bounds__(256)
cvt_x_kernel(const float* __restrict__ X)   // X [8192][2048]
{
    const int kStep = blockIdx.x, rowTile = blockIdx.y;
    const int tid = threadIdx.x;
    const int r  = tid >> 1;
    const int ce = (tid & 1) * 16;
    const float* src = X + (size_t)(rowTile * 128 + r) * C_ + kStep * 32 + ce;
    char* dst = g_xext + ((size_t)rowTile * 64 + kStep) * 16384;
#pragma unroll
    for (int i = 0; i < 4; i++)
        cvt_store4(dst, (uint32_t)(r * 128 + (ce + 4 * i) * 2), *(const float4*)(src + 4 * i));
}

__global__ void __launch_bounds__(256)
cvt_wq_kernel(const float* __restrict__ W)  // Wq [512][2048]
{
    const int kStep = blockIdx.x, nTile = blockIdx.y;
    const int tid = threadIdx.x;
    const int r  = tid >> 1;
    const int ce = (tid & 1) * 16;
    const float* src = W + (size_t)(nTile * 128 + r) * C_ + kStep * 32 + ce;
    char* dst = g_wqext + ((size_t)nTile * 64 + kStep) * 16384;
#pragma unroll
    for (int i = 0; i < 4; i++)
        cvt_store4(dst, (uint32_t)(r * 128 + (ce + 4 * i) * 2), *(const float4*)(src + 4 * i));
}

__global__ void __launch_bounds__(256)
cvt_wkw_kernel(const float* __restrict__ Wk, const float* __restrict__ Ww)
{
    const int kStep = blockIdx.x;
    const int tid = threadIdx.x;
    if (tid >= 96) return;
    const int r  = tid >> 1;     // 0..47
    const int ce = (tid & 1) * 16;
    const float* src = (r < 32) ? (Wk + (size_t)r * C_ + kStep * 32 + ce)
                                : (Ww + (size_t)(r - 32) * C_ + kStep * 32 + ce);
    char* dst = g_kwext + (size_t)kStep * 6144;
#pragma unroll
    for (int i = 0; i < 4; i++)
        cvt_store4(dst, (uint32_t)(r * 128 + (ce + 4 * i) * 2), *(const float4*)(src + 4 * i));
}

// ===========================================================================
// Q projection (pure bf16, 3-stage cp.async): writes g_qext tiles
// CTA = 128(m) x 128(n), 8 warps 4x2. grid (4 n, 64 m).
// ===========================================================================
__global__ void __launch_bounds__(256, 1)
qproj_mma_kernel()
{
    extern __shared__ char dsm_raw[];
    char* dsm = (char*)(((uintptr_t)dsm_raw + 1023) & ~(uintptr_t)1023);
    // stage s: X at s*32768, W at s*32768+16384   (3 stages, 96KB)

    const int tid  = threadIdx.x;
    const int wid  = tid >> 5;
    const int lane = tid & 31;
    const int nTile = blockIdx.x;           // 0..3
    const int mTile = blockIdx.y;           // 0..63
    const int m0 = (wid & 3) * 32;
    const int n0 = (wid >> 2) * 64;

    const char* xsrc = g_xext + (size_t)mTile * 64 * 16384;
    const char* wsrc = g_wqext + (size_t)nTile * 64 * 16384;

    uint32_t sbase[3];
#pragma unroll
    for (int s = 0; s < 3; s++) sbase[s] = smem_u32(dsm + s * 32768);

    // ldsm offsets (relative to stage base)
    uint32_t aoff[2][4], boff[4][4];
    {
        const int arow = lane & 15, aseg = lane >> 4;
        const int brow = (lane & 7) + ((lane & 16) >> 1);
        const int bseg = (lane >> 3) & 1;
#pragma unroll
        for (int t = 0; t < 4; t++)
#pragma unroll
            for (int ks = 0; ks < 4; ks++) {
                if (t < 2)
                    aoff[t][ks] = sw128((uint32_t)((m0 + t * 16 + arow) * 128 +
                                                   ks * 32 + aseg * 16));
                boff[t][ks] = 16384u + sw128((uint32_t)((n0 + t * 16 + brow) * 128 +
                                                        ks * 32 + bseg * 16));
            }
    }

    // prologue: stages 0,1
#pragma unroll
    for (int s = 0; s < 2; s++) {
#pragma unroll
        for (int j = 0; j < 4; j++) {
            uint32_t off = (uint32_t)(tid + j * 256) * 16;
            cp16(sbase[s] + off, xsrc + (size_t)s * 16384 + off);
            cp16(sbase[s] + 16384 + off, wsrc + (size_t)s * 16384 + off);
        }
        CP_COMMIT();
    }

    float acc[2][8][4];
#pragma unroll
    for (int mt = 0; mt < 2; mt++)
#pragma unroll
        for (int nt = 0; nt < 8; nt++)
#pragma unroll
            for (int c = 0; c < 4; c++) acc[mt][nt][c] = 0.f;

    CP_WAIT(1);
    __syncthreads();

#pragma unroll 1
    for (int it = 0; it < 64; it++) {
        if (it > 0) {
            if (it == 63) CP_WAIT(0); else CP_WAIT(1);
            __syncthreads();
        }
        // issue stage it+2
        if (it + 2 < 64) {
            uint32_t sb = sbase[(it + 2) % 3];
#pragma unroll
            for (int j = 0; j < 4; j++) {
                uint32_t off = (uint32_t)(tid + j * 256) * 16;
                cp16(sb + off, xsrc + (size_t)(it + 2) * 16384 + off);
                cp16(sb + 16384 + off, wsrc + (size_t)(it + 2) * 16384 + off);
            }
        }
        CP_COMMIT();

        const uint32_t cb = sbase[it % 3];
        uint32_t bfr[4][4][4];
#pragma unroll
        for (int ntp = 0; ntp < 4; ntp++)
#pragma unroll
            for (int ks = 0; ks < 4; ks++) ldsm4(bfr[ntp][ks], cb + boff[ntp][ks]);

#pragma unroll
        for (int mt = 0; mt < 2; mt++) {
            uint32_t af[4][4];
#pragma unroll
            for (int ks = 0; ks < 4; ks++) ldsm4(af[ks], cb + aoff[mt][ks]);
#pragma unroll
            for (int ntp = 0; ntp < 4; ntp++)
                mma_split3_n16(acc[mt][ntp * 2], acc[mt][ntp * 2 + 1], af, bfr[ntp]);
        }
    }

    // epilogue: write ext-bf16 tiles g_qext[mTile][head]
#pragma unroll
    for (int mt = 0; mt < 2; mt++)
#pragma unroll
        for (int rp = 0; rp < 2; rp++) {
            const int r = m0 + mt * 16 + (lane >> 2) + rp * 8;
#pragma unroll
            for (int nt = 0; nt < 8; nt++) {
                const int col = nTile * 128 + n0 + nt * 8 + (lane & 3) * 2;
                const int head = col >> 5;
                const int d = col & 31;
                uint32_t hi, lo;
                split2(acc[mt][nt][rp * 2], acc[mt][nt][rp * 2 + 1], hi, lo);
                char* dst = g_qext + ((size_t)mTile * 16 + head) * 16384;
                *(uint32_t*)(dst + sw128((uint32_t)(r * 128 + d * 2)))      = hi;
                *(uint32_t*)(dst + sw128((uint32_t)(r * 128 + 64 + d * 2))) = lo;
            }
        }
}

// ===========================================================================
// K + W projections (pure bf16, 3-stage): writes g_kext tiles + g_w f32
// CTA = 128 rows x 48 cols, 8 warps each 16(m) x 48(n). grid 64.
// ===========================================================================
__global__ void __launch_bounds__(256, 1)
kwproj_mma_kernel()
{
    extern __shared__ char dsm_raw[];
    char* dsm = (char*)(((uintptr_t)dsm_raw + 1023) & ~(uintptr_t)1023);
    // stage s: X at s*24576 (16KB), B at s*24576+16384 (6KB)

    const int tid  = threadIdx.x;
    const int wid  = tid >> 5;
    const int lane = tid & 31;
    const int mTile = blockIdx.x;
    const int m0 = wid * 16;

    const char* xsrc = g_xext + (size_t)mTile * 64 * 16384;

    uint32_t sbase[3];
#pragma unroll
    for (int s = 0; s < 3; s++) sbase[s] = smem_u32(dsm + s * 24576);

    uint32_t aoff[4], boff[3][4];
    {
        const int arow = lane & 15, aseg = lane >> 4;
        const int brow = (lane & 7) + ((lane & 16) >> 1);
        const int bseg = (lane >> 3) & 1;
#pragma unroll
        for (int ks = 0; ks < 4; ks++) {
            aoff[ks] = sw128((uint32_t)((m0 + arow) * 128 + ks * 32 + aseg * 16));
#pragma unroll
            for (int ntp = 0; ntp < 3; ntp++)
                boff[ntp][ks] = 16384u + sw128((uint32_t)((ntp * 16 + brow) * 128 +
                                                          ks * 32 + bseg * 16));
        }
    }

#pragma unroll
    for (int s = 0; s < 2; s++) {
#pragma unroll
        for (int j = 0; j < 4; j++) {
            uint32_t off = (uint32_t)(tid + j * 256) * 16;
            cp16(sbase[s] + off, xsrc + (size_t)s * 16384 + off);
        }
#pragma unroll
        for (int j = 0; j < 2; j++) {
            uint32_t idx = (uint32_t)(tid + j * 256);
            if (idx < 384)
                cp16(sbase[s] + 16384 + idx * 16, g_kwext + (size_t)s * 6144 + idx * 16);
        }
        CP_COMMIT();
    }

    float acc[6][4];
#pragma unroll
    for (int nt = 0; nt < 6; nt++)
#pragma unroll
        for (int c = 0; c < 4; c++) acc[nt][c] = 0.f;

    CP_WAIT(1);
    __syncthreads();

#pragma unroll 1
    for (int it = 0; it < 64; it++) {
        if (it > 0) {
            if (it == 63) CP_WAIT(0); else CP_WAIT(1);
            __syncthreads();
        }
        if (it + 2 < 64) {
            uint32_t sb = sbase[(it + 2) % 3];
#pragma unroll
            for (int j = 0; j < 4; j++) {
                uint32_t off = (uint32_t)(tid + j * 256) * 16;
                cp16(sb + off, xsrc + (size_t)(it + 2) * 16384 + off);
            }
#pragma unroll
            for (int j = 0; j < 2; j++) {
                uint32_t idx = (uint32_t)(tid + j * 256);
                if (idx < 384)
                    cp16(sb + 16384 + idx * 16, g_kwext + (size_t)(it + 2) * 6144 + idx * 16);
            }
        }
        CP_COMMIT();

        const uint32_t cb = sbase[it % 3];
        uint32_t af[4][4];
#pragma unroll
        for (int ks = 0; ks < 4; ks++) ldsm4(af[ks], cb + aoff[ks]);

#pragma unroll
        for (int ntp = 0; ntp < 3; ntp++) {
            uint32_t bfr[4][4];
#pragma unroll
            for (int ks = 0; ks < 4; ks++) ldsm4(bfr[ks], cb + boff[ntp][ks]);
            mma_split3_n16(acc[ntp * 2], acc[ntp * 2 + 1], af, bfr);
        }
    }

    // epilogue: K -> ext tiles, W -> f32
#pragma unroll
    for (int rp = 0; rp < 2; rp++) {
        const int r = m0 + (lane >> 2) + rp * 8;
#pragma unroll
        for (int nt = 0; nt < 6; nt++) {
            const int col = nt * 8 + (lane & 3) * 2;
            if (nt < 4) {
                uint32_t hi, lo;
                split2(acc[nt][rp * 2], acc[nt][rp * 2 + 1], hi, lo);
                char* dst = g_kext + (size_t)mTile * 16384;
                *(uint32_t*)(dst + sw128((uint32_t)(r * 128 + col * 2)))      = hi;
                *(uint32_t*)(dst + sw128((uint32_t)(r * 128 + 64 + col * 2))) = lo;
            } else {
                *(float2*)(g_w + (size_t)(mTile * 128 + r) * H_ + (col - 32)) =
                    make_float2(acc[nt][rp * 2], acc[nt][rp * 2 + 1]);
            }
        }
    }
}

// ===========================================================================
// Fused scores+importance: out[b,q,k] = sum_h w[b,q,h]*relu(dot(q,k))
// CTA = 128(q) x 128(k), 8 warps 4x2. K frags register-resident;
// Q head tiles streamed via 3-buffer cp.async, 1 sync per head.
// ===========================================================================
__global__ void __launch_bounds__(256, 1)
fused_mma_kernel(float* __restrict__ out)
{
    extern __shared__ char dsm_raw[];
    char* dsm = (char*)(((uintptr_t)dsm_raw + 1023) & ~(uintptr_t)1023);
    char* Ks   = dsm;                   // 16KB
    char* Qb   = dsm + 16384;           // 3 x 16KB
    float* w_s = (float*)(dsm + 65536); // 8KB

    const int tid  = threadIdx.x;
    const int wid  = tid >> 5;
    const int lane = tid & 31;
    const int b  = blockIdx.z;
    const int q0 = blockIdx.y * 128;
    const int k0 = blockIdx.x * 128;
    const int m0 = (wid & 3) * 32;
    const int n0 = (wid >> 2) * 64;

    const int qTile = b * 32 + blockIdx.y;
    const int kTile = b * 32 + blockIdx.x;
    const char* qsrc = g_qext + (size_t)qTile * 16 * 16384;   // + h*16384
    const char* ksrc = g_kext + (size_t)kTile * 16384;
    const float* wsrc = g_w + (size_t)(b * T_ + q0) * H_;

    const uint32_t ksb = smem_u32(Ks);
    const uint32_t wsb_smem = smem_u32(w_s);
    uint32_t qbase[3];
#pragma unroll
    for (int s = 0; s < 3; s++) qbase[s] = smem_u32(Qb + s * 16384);

    // prologue: G0 = {K, w, Q0}, G1 = {Q1}
#pragma unroll
    for (int j = 0; j < 4; j++) {
        uint32_t off = (uint32_t)(tid + j * 256) * 16;
        cp16(ksb + off, ksrc + off);
        cp16(qbase[0] + off, qsrc + off);
    }
#pragma unroll
    for (int j = 0; j < 2; j++) {
        uint32_t off = (uint32_t)(tid + j * 256) * 16;
        cp16(wsb_smem + off, (const char*)wsrc + off);
    }
    CP_COMMIT();
#pragma unroll
    for (int j = 0; j < 4; j++) {
        uint32_t off = (uint32_t)(tid + j * 256) * 16;
        cp16(qbase[1] + off, qsrc + 16384 + off);
    }
    CP_COMMIT();

    // ldsm offsets
    uint32_t aoff[2][4];
    uint32_t baddr[4][4];
    {
        const int arow = lane & 15, aseg = lane >> 4;
        const int brow = (lane & 7) + ((lane & 16) >> 1);
        const int bseg = (lane >> 3) & 1;
#pragma unroll
        for (int t = 0; t < 4; t++)
#pragma unroll
            for (int ks = 0; ks < 4; ks++) {
                if (t < 2)
                    aoff[t][ks] = sw128((uint32_t)((m0 + t * 16 + arow) * 128 +
                                                   ks * 32 + aseg * 16));
                baddr[t][ks] = ksb + sw128((uint32_t)((n0 + t * 16 + brow) * 128 +
                                                      ks * 32 + bseg * 16));
            }
    }

    float acc[2][8][4];
#pragma unroll
    for (int mt = 0; mt < 2; mt++)
#pragma unroll
        for (int nt = 0; nt < 8; nt++)
#pragma unroll
            for (int c = 0; c < 4; c++) acc[mt][nt][c] = 0.f;

    CP_WAIT(1);       // G0 done: K, w, Q0
    __syncthreads();

    // K fragments register-resident
    uint32_t bfr[4][4][4];
#pragma unroll
    for (int ntp = 0; ntp < 4; ntp++)
#pragma unroll
        for (int ks = 0; ks < 4; ks++) ldsm4(bfr[ntp][ks], baddr[ntp][ks]);

    const int wrow0 = m0 + (lane >> 2);

#pragma unroll 1
    for (int h = 0; h < H_; h++) {
        if (h > 0) {
            if (h == H_ - 1) CP_WAIT(0); else CP_WAIT(1);
            __syncthreads();   // all warps done computing head h-1
        }
        // issue Q_{h+2} into buffer (h+2)%3  (its last reader was head h-1)
        if (h + 2 < H_) {
            uint32_t qb = qbase[(h + 2) % 3];
            const char* src = qsrc + (size_t)(h + 2) * 16384;
#pragma unroll
            for (int j = 0; j < 4; j++) {
                uint32_t off = (uint32_t)(tid + j * 256) * 16;
                cp16(qb + off, src + off);
            }
        }
        CP_COMMIT();

        const uint32_t qb = qbase[h % 3];
#pragma unroll
        for (int mt = 0; mt < 2; mt++) {
            uint32_t af[4][4];
#pragma unroll
            for (int ks = 0; ks < 4; ks++) ldsm4(af[ks], qb + aoff[mt][ks]);

            const float wv0 = w_s[(wrow0 + mt * 16) * H_ + h];
            const float wv1 = w_s[(wrow0 + mt * 16 + 8) * H_ + h];

#pragma unroll
            for (int ntp = 0; ntp < 4; ntp++) {
                float s0[4] = {0.f, 0.f, 0.f, 0.f};
                float s1[4] = {0.f, 0.f, 0.f, 0.f};
                mma_split3_n16(s0, s1, af, bfr[ntp]);
                acc[mt][ntp * 2][0] += wv0 * fmaxf(s0[0], 0.f);
                acc[mt][ntp * 2][1] += wv0 * fmaxf(s0[1], 0.f);
                acc[mt][ntp * 2][2] += wv1 * fmaxf(s0[2], 0.f);
                acc[mt][ntp * 2][3] += wv1 * fmaxf(s0[3], 0.f);
                acc[mt][ntp * 2 + 1][0] += wv0 * fmaxf(s1[0], 0.f);
                acc[mt][ntp * 2 + 1][1] += wv0 * fmaxf(s1[1], 0.f);
                acc[mt][ntp * 2 + 1][2] += wv1 * fmaxf(s1[2], 0.f);
                acc[mt][ntp * 2 + 1][3] += wv1 * fmaxf(s1[3], 0.f);
            }
        }
    }

    // epilogue
#pragma unroll
    for (int mt = 0; mt < 2; mt++)
#pragma unroll
        for (int rp = 0; rp < 2; rp++) {
            const int row = q0 + m0 + mt * 16 + (lane >> 2) + rp * 8;
            float* op = out + (size_t)(b * T_ + row) * T_ + k0 + n0 + (lane & 3) * 2;
#pragma unroll
            for (int nt = 0; nt < 8; nt++)
                *(float2*)(op + nt * 8) =
                    make_float2(acc[mt][nt][rp * 2], acc[mt][nt][rp * 2 + 1]);
        }
}

// ===========================================================================
extern "C" void kernel_launch(void* const* d_in, const int* in_sizes, int n_in,
                              void* d_out, int out_size)
{
    (void)in_sizes; (void)n_in; (void)out_size;
    const float* x  = (const float*)d_in[0];
    const float* Wq = (const float*)d_in[1];
    const float* Wk = (const float*)d_in[2];
    const float* Ww = (const float*)d_in[3];
    float* out = (float*)d_out;

    static bool attr_done = false;
    if (!attr_done) {
        cudaFuncSetAttribute(qproj_mma_kernel,
                             cudaFuncAttributeMaxDynamicSharedMemorySize, 99328);
        cudaFuncSetAttribute(kwproj_mma_kernel,
                             cudaFuncAttributeMaxDynamicSharedMemorySize, 74752);
        cudaFuncSetAttribute(fused_mma_kernel,
                             cudaFuncAttributeMaxDynamicSharedMemorySize, 74752);
        attr_done = true;
    }

    cvt_x_kernel<<<dim3(64, 64), 256>>>(x);
    cvt_wq_kernel<<<dim3(64, 4), 256>>>(Wq);
    cvt_wkw_kernel<<<64, 256>>>(Wk, Ww);

    qproj_mma_kernel<<<dim3(4, 64), 256, 99328>>>();
    kwproj_mma_kernel<<<64, 256, 74752>>>();
    fused_mma_kernel<<<dim3(T_ / 128, T_ / 128, B_), 256, 74752>>>(out);
}

// round 6
// speedup vs baseline: 2.8071x; 1.0230x over previous
#include <cuda_runtime.h>
#include <cuda_bf16.h>
#include <cstdint>

// Problem constants
#define B_ 2
#define T_ 4096
#define C_ 2048
#define H_ 16
#define D_ 32

// ---------------------------------------------------------------------------
// Ext-bf16 tile format: a 128-row x 32-f32-col operand block is stored as
// 16384 bytes; logical (row r, ext col c in [0,64): c<32 = hi of d=c,
// c>=32 = lo of d=c-32) lives at byte offset sw128(r*128 + c*2).
// Gmem byte order == smem byte order -> plain 16B cp.async copies.
// ---------------------------------------------------------------------------
__device__ __align__(1024) char g_xext [(size_t)64 * 64 * 16384];  // [rowTile][kStep]
__device__ __align__(1024) char g_wqext[(size_t)4  * 64 * 16384];  // [nTile][kStep]
__device__ __align__(1024) char g_kwext[(size_t)64 * 6144];        // [kStep] 48 rows
__device__ __align__(1024) char g_qext [(size_t)64 * 16 * 16384];  // [qTile][head]
__device__ __align__(1024) char g_kext [(size_t)64 * 16384];       // [kTile]
__device__ __align__(1024) float g_w[(size_t)B_ * T_ * H_];        // [8192][16]

// ===========================================================================
// Helpers (base sm_103-safe: ldmatrix + mma.sync + cp.async)
// ===========================================================================
__device__ __forceinline__ uint32_t smem_u32(const void* p) {
    uint32_t a;
    asm("{ .reg .u64 t; cvta.to.shared.u64 t, %1; cvt.u32.u64 %0, t; }"
        : "=r"(a) : "l"(p));
    return a;
}

__device__ __forceinline__ uint32_t sw128(uint32_t o) { return o ^ ((o >> 3) & 0x70); }

__device__ __forceinline__ void ldsm4(uint32_t* r, uint32_t a) {
    asm volatile("ldmatrix.sync.aligned.m8n8.x4.shared.b16 {%0,%1,%2,%3}, [%4];"
                 : "=r"(r[0]), "=r"(r[1]), "=r"(r[2]), "=r"(r[3]) : "r"(a));
}

__device__ __forceinline__ void mma_bf16(float* d, const uint32_t* a, const uint32_t* b) {
    asm volatile(
        "mma.sync.aligned.m16n8k16.row.col.f32.bf16.bf16.f32 "
        "{%0,%1,%2,%3}, {%4,%5,%6,%7}, {%8,%9}, {%0,%1,%2,%3};"
        : "+f"(d[0]), "+f"(d[1]), "+f"(d[2]), "+f"(d[3])
        : "r"(a[0]), "r"(a[1]), "r"(a[2]), "r"(a[3]), "r"(b[0]), "r"(b[1]));
}

__device__ __forceinline__ void cp16(uint32_t s, const void* g) {
    asm volatile("cp.async.cg.shared.global [%0], [%1], 16;" :: "r"(s), "l"(g));
}
#define CP_COMMIT() asm volatile("cp.async.commit_group;" ::: "memory")
#define CP_WAIT(n)  asm volatile("cp.async.wait_group %0;" :: "n"(n) : "memory")

__device__ __forceinline__ uint32_t pack2bf(float x, float y) {
    __nv_bfloat16 bx = __float2bfloat16_rn(x), by = __float2bfloat16_rn(y);
    return ((uint32_t)__bfloat16_as_ushort(by) << 16) | (uint32_t)__bfloat16_as_ushort(bx);
}

__device__ __forceinline__ void split2(float v0, float v1, uint32_t& hi, uint32_t& lo) {
    __nv_bfloat16 h0 = __float2bfloat16_rn(v0), h1 = __float2bfloat16_rn(v1);
    hi = ((uint32_t)__bfloat16_as_ushort(h1) << 16) | (uint32_t)__bfloat16_as_ushort(h0);
    lo = pack2bf(v0 - __bfloat162float(h0), v1 - __bfloat162float(h1));
}

__device__ __forceinline__ void cvt_store4(char* tile, uint32_t base_off, float4 v) {
    uint32_t hi0, lo0, hi1, lo1;
    split2(v.x, v.y, hi0, lo0);
    split2(v.z, v.w, hi1, lo1);
    *(uint2*)(tile + sw128(base_off))      = make_uint2(hi0, hi1);
    *(uint2*)(tile + sw128(base_off + 64)) = make_uint2(lo0, lo1);
}

// 3-term split product: frag 0,1 = hi k-steps; 2,3 = lo k-steps.
//   s = a_hi*b_hi + a_hi*b_lo + a_lo*b_hi
__device__ __forceinline__ void mma_split3_n16(float* s0, float* s1,
                                               const uint32_t af[4][4],
                                               const uint32_t bf[4][4]) {
    const int PA[6] = {0, 1, 0, 1, 2, 3};
    const int PB[6] = {0, 1, 2, 3, 0, 1};
#pragma unroll
    for (int p = 0; p < 6; p++) {
        mma_bf16(s0, af[PA[p]], &bf[PB[p]][0]);
        mma_bf16(s1, af[PA[p]], &bf[PB[p]][2]);
    }
}

// ===========================================================================
// Conversion passes: f32 row-major -> ext-bf16 swizzled tiles in gmem
// ===========================================================================
__global__ void __launch_bounds__(256)
cvt_x_kernel(const float* __restrict__ X)
{
    const int kStep = blockIdx.x, rowTile = blockIdx.y;
    const int tid = threadIdx.x;
    const int r  = tid >> 1;
    const int ce = (tid & 1) * 16;
    const float* src = X + (size_t)(rowTile * 128 + r) * C_ + kStep * 32 + ce;
    char* dst = g_xext + ((size_t)rowTile * 64 + kStep) * 16384;
#pragma unroll
    for (int i = 0; i < 4; i++)
        cvt_store4(dst, (uint32_t)(r * 128 + (ce + 4 * i) * 2), *(const float4*)(src + 4 * i));
}

__global__ void __launch_bounds__(256)
cvt_wq_kernel(const float* __restrict__ W)
{
    const int kStep = blockIdx.x, nTile = blockIdx.y;
    const int tid = threadIdx.x;
    const int r  = tid >> 1;
    const int ce = (tid & 1) * 16;
    const float* src = W + (size_t)(nTile * 128 + r) * C_ + kStep * 32 + ce;
    char* dst = g_wqext + ((size_t)nTile * 64 + kStep) * 16384;
#pragma unroll
    for (int i = 0; i < 4; i++)
        cvt_store4(dst, (uint32_t)(r * 128 + (ce + 4 * i) * 2), *(const float4*)(src + 4 * i));
}

__global__ void __launch_bounds__(256)
cvt_wkw_kernel(const float* __restrict__ Wk, const float* __restrict__ Ww)
{
    const int kStep = blockIdx.x;
    const int tid = threadIdx.x;
    if (tid >= 96) return;
    const int r  = tid >> 1;
    const int ce = (tid & 1) * 16;
    const float* src = (r < 32) ? (Wk + (size_t)r * C_ + kStep * 32 + ce)
                                : (Ww + (size_t)(r - 32) * C_ + kStep * 32 + ce);
    char* dst = g_kwext + (size_t)kStep * 6144;
#pragma unroll
    for (int i = 0; i < 4; i++)
        cvt_store4(dst, (uint32_t)(r * 128 + (ce + 4 * i) * 2), *(const float4*)(src + 4 * i));
}

// ===========================================================================
// Q projection (512 threads, 16 warps 4x4, warp tile 32x32, 3-stage cp.async)
// ===========================================================================
__global__ void __launch_bounds__(512, 1)
qproj_mma_kernel()
{
    extern __shared__ char dsm_raw[];
    char* dsm = (char*)(((uintptr_t)dsm_raw + 1023) & ~(uintptr_t)1023);

    const int tid  = threadIdx.x;
    const int wid  = tid >> 5;
    const int lane = tid & 31;
    const int nTile = blockIdx.x;           // 0..3
    const int mTile = blockIdx.y;           // 0..63
    const int m0 = (wid & 3) * 32;
    const int n0 = (wid >> 2) * 32;

    const char* xsrc = g_xext + (size_t)mTile * 64 * 16384;
    const char* wsrc = g_wqext + (size_t)nTile * 64 * 16384;

    uint32_t sbase[3];
#pragma unroll
    for (int s = 0; s < 3; s++) sbase[s] = smem_u32(dsm + s * 32768);

    uint32_t aoff[2][4], boff[2][4];
    {
        const int arow = lane & 15, aseg = lane >> 4;
        const int brow = (lane & 7) + ((lane & 16) >> 1);
        const int bseg = (lane >> 3) & 1;
#pragma unroll
        for (int t = 0; t < 2; t++)
#pragma unroll
            for (int ks = 0; ks < 4; ks++) {
                aoff[t][ks] = sw128((uint32_t)((m0 + t * 16 + arow) * 128 +
                                               ks * 32 + aseg * 16));
                boff[t][ks] = 16384u + sw128((uint32_t)((n0 + t * 16 + brow) * 128 +
                                                        ks * 32 + bseg * 16));
            }
    }

    // prologue: stages 0,1
#pragma unroll
    for (int s = 0; s < 2; s++) {
#pragma unroll
        for (int j = 0; j < 2; j++) {
            uint32_t off = (uint32_t)(tid + j * 512) * 16;
            cp16(sbase[s] + off, xsrc + (size_t)s * 16384 + off);
            cp16(sbase[s] + 16384 + off, wsrc + (size_t)s * 16384 + off);
        }
        CP_COMMIT();
    }

    float acc[2][4][4];
#pragma unroll
    for (int mt = 0; mt < 2; mt++)
#pragma unroll
        for (int nt = 0; nt < 4; nt++)
#pragma unroll
            for (int c = 0; c < 4; c++) acc[mt][nt][c] = 0.f;

    CP_WAIT(1);
    __syncthreads();

#pragma unroll 1
    for (int it = 0; it < 64; it++) {
        if (it > 0) {
            if (it == 63) CP_WAIT(0); else CP_WAIT(1);
            __syncthreads();
        }
        if (it + 2 < 64) {
            uint32_t sb = sbase[(it + 2) % 3];
#pragma unroll
            for (int j = 0; j < 2; j++) {
                uint32_t off = (uint32_t)(tid + j * 512) * 16;
                cp16(sb + off, xsrc + (size_t)(it + 2) * 16384 + off);
                cp16(sb + 16384 + off, wsrc + (size_t)(it + 2) * 16384 + off);
            }
        }
        CP_COMMIT();

        const uint32_t cb = sbase[it % 3];
        uint32_t bfr[2][4][4];
#pragma unroll
        for (int ntp = 0; ntp < 2; ntp++)
#pragma unroll
            for (int ks = 0; ks < 4; ks++) ldsm4(bfr[ntp][ks], cb + boff[ntp][ks]);

#pragma unroll
        for (int mt = 0; mt < 2; mt++) {
            uint32_t af[4][4];
#pragma unroll
            for (int ks = 0; ks < 4; ks++) ldsm4(af[ks], cb + aoff[mt][ks]);
#pragma unroll
            for (int ntp = 0; ntp < 2; ntp++)
                mma_split3_n16(acc[mt][ntp * 2], acc[mt][ntp * 2 + 1], af, bfr[ntp]);
        }
    }

    // epilogue: write ext-bf16 tiles g_qext[mTile][head]
#pragma unroll
    for (int mt = 0; mt < 2; mt++)
#pragma unroll
        for (int rp = 0; rp < 2; rp++) {
            const int r = m0 + mt * 16 + (lane >> 2) + rp * 8;
#pragma unroll
            for (int nt = 0; nt < 4; nt++) {
                const int col = nTile * 128 + n0 + nt * 8 + (lane & 3) * 2;
                const int head = col >> 5;
                const int d = col & 31;
                uint32_t hi, lo;
                split2(acc[mt][nt][rp * 2], acc[mt][nt][rp * 2 + 1], hi, lo);
                char* dst = g_qext + ((size_t)mTile * 16 + head) * 16384;
                *(uint32_t*)(dst + sw128((uint32_t)(r * 128 + d * 2)))      = hi;
                *(uint32_t*)(dst + sw128((uint32_t)(r * 128 + 64 + d * 2))) = lo;
            }
        }
}

// ===========================================================================
// K + W projections (256 threads): writes g_kext tiles + g_w f32
// ===========================================================================
__global__ void __launch_bounds__(256, 1)
kwproj_mma_kernel()
{
    extern __shared__ char dsm_raw[];
    char* dsm = (char*)(((uintptr_t)dsm_raw + 1023) & ~(uintptr_t)1023);

    const int tid  = threadIdx.x;
    const int wid  = tid >> 5;
    const int lane = tid & 31;
    const int mTile = blockIdx.x;
    const int m0 = wid * 16;

    const char* xsrc = g_xext + (size_t)mTile * 64 * 16384;

    uint32_t sbase[3];
#pragma unroll
    for (int s = 0; s < 3; s++) sbase[s] = smem_u32(dsm + s * 24576);

    uint32_t aoff[4], boff[3][4];
    {
        const int arow = lane & 15, aseg = lane >> 4;
        const int brow = (lane & 7) + ((lane & 16) >> 1);
        const int bseg = (lane >> 3) & 1;
#pragma unroll
        for (int ks = 0; ks < 4; ks++) {
            aoff[ks] = sw128((uint32_t)((m0 + arow) * 128 + ks * 32 + aseg * 16));
#pragma unroll
            for (int ntp = 0; ntp < 3; ntp++)
                boff[ntp][ks] = 16384u + sw128((uint32_t)((ntp * 16 + brow) * 128 +
                                                          ks * 32 + bseg * 16));
        }
    }

#pragma unroll
    for (int s = 0; s < 2; s++) {
#pragma unroll
        for (int j = 0; j < 4; j++) {
            uint32_t off = (uint32_t)(tid + j * 256) * 16;
            cp16(sbase[s] + off, xsrc + (size_t)s * 16384 + off);
        }
#pragma unroll
        for (int j = 0; j < 2; j++) {
            uint32_t idx = (uint32_t)(tid + j * 256);
            if (idx < 384)
                cp16(sbase[s] + 16384 + idx * 16, g_kwext + (size_t)s * 6144 + idx * 16);
        }
        CP_COMMIT();
    }

    float acc[6][4];
#pragma unroll
    for (int nt = 0; nt < 6; nt++)
#pragma unroll
        for (int c = 0; c < 4; c++) acc[nt][c] = 0.f;

    CP_WAIT(1);
    __syncthreads();

#pragma unroll 1
    for (int it = 0; it < 64; it++) {
        if (it > 0) {
            if (it == 63) CP_WAIT(0); else CP_WAIT(1);
            __syncthreads();
        }
        if (it + 2 < 64) {
            uint32_t sb = sbase[(it + 2) % 3];
#pragma unroll
            for (int j = 0; j < 4; j++) {
                uint32_t off = (uint32_t)(tid + j * 256) * 16;
                cp16(sb + off, xsrc + (size_t)(it + 2) * 16384 + off);
            }
#pragma unroll
            for (int j = 0; j < 2; j++) {
                uint32_t idx = (uint32_t)(tid + j * 256);
                if (idx < 384)
                    cp16(sb + 16384 + idx * 16, g_kwext + (size_t)(it + 2) * 6144 + idx * 16);
            }
        }
        CP_COMMIT();

        const uint32_t cb = sbase[it % 3];
        uint32_t af[4][4];
#pragma unroll
        for (int ks = 0; ks < 4; ks++) ldsm4(af[ks], cb + aoff[ks]);

#pragma unroll
        for (int ntp = 0; ntp < 3; ntp++) {
            uint32_t bfr[4][4];
#pragma unroll
            for (int ks = 0; ks < 4; ks++) ldsm4(bfr[ks], cb + boff[ntp][ks]);
            mma_split3_n16(acc[ntp * 2], acc[ntp * 2 + 1], af, bfr);
        }
    }

#pragma unroll
    for (int rp = 0; rp < 2; rp++) {
        const int r = m0 + (lane >> 2) + rp * 8;
#pragma unroll
        for (int nt = 0; nt < 6; nt++) {
            const int col = nt * 8 + (lane & 3) * 2;
            if (nt < 4) {
                uint32_t hi, lo;
                split2(acc[nt][rp * 2], acc[nt][rp * 2 + 1], hi, lo);
                char* dst = g_kext + (size_t)mTile * 16384;
                *(uint32_t*)(dst + sw128((uint32_t)(r * 128 + col * 2)))      = hi;
                *(uint32_t*)(dst + sw128((uint32_t)(r * 128 + 64 + col * 2))) = lo;
            } else {
                *(float2*)(g_w + (size_t)(mTile * 128 + r) * H_ + (col - 32)) =
                    make_float2(acc[nt][rp * 2], acc[nt][rp * 2 + 1]);
            }
        }
    }
}

// ===========================================================================
// Fused scores+importance (512 threads, 16 warps 4x4, warp tile 32x32)
//   out[b,q,k] = sum_h w[b,q,h]*relu(dot(q,k))
// K frags register-resident; Q head tiles 3-buffer cp.async, 1 sync/head.
// ===========================================================================
__global__ void __launch_bounds__(512, 1)
fused_mma_kernel(float* __restrict__ out)
{
    extern __shared__ char dsm_raw[];
    char* dsm = (char*)(((uintptr_t)dsm_raw + 1023) & ~(uintptr_t)1023);
    char* Ks   = dsm;                   // 16KB
    char* Qb   = dsm + 16384;           // 3 x 16KB
    float* w_s = (float*)(dsm + 65536); // 8KB

    const int tid  = threadIdx.x;
    const int wid  = tid >> 5;
    const int lane = tid & 31;
    const int b  = blockIdx.z;
    const int q0 = blockIdx.y * 128;
    const int k0 = blockIdx.x * 128;
    const int m0 = (wid & 3) * 32;
    const int n0 = (wid >> 2) * 32;

    const int qTile = b * 32 + blockIdx.y;
    const int kTile = b * 32 + blockIdx.x;
    const char* qsrc = g_qext + (size_t)qTile * 16 * 16384;
    const char* ksrc = g_kext + (size_t)kTile * 16384;
    const float* wsrc = g_w + (size_t)(b * T_ + q0) * H_;

    const uint32_t ksb = smem_u32(Ks);
    const uint32_t wsb_smem = smem_u32(w_s);
    uint32_t qbase[3];
#pragma unroll
    for (int s = 0; s < 3; s++) qbase[s] = smem_u32(Qb + s * 16384);

    // prologue: G0 = {K, w, Q0}, G1 = {Q1}
#pragma unroll
    for (int j = 0; j < 2; j++) {
        uint32_t off = (uint32_t)(tid + j * 512) * 16;
        cp16(ksb + off, ksrc + off);
        cp16(qbase[0] + off, qsrc + off);
    }
    cp16(wsb_smem + (uint32_t)tid * 16, (const char*)wsrc + (uint32_t)tid * 16);
    CP_COMMIT();
#pragma unroll
    for (int j = 0; j < 2; j++) {
        uint32_t off = (uint32_t)(tid + j * 512) * 16;
        cp16(qbase[1] + off, qsrc + 16384 + off);
    }
    CP_COMMIT();

    uint32_t aoff[2][4];
    uint32_t baddr[2][4];
    {
        const int arow = lane & 15, aseg = lane >> 4;
        const int brow = (lane & 7) + ((lane & 16) >> 1);
        const int bseg = (lane >> 3) & 1;
#pragma unroll
        for (int t = 0; t < 2; t++)
#pragma unroll
            for (int ks = 0; ks < 4; ks++) {
                aoff[t][ks] = sw128((uint32_t)((m0 + t * 16 + arow) * 128 +
                                               ks * 32 + aseg * 16));
                baddr[t][ks] = ksb + sw128((uint32_t)((n0 + t * 16 + brow) * 128 +
                                                      ks * 32 + bseg * 16));
            }
    }

    float acc[2][4][4];
#pragma unroll
    for (int mt = 0; mt < 2; mt++)
#pragma unroll
        for (int nt = 0; nt < 4; nt++)
#pragma unroll
            for (int c = 0; c < 4; c++) acc[mt][nt][c] = 0.f;

    CP_WAIT(1);       // G0 done: K, w, Q0
    __syncthreads();

    // K fragments register-resident (this warp's 32 n-cols)
    uint32_t bfr[2][4][4];
#pragma unroll
    for (int ntp = 0; ntp < 2; ntp++)
#pragma unroll
        for (int ks = 0; ks < 4; ks++) ldsm4(bfr[ntp][ks], baddr[ntp][ks]);

    const int wrow0 = m0 + (lane >> 2);

#pragma unroll 1
    for (int h = 0; h < H_; h++) {
        if (h > 0) {
            if (h == H_ - 1) CP_WAIT(0); else CP_WAIT(1);
            __syncthreads();
        }
        if (h + 2 < H_) {
            uint32_t qb = qbase[(h + 2) % 3];
            const char* src = qsrc + (size_t)(h + 2) * 16384;
#pragma unroll
            for (int j = 0; j < 2; j++) {
                uint32_t off = (uint32_t)(tid + j * 512) * 16;
                cp16(qb + off, src + off);
            }
        }
        CP_COMMIT();

        const uint32_t qb = qbase[h % 3];
#pragma unroll
        for (int mt = 0; mt < 2; mt++) {
            uint32_t af[4][4];
#pragma unroll
            for (int ks = 0; ks < 4; ks++) ldsm4(af[ks], qb + aoff[mt][ks]);

            const float wv0 = w_s[(wrow0 + mt * 16) * H_ + h];
            const float wv1 = w_s[(wrow0 + mt * 16 + 8) * H_ + h];

            // 4 independent MMA chains (2 ntp x s0/s1) for ILP
            float s[2][2][4];
#pragma unroll
            for (int ntp = 0; ntp < 2; ntp++)
#pragma unroll
                for (int q = 0; q < 2; q++)
#pragma unroll
                    for (int c = 0; c < 4; c++) s[ntp][q][c] = 0.f;
#pragma unroll
            for (int ntp = 0; ntp < 2; ntp++)
                mma_split3_n16(s[ntp][0], s[ntp][1], af, bfr[ntp]);

#pragma unroll
            for (int ntp = 0; ntp < 2; ntp++)
#pragma unroll
                for (int q = 0; q < 2; q++) {
                    float* a = acc[mt][ntp * 2 + q];
                    const float* sv = s[ntp][q];
                    a[0] += wv0 * fmaxf(sv[0], 0.f);
                    a[1] += wv0 * fmaxf(sv[1], 0.f);
                    a[2] += wv1 * fmaxf(sv[2], 0.f);
                    a[3] += wv1 * fmaxf(sv[3], 0.f);
                }
        }
    }

    // epilogue
#pragma unroll
    for (int mt = 0; mt < 2; mt++)
#pragma unroll
        for (int rp = 0; rp < 2; rp++) {
            const int row = q0 + m0 + mt * 16 + (lane >> 2) + rp * 8;
            float* op = out + (size_t)(b * T_ + row) * T_ + k0 + n0 + (lane & 3) * 2;
#pragma unroll
            for (int nt = 0; nt < 4; nt++)
                *(float2*)(op + nt * 8) =
                    make_float2(acc[mt][nt][rp * 2], acc[mt][nt][rp * 2 + 1]);
        }
}

// ===========================================================================
extern "C" void kernel_launch(void* const* d_in, const int* in_sizes, int n_in,
                              void* d_out, int out_size)
{
    (void)in_sizes; (void)n_in; (void)out_size;
    const float* x  = (const float*)d_in[0];
    const float* Wq = (const float*)d_in[1];
    const float* Wk = (const float*)d_in[2];
    const float* Ww = (const float*)d_in[3];
    float* out = (float*)d_out;

    static bool attr_done = false;
    if (!attr_done) {
        cudaFuncSetAttribute(qproj_mma_kernel,
                             cudaFuncAttributeMaxDynamicSharedMemorySize, 99328);
        cudaFuncSetAttribute(kwproj_mma_kernel,
                             cudaFuncAttributeMaxDynamicSharedMemorySize, 74752);
        cudaFuncSetAttribute(fused_mma_kernel,
                             cudaFuncAttributeMaxDynamicSharedMemorySize, 74752);
        attr_done = true;
    }

    cvt_x_kernel<<<dim3(64, 64), 256>>>(x);
    cvt_wq_kernel<<<dim3(64, 4), 256>>>(Wq);
    cvt_wkw_kernel<<<64, 256>>>(Wk, Ww);

    qproj_mma_kernel<<<dim3(4, 64), 512, 99328>>>();
    kwproj_mma_kernel<<<64, 256, 74752>>>();
    fused_mma_kernel<<<dim3(T_ / 128, T_ / 128, B_), 512, 74752>>>(out);
}

// round 7
// speedup vs baseline: 3.1403x; 1.1187x over previous
#include <cuda_runtime.h>
#include <cuda_bf16.h>
#include <cstdint>

// Problem constants
#define B_ 2
#define T_ 4096
#define C_ 2048
#define H_ 16
#define D_ 32

// ---------------------------------------------------------------------------
// Ext-bf16 tile format: a 128-row x 32-f32-col operand block is stored as
// 16384 bytes; logical (row r, ext col c in [0,64): c<32 = hi of d=c,
// c>=32 = lo of d=c-32) lives at byte offset sw128(r*128 + c*2).
// Gmem byte order == smem byte order -> plain 16B cp.async copies.
// ---------------------------------------------------------------------------
__device__ __align__(1024) char g_xext [(size_t)64 * 64 * 16384];  // [rowTile][kStep]
__device__ __align__(1024) char g_wqext[(size_t)4  * 64 * 16384];  // [nTile][kStep]
__device__ __align__(1024) char g_kwext[(size_t)64 * 6144];        // [kStep] 48 rows
__device__ __align__(1024) char g_qext [(size_t)64 * 16 * 16384];  // [qTile][head]
__device__ __align__(1024) char g_kext [(size_t)64 * 16384];       // [kTile]
__device__ __align__(1024) float g_w[(size_t)B_ * T_ * H_];        // [8192][16]

// ===========================================================================
// Helpers (base sm_103-safe: ldmatrix + mma.sync + cp.async)
// ===========================================================================
__device__ __forceinline__ uint32_t smem_u32(const void* p) {
    uint32_t a;
    asm("{ .reg .u64 t; cvta.to.shared.u64 t, %1; cvt.u32.u64 %0, t; }"
        : "=r"(a) : "l"(p));
    return a;
}

__device__ __forceinline__ uint32_t sw128(uint32_t o) { return o ^ ((o >> 3) & 0x70); }

__device__ __forceinline__ void ldsm4(uint32_t* r, uint32_t a) {
    asm volatile("ldmatrix.sync.aligned.m8n8.x4.shared.b16 {%0,%1,%2,%3}, [%4];"
                 : "=r"(r[0]), "=r"(r[1]), "=r"(r[2]), "=r"(r[3]) : "r"(a));
}

__device__ __forceinline__ void mma_bf16(float* d, const uint32_t* a, const uint32_t* b) {
    asm volatile(
        "mma.sync.aligned.m16n8k16.row.col.f32.bf16.bf16.f32 "
        "{%0,%1,%2,%3}, {%4,%5,%6,%7}, {%8,%9}, {%0,%1,%2,%3};"
        : "+f"(d[0]), "+f"(d[1]), "+f"(d[2]), "+f"(d[3])
        : "r"(a[0]), "r"(a[1]), "r"(a[2]), "r"(a[3]), "r"(b[0]), "r"(b[1]));
}

__device__ __forceinline__ void cp16(uint32_t s, const void* g) {
    asm volatile("cp.async.cg.shared.global [%0], [%1], 16;" :: "r"(s), "l"(g));
}
#define CP_COMMIT() asm volatile("cp.async.commit_group;" ::: "memory")
#define CP_WAIT(n)  asm volatile("cp.async.wait_group %0;" :: "n"(n) : "memory")

__device__ __forceinline__ uint32_t pack2bf(float x, float y) {
    __nv_bfloat16 bx = __float2bfloat16_rn(x), by = __float2bfloat16_rn(y);
    return ((uint32_t)__bfloat16_as_ushort(by) << 16) | (uint32_t)__bfloat16_as_ushort(bx);
}

__device__ __forceinline__ void split2(float v0, float v1, uint32_t& hi, uint32_t& lo) {
    __nv_bfloat16 h0 = __float2bfloat16_rn(v0), h1 = __float2bfloat16_rn(v1);
    hi = ((uint32_t)__bfloat16_as_ushort(h1) << 16) | (uint32_t)__bfloat16_as_ushort(h0);
    lo = pack2bf(v0 - __bfloat162float(h0), v1 - __bfloat162float(h1));
}

__device__ __forceinline__ void cvt_store4(char* tile, uint32_t base_off, float4 v) {
    uint32_t hi0, lo0, hi1, lo1;
    split2(v.x, v.y, hi0, lo0);
    split2(v.z, v.w, hi1, lo1);
    *(uint2*)(tile + sw128(base_off))      = make_uint2(hi0, hi1);
    *(uint2*)(tile + sw128(base_off + 64)) = make_uint2(lo0, lo1);
}

// 3-term split product over FOUR independent accumulator chains, issued
// round-robin so same-chain MMAs are 4 issues apart (hides HMMA RAW latency).
// frag 0,1 = hi k-steps; 2,3 = lo k-steps.  s = a_hi*b_hi + a_hi*b_lo + a_lo*b_hi
__device__ __forceinline__ void mma_split3_x4(float* s00, float* s01,
                                              float* s10, float* s11,
                                              const uint32_t af[4][4],
                                              const uint32_t b0[4][4],
                                              const uint32_t b1[4][4]) {
    const int PA[6] = {0, 1, 0, 1, 2, 3};
    const int PB[6] = {0, 1, 2, 3, 0, 1};
#pragma unroll
    for (int p = 0; p < 6; p++) {
        mma_bf16(s00, af[PA[p]], &b0[PB[p]][0]);
        mma_bf16(s01, af[PA[p]], &b0[PB[p]][2]);
        mma_bf16(s10, af[PA[p]], &b1[PB[p]][0]);
        mma_bf16(s11, af[PA[p]], &b1[PB[p]][2]);
    }
}

// ===========================================================================
// Conversion passes: f32 row-major -> ext-bf16 swizzled tiles in gmem
// ===========================================================================
__global__ void __launch_bounds__(256)
cvt_x_kernel(const float* __restrict__ X)
{
    const int kStep = blockIdx.x, rowTile = blockIdx.y;
    const int tid = threadIdx.x;
    const int r  = tid >> 1;
    const int ce = (tid & 1) * 16;
    const float* src = X + (size_t)(rowTile * 128 + r) * C_ + kStep * 32 + ce;
    char* dst = g_xext + ((size_t)rowTile * 64 + kStep) * 16384;
#pragma unroll
    for (int i = 0; i < 4; i++)
        cvt_store4(dst, (uint32_t)(r * 128 + (ce + 4 * i) * 2), *(const float4*)(src + 4 * i));
}

__global__ void __launch_bounds__(256)
cvt_wq_kernel(const float* __restrict__ W)
{
    const int kStep = blockIdx.x, nTile = blockIdx.y;
    const int tid = threadIdx.x;
    const int r  = tid >> 1;
    const int ce = (tid & 1) * 16;
    const float* src = W + (size_t)(nTile * 128 + r) * C_ + kStep * 32 + ce;
    char* dst = g_wqext + ((size_t)nTile * 64 + kStep) * 16384;
#pragma unroll
    for (int i = 0; i < 4; i++)
        cvt_store4(dst, (uint32_t)(r * 128 + (ce + 4 * i) * 2), *(const float4*)(src + 4 * i));
}

__global__ void __launch_bounds__(256)
cvt_wkw_kernel(const float* __restrict__ Wk, const float* __restrict__ Ww)
{
    const int kStep = blockIdx.x;
    const int tid = threadIdx.x;
    if (tid >= 96) return;
    const int r  = tid >> 1;
    const int ce = (tid & 1) * 16;
    const float* src = (r < 32) ? (Wk + (size_t)r * C_ + kStep * 32 + ce)
                                : (Ww + (size_t)(r - 32) * C_ + kStep * 32 + ce);
    char* dst = g_kwext + (size_t)kStep * 6144;
#pragma unroll
    for (int i = 0; i < 4; i++)
        cvt_store4(dst, (uint32_t)(r * 128 + (ce + 4 * i) * 2), *(const float4*)(src + 4 * i));
}

// ===========================================================================
// Unified projection kernel. grid (9, 64):
//   nT in 0..7 : Q-proj, 64 output cols (nT*64..), writes g_qext
//   nT == 8    : K+W proj (48 cols from g_kwext), writes g_kext + g_w
// CTA: 128(m) x 64(n), 256 threads, 8 warps 4(m) x 2(n), warp tile 32x32.
// 3-stage cp.async (16KB X + 8KB W per stage = 72KB), 2 CTAs/SM.
// ===========================================================================
__global__ void __launch_bounds__(256, 2)
proj_mma_kernel()
{
    extern __shared__ char dsm_raw[];
    char* dsm = (char*)(((uintptr_t)dsm_raw + 1023) & ~(uintptr_t)1023);

    const int tid  = threadIdx.x;
    const int wid  = tid >> 5;
    const int lane = tid & 31;
    const int nT    = blockIdx.x;           // 0..8
    const int mTile = blockIdx.y;           // 0..63
    const int m0 = (wid & 3) * 32;
    const int n0 = (wid >> 2) * 32;
    const bool iskw = (nT == 8);

    const char* xsrc = g_xext + (size_t)mTile * 64 * 16384;
    const char* wsrc = iskw ? g_kwext
                            : g_wqext + (size_t)(nT >> 1) * 64 * 16384 + (nT & 1) * 8192;
    const uint32_t wstep  = iskw ? 6144u : 16384u;   // bytes per k-step in gmem
    const uint32_t wbytes = iskw ? 6144u : 8192u;    // bytes to copy per k-step

    uint32_t sbase[3];
#pragma unroll
    for (int s = 0; s < 3; s++) sbase[s] = smem_u32(dsm + s * 24576);

    uint32_t aoff[2][4], boff[2][4];
    {
        const int arow = lane & 15, aseg = lane >> 4;
        const int brow = (lane & 7) + ((lane & 16) >> 1);
        const int bseg = (lane >> 3) & 1;
#pragma unroll
        for (int t = 0; t < 2; t++)
#pragma unroll
            for (int ks = 0; ks < 4; ks++) {
                aoff[t][ks] = sw128((uint32_t)((m0 + t * 16 + arow) * 128 +
                                               ks * 32 + aseg * 16));
                boff[t][ks] = 16384u + sw128((uint32_t)((n0 + t * 16 + brow) * 128 +
                                                        ks * 32 + bseg * 16));
            }
    }

    // prologue: stages 0,1
#pragma unroll
    for (int s = 0; s < 2; s++) {
#pragma unroll
        for (int j = 0; j < 4; j++) {
            uint32_t off = (uint32_t)(tid + j * 256) * 16;
            cp16(sbase[s] + off, xsrc + (size_t)s * 16384 + off);
        }
#pragma unroll
        for (int j = 0; j < 2; j++) {
            uint32_t off = (uint32_t)(tid + j * 256) * 16;
            if (off < wbytes)
                cp16(sbase[s] + 16384 + off, wsrc + (size_t)s * wstep + off);
        }
        CP_COMMIT();
    }

    float acc[2][4][4];
#pragma unroll
    for (int mt = 0; mt < 2; mt++)
#pragma unroll
        for (int nt = 0; nt < 4; nt++)
#pragma unroll
            for (int c = 0; c < 4; c++) acc[mt][nt][c] = 0.f;

    CP_WAIT(1);
    __syncthreads();

#pragma unroll 1
    for (int it = 0; it < 64; it++) {
        if (it > 0) {
            if (it == 63) CP_WAIT(0); else CP_WAIT(1);
            __syncthreads();
        }
        if (it + 2 < 64) {
            uint32_t sb = sbase[(it + 2) % 3];
#pragma unroll
            for (int j = 0; j < 4; j++) {
                uint32_t off = (uint32_t)(tid + j * 256) * 16;
                cp16(sb + off, xsrc + (size_t)(it + 2) * 16384 + off);
            }
#pragma unroll
            for (int j = 0; j < 2; j++) {
                uint32_t off = (uint32_t)(tid + j * 256) * 16;
                if (off < wbytes)
                    cp16(sb + 16384 + off, wsrc + (size_t)(it + 2) * wstep + off);
            }
        }
        CP_COMMIT();

        const uint32_t cb = sbase[it % 3];
        uint32_t bfr[2][4][4];
#pragma unroll
        for (int ntp = 0; ntp < 2; ntp++)
#pragma unroll
            for (int ks = 0; ks < 4; ks++) ldsm4(bfr[ntp][ks], cb + boff[ntp][ks]);

#pragma unroll
        for (int mt = 0; mt < 2; mt++) {
            uint32_t af[4][4];
#pragma unroll
            for (int ks = 0; ks < 4; ks++) ldsm4(af[ks], cb + aoff[mt][ks]);
            mma_split3_x4(acc[mt][0], acc[mt][1], acc[mt][2], acc[mt][3],
                          af, bfr[0], bfr[1]);
        }
    }

    // epilogue
#pragma unroll
    for (int mt = 0; mt < 2; mt++)
#pragma unroll
        for (int rp = 0; rp < 2; rp++) {
            const int r = m0 + mt * 16 + (lane >> 2) + rp * 8;
#pragma unroll
            for (int nt = 0; nt < 4; nt++) {
                const int colL = n0 + nt * 8 + (lane & 3) * 2;
                const float v0 = acc[mt][nt][rp * 2];
                const float v1 = acc[mt][nt][rp * 2 + 1];
                if (!iskw) {
                    const int col = nT * 64 + colL;
                    const int head = col >> 5;
                    const int d = col & 31;
                    uint32_t hi, lo;
                    split2(v0, v1, hi, lo);
                    char* dst = g_qext + ((size_t)mTile * 16 + head) * 16384;
                    *(uint32_t*)(dst + sw128((uint32_t)(r * 128 + d * 2)))      = hi;
                    *(uint32_t*)(dst + sw128((uint32_t)(r * 128 + 64 + d * 2))) = lo;
                } else if (colL < 32) {
                    uint32_t hi, lo;
                    split2(v0, v1, hi, lo);
                    char* dst = g_kext + (size_t)mTile * 16384;
                    *(uint32_t*)(dst + sw128((uint32_t)(r * 128 + colL * 2)))      = hi;
                    *(uint32_t*)(dst + sw128((uint32_t)(r * 128 + 64 + colL * 2))) = lo;
                } else if (colL < 48) {
                    *(float2*)(g_w + (size_t)(mTile * 128 + r) * H_ + (colL - 32)) =
                        make_float2(v0, v1);
                }
            }
        }
}

// ===========================================================================
// Fused scores+importance (512 threads, 16 warps 4x4, warp tile 32x32)
//   out[b,q,k] = sum_h w[b,q,h]*relu(dot(q,k))
// K frags register-resident; Q head tiles 3-buffer cp.async, 1 sync/head.
// ===========================================================================
__global__ void __launch_bounds__(512, 1)
fused_mma_kernel(float* __restrict__ out)
{
    extern __shared__ char dsm_raw[];
    char* dsm = (char*)(((uintptr_t)dsm_raw + 1023) & ~(uintptr_t)1023);
    char* Ks   = dsm;                   // 16KB
    char* Qb   = dsm + 16384;           // 3 x 16KB
    float* w_s = (float*)(dsm + 65536); // 8KB

    const int tid  = threadIdx.x;
    const int wid  = tid >> 5;
    const int lane = tid & 31;
    const int b  = blockIdx.z;
    const int q0 = blockIdx.y * 128;
    const int k0 = blockIdx.x * 128;
    const int m0 = (wid & 3) * 32;
    const int n0 = (wid >> 2) * 32;

    const int qTile = b * 32 + blockIdx.y;
    const int kTile = b * 32 + blockIdx.x;
    const char* qsrc = g_qext + (size_t)qTile * 16 * 16384;
    const char* ksrc = g_kext + (size_t)kTile * 16384;
    const float* wsrc = g_w + (size_t)(b * T_ + q0) * H_;

    const uint32_t ksb = smem_u32(Ks);
    const uint32_t wsb_smem = smem_u32(w_s);
    uint32_t qbase[3];
#pragma unroll
    for (int s = 0; s < 3; s++) qbase[s] = smem_u32(Qb + s * 16384);

    // prologue: G0 = {K, w, Q0}, G1 = {Q1}
#pragma unroll
    for (int j = 0; j < 2; j++) {
        uint32_t off = (uint32_t)(tid + j * 512) * 16;
        cp16(ksb + off, ksrc + off);
        cp16(qbase[0] + off, qsrc + off);
    }
    cp16(wsb_smem + (uint32_t)tid * 16, (const char*)wsrc + (uint32_t)tid * 16);
    CP_COMMIT();
#pragma unroll
    for (int j = 0; j < 2; j++) {
        uint32_t off = (uint32_t)(tid + j * 512) * 16;
        cp16(qbase[1] + off, qsrc + 16384 + off);
    }
    CP_COMMIT();

    uint32_t aoff[2][4];
    uint32_t baddr[2][4];
    {
        const int arow = lane & 15, aseg = lane >> 4;
        const int brow = (lane & 7) + ((lane & 16) >> 1);
        const int bseg = (lane >> 3) & 1;
#pragma unroll
        for (int t = 0; t < 2; t++)
#pragma unroll
            for (int ks = 0; ks < 4; ks++) {
                aoff[t][ks] = sw128((uint32_t)((m0 + t * 16 + arow) * 128 +
                                               ks * 32 + aseg * 16));
                baddr[t][ks] = ksb + sw128((uint32_t)((n0 + t * 16 + brow) * 128 +
                                                      ks * 32 + bseg * 16));
            }
    }

    float acc[2][4][4];
#pragma unroll
    for (int mt = 0; mt < 2; mt++)
#pragma unroll
        for (int nt = 0; nt < 4; nt++)
#pragma unroll
            for (int c = 0; c < 4; c++) acc[mt][nt][c] = 0.f;

    CP_WAIT(1);       // G0 done: K, w, Q0
    __syncthreads();

    // K fragments register-resident (this warp's 32 n-cols)
    uint32_t bfr[2][4][4];
#pragma unroll
    for (int ntp = 0; ntp < 2; ntp++)
#pragma unroll
        for (int ks = 0; ks < 4; ks++) ldsm4(bfr[ntp][ks], baddr[ntp][ks]);

    const int wrow0 = m0 + (lane >> 2);

#pragma unroll 1
    for (int h = 0; h < H_; h++) {
        if (h > 0) {
            if (h == H_ - 1) CP_WAIT(0); else CP_WAIT(1);
            __syncthreads();
        }
        if (h + 2 < H_) {
            uint32_t qb = qbase[(h + 2) % 3];
            const char* src = qsrc + (size_t)(h + 2) * 16384;
#pragma unroll
            for (int j = 0; j < 2; j++) {
                uint32_t off = (uint32_t)(tid + j * 512) * 16;
                cp16(qb + off, src + off);
            }
        }
        CP_COMMIT();

        const uint32_t qb = qbase[h % 3];
#pragma unroll
        for (int mt = 0; mt < 2; mt++) {
            uint32_t af[4][4];
#pragma unroll
            for (int ks = 0; ks < 4; ks++) ldsm4(af[ks], qb + aoff[mt][ks]);

            const float wv0 = w_s[(wrow0 + mt * 16) * H_ + h];
            const float wv1 = w_s[(wrow0 + mt * 16 + 8) * H_ + h];

            float s[2][2][4];
#pragma unroll
            for (int ntp = 0; ntp < 2; ntp++)
#pragma unroll
                for (int q = 0; q < 2; q++)
#pragma unroll
                    for (int c = 0; c < 4; c++) s[ntp][q][c] = 0.f;

            mma_split3_x4(s[0][0], s[0][1], s[1][0], s[1][1], af, bfr[0], bfr[1]);

#pragma unroll
            for (int ntp = 0; ntp < 2; ntp++)
#pragma unroll
                for (int q = 0; q < 2; q++) {
                    float* a = acc[mt][ntp * 2 + q];
                    const float* sv = s[ntp][q];
                    a[0] += wv0 * fmaxf(sv[0], 0.f);
                    a[1] += wv0 * fmaxf(sv[1], 0.f);
                    a[2] += wv1 * fmaxf(sv[2], 0.f);
                    a[3] += wv1 * fmaxf(sv[3], 0.f);
                }
        }
    }

    // epilogue
#pragma unroll
    for (int mt = 0; mt < 2; mt++)
#pragma unroll
        for (int rp = 0; rp < 2; rp++) {
            const int row = q0 + m0 + mt * 16 + (lane >> 2) + rp * 8;
            float* op = out + (size_t)(b * T_ + row) * T_ + k0 + n0 + (lane & 3) * 2;
#pragma unroll
            for (int nt = 0; nt < 4; nt++)
                *(float2*)(op + nt * 8) =
                    make_float2(acc[mt][nt][rp * 2], acc[mt][nt][rp * 2 + 1]);
        }
}

// ===========================================================================
extern "C" void kernel_launch(void* const* d_in, const int* in_sizes, int n_in,
                              void* d_out, int out_size)
{
    (void)in_sizes; (void)n_in; (void)out_size;
    const float* x  = (const float*)d_in[0];
    const float* Wq = (const float*)d_in[1];
    const float* Wk = (const float*)d_in[2];
    const float* Ww = (const float*)d_in[3];
    float* out = (float*)d_out;

    static bool attr_done = false;
    if (!attr_done) {
        cudaFuncSetAttribute(proj_mma_kernel,
                             cudaFuncAttributeMaxDynamicSharedMemorySize, 74752);
        cudaFuncSetAttribute(fused_mma_kernel,
                             cudaFuncAttributeMaxDynamicSharedMemorySize, 74752);
        attr_done = true;
    }

    cvt_x_kernel<<<dim3(64, 64), 256>>>(x);
    cvt_wq_kernel<<<dim3(64, 4), 256>>>(Wq);
    cvt_wkw_kernel<<<64, 256>>>(Wk, Ww);

    proj_mma_kernel<<<dim3(9, 64), 256, 74752>>>();
    fused_mma_kernel<<<dim3(T_ / 128, T_ / 128, B_), 512, 74752>>>(out);
}

// round 8
// speedup vs baseline: 3.4492x; 1.0984x over previous
#include <cuda_runtime.h>
#include <cuda_bf16.h>
#include <cstdint>

// Problem constants
#define B_ 2
#define T_ 4096
#define C_ 2048
#define H_ 16
#define D_ 32

// ---------------------------------------------------------------------------
// Ext-bf16 tile format: a 128-row x 32-f32-col operand block is stored as
// 16384 bytes; logical (row r, ext col c in [0,64): c<32 = hi of d=c,
// c>=32 = lo of d=c-32) lives at byte offset sw128(r*128 + c*2).
// Gmem byte order == smem byte order -> plain 16B cp.async copies.
// ---------------------------------------------------------------------------
__device__ __align__(1024) char g_xext [(size_t)64 * 64 * 16384];  // [rowTile][kStep]
__device__ __align__(1024) char g_wqext[(size_t)4  * 64 * 16384];  // [nTile][kStep]
__device__ __align__(1024) char g_kwext[(size_t)64 * 6144];        // [kStep] 48 rows
__device__ __align__(1024) char g_qext [(size_t)64 * 16 * 16384];  // [qTile][head]
__device__ __align__(1024) char g_kext [(size_t)64 * 16384];       // [kTile]
__device__ __align__(1024) float g_w[(size_t)B_ * T_ * H_];        // [8192][16]

// ===========================================================================
// Helpers (base sm_103-safe: ldmatrix + mma.sync + cp.async)
// ===========================================================================
__device__ __forceinline__ uint32_t smem_u32(const void* p) {
    uint32_t a;
    asm("{ .reg .u64 t; cvta.to.shared.u64 t, %1; cvt.u32.u64 %0, t; }"
        : "=r"(a) : "l"(p));
    return a;
}

__device__ __forceinline__ uint32_t sw128(uint32_t o) { return o ^ ((o >> 3) & 0x70); }

__device__ __forceinline__ void ldsm4(uint32_t* r, uint32_t a) {
    asm volatile("ldmatrix.sync.aligned.m8n8.x4.shared.b16 {%0,%1,%2,%3}, [%4];"
                 : "=r"(r[0]), "=r"(r[1]), "=r"(r[2]), "=r"(r[3]) : "r"(a));
}

__device__ __forceinline__ void mma_bf16(float* d, const uint32_t* a, const uint32_t* b) {
    asm volatile(
        "mma.sync.aligned.m16n8k16.row.col.f32.bf16.bf16.f32 "
        "{%0,%1,%2,%3}, {%4,%5,%6,%7}, {%8,%9}, {%0,%1,%2,%3};"
        : "+f"(d[0]), "+f"(d[1]), "+f"(d[2]), "+f"(d[3])
        : "r"(a[0]), "r"(a[1]), "r"(a[2]), "r"(a[3]), "r"(b[0]), "r"(b[1]));
}

__device__ __forceinline__ void cp16(uint32_t s, const void* g) {
    asm volatile("cp.async.cg.shared.global [%0], [%1], 16;" :: "r"(s), "l"(g));
}
#define CP_COMMIT() asm volatile("cp.async.commit_group;" ::: "memory")
#define CP_WAIT(n)  asm volatile("cp.async.wait_group %0;" :: "n"(n) : "memory")

__device__ __forceinline__ uint32_t pack2bf(float x, float y) {
    __nv_bfloat16 bx = __float2bfloat16_rn(x), by = __float2bfloat16_rn(y);
    return ((uint32_t)__bfloat16_as_ushort(by) << 16) | (uint32_t)__bfloat16_as_ushort(bx);
}

__device__ __forceinline__ void split2(float v0, float v1, uint32_t& hi, uint32_t& lo) {
    __nv_bfloat16 h0 = __float2bfloat16_rn(v0), h1 = __float2bfloat16_rn(v1);
    hi = ((uint32_t)__bfloat16_as_ushort(h1) << 16) | (uint32_t)__bfloat16_as_ushort(h0);
    lo = pack2bf(v0 - __bfloat162float(h0), v1 - __bfloat162float(h1));
}

__device__ __forceinline__ void cvt_store4(char* tile, uint32_t base_off, float4 v) {
    uint32_t hi0, lo0, hi1, lo1;
    split2(v.x, v.y, hi0, lo0);
    split2(v.z, v.w, hi1, lo1);
    *(uint2*)(tile + sw128(base_off))      = make_uint2(hi0, hi1);
    *(uint2*)(tile + sw128(base_off + 64)) = make_uint2(lo0, lo1);
}

// 3-term split product over FOUR independent accumulator chains, issued
// round-robin so same-chain MMAs are 4 issues apart (hides HMMA RAW latency).
// frag 0,1 = hi k-steps; 2,3 = lo k-steps.  s = a_hi*b_hi + a_hi*b_lo + a_lo*b_hi
__device__ __forceinline__ void mma_split3_x4(float* s00, float* s01,
                                              float* s10, float* s11,
                                              const uint32_t af[4][4],
                                              const uint32_t b0[4][4],
                                              const uint32_t b1[4][4]) {
    const int PA[6] = {0, 1, 0, 1, 2, 3};
    const int PB[6] = {0, 1, 2, 3, 0, 1};
#pragma unroll
    for (int p = 0; p < 6; p++) {
        mma_bf16(s00, af[PA[p]], &b0[PB[p]][0]);
        mma_bf16(s01, af[PA[p]], &b0[PB[p]][2]);
        mma_bf16(s10, af[PA[p]], &b1[PB[p]][0]);
        mma_bf16(s11, af[PA[p]], &b1[PB[p]][2]);
    }
}

// ===========================================================================
// Conversion passes: f32 row-major -> ext-bf16 swizzled tiles in gmem
// ===========================================================================
__global__ void __launch_bounds__(256)
cvt_x_kernel(const float* __restrict__ X)
{
    const int kStep = blockIdx.x, rowTile = blockIdx.y;
    const int tid = threadIdx.x;
    const int r  = tid >> 1;
    const int ce = (tid & 1) * 16;
    const float* src = X + (size_t)(rowTile * 128 + r) * C_ + kStep * 32 + ce;
    char* dst = g_xext + ((size_t)rowTile * 64 + kStep) * 16384;
#pragma unroll
    for (int i = 0; i < 4; i++)
        cvt_store4(dst, (uint32_t)(r * 128 + (ce + 4 * i) * 2), *(const float4*)(src + 4 * i));
}

__global__ void __launch_bounds__(256)
cvt_wq_kernel(const float* __restrict__ W)
{
    const int kStep = blockIdx.x, nTile = blockIdx.y;
    const int tid = threadIdx.x;
    const int r  = tid >> 1;
    const int ce = (tid & 1) * 16;
    const float* src = W + (size_t)(nTile * 128 + r) * C_ + kStep * 32 + ce;
    char* dst = g_wqext + ((size_t)nTile * 64 + kStep) * 16384;
#pragma unroll
    for (int i = 0; i < 4; i++)
        cvt_store4(dst, (uint32_t)(r * 128 + (ce + 4 * i) * 2), *(const float4*)(src + 4 * i));
}

__global__ void __launch_bounds__(256)
cvt_wkw_kernel(const float* __restrict__ Wk, const float* __restrict__ Ww)
{
    const int kStep = blockIdx.x;
    const int tid = threadIdx.x;
    if (tid >= 96) return;
    const int r  = tid >> 1;
    const int ce = (tid & 1) * 16;
    const float* src = (r < 32) ? (Wk + (size_t)r * C_ + kStep * 32 + ce)
                                : (Ww + (size_t)(r - 32) * C_ + kStep * 32 + ce);
    char* dst = g_kwext + (size_t)kStep * 6144;
#pragma unroll
    for (int i = 0; i < 4; i++)
        cvt_store4(dst, (uint32_t)(r * 128 + (ce + 4 * i) * 2), *(const float4*)(src + 4 * i));
}

// ===========================================================================
// Unified projection kernel. grid (9, 64):
//   nT in 0..7 : Q-proj, 64 output cols (nT*64..), writes g_qext
//   nT == 8    : K+W proj (48 cols from g_kwext), writes g_kext + g_w
// CTA: 128(m) x 64(n), 256 threads, 8 warps 4(m) x 2(n), warp tile 32x32.
// 3-stage cp.async (16KB X + 8KB W per stage = 72KB), 2 CTAs/SM.
// ===========================================================================
__global__ void __launch_bounds__(256, 2)
proj_mma_kernel()
{
    extern __shared__ char dsm_raw[];
    char* dsm = (char*)(((uintptr_t)dsm_raw + 1023) & ~(uintptr_t)1023);

    const int tid  = threadIdx.x;
    const int wid  = tid >> 5;
    const int lane = tid & 31;
    const int nT    = blockIdx.x;           // 0..8
    const int mTile = blockIdx.y;           // 0..63
    const int m0 = (wid & 3) * 32;
    const int n0 = (wid >> 2) * 32;
    const bool iskw = (nT == 8);

    const char* xsrc = g_xext + (size_t)mTile * 64 * 16384;
    const char* wsrc = iskw ? g_kwext
                            : g_wqext + (size_t)(nT >> 1) * 64 * 16384 + (nT & 1) * 8192;
    const uint32_t wstep  = iskw ? 6144u : 16384u;   // bytes per k-step in gmem
    const uint32_t wbytes = iskw ? 6144u : 8192u;    // bytes to copy per k-step

    uint32_t sbase[3];
#pragma unroll
    for (int s = 0; s < 3; s++) sbase[s] = smem_u32(dsm + s * 24576);

    uint32_t aoff[2][4], boff[2][4];
    {
        const int arow = lane & 15, aseg = lane >> 4;
        const int brow = (lane & 7) + ((lane & 16) >> 1);
        const int bseg = (lane >> 3) & 1;
#pragma unroll
        for (int t = 0; t < 2; t++)
#pragma unroll
            for (int ks = 0; ks < 4; ks++) {
                aoff[t][ks] = sw128((uint32_t)((m0 + t * 16 + arow) * 128 +
                                               ks * 32 + aseg * 16));
                boff[t][ks] = 16384u + sw128((uint32_t)((n0 + t * 16 + brow) * 128 +
                                                        ks * 32 + bseg * 16));
            }
    }

    // prologue: stages 0,1
#pragma unroll
    for (int s = 0; s < 2; s++) {
#pragma unroll
        for (int j = 0; j < 4; j++) {
            uint32_t off = (uint32_t)(tid + j * 256) * 16;
            cp16(sbase[s] + off, xsrc + (size_t)s * 16384 + off);
        }
#pragma unroll
        for (int j = 0; j < 2; j++) {
            uint32_t off = (uint32_t)(tid + j * 256) * 16;
            if (off < wbytes)
                cp16(sbase[s] + 16384 + off, wsrc + (size_t)s * wstep + off);
        }
        CP_COMMIT();
    }

    float acc[2][4][4];
#pragma unroll
    for (int mt = 0; mt < 2; mt++)
#pragma unroll
        for (int nt = 0; nt < 4; nt++)
#pragma unroll
            for (int c = 0; c < 4; c++) acc[mt][nt][c] = 0.f;

    CP_WAIT(1);
    __syncthreads();

#pragma unroll 1
    for (int it = 0; it < 64; it++) {
        if (it > 0) {
            if (it == 63) CP_WAIT(0); else CP_WAIT(1);
            __syncthreads();
        }
        if (it + 2 < 64) {
            uint32_t sb = sbase[(it + 2) % 3];
#pragma unroll
            for (int j = 0; j < 4; j++) {
                uint32_t off = (uint32_t)(tid + j * 256) * 16;
                cp16(sb + off, xsrc + (size_t)(it + 2) * 16384 + off);
            }
#pragma unroll
            for (int j = 0; j < 2; j++) {
                uint32_t off = (uint32_t)(tid + j * 256) * 16;
                if (off < wbytes)
                    cp16(sb + 16384 + off, wsrc + (size_t)(it + 2) * wstep + off);
            }
        }
        CP_COMMIT();

        const uint32_t cb = sbase[it % 3];
        uint32_t bfr[2][4][4];
#pragma unroll
        for (int ntp = 0; ntp < 2; ntp++)
#pragma unroll
            for (int ks = 0; ks < 4; ks++) ldsm4(bfr[ntp][ks], cb + boff[ntp][ks]);

#pragma unroll
        for (int mt = 0; mt < 2; mt++) {
            uint32_t af[4][4];
#pragma unroll
            for (int ks = 0; ks < 4; ks++) ldsm4(af[ks], cb + aoff[mt][ks]);
            mma_split3_x4(acc[mt][0], acc[mt][1], acc[mt][2], acc[mt][3],
                          af, bfr[0], bfr[1]);
        }
    }

    // epilogue
#pragma unroll
    for (int mt = 0; mt < 2; mt++)
#pragma unroll
        for (int rp = 0; rp < 2; rp++) {
            const int r = m0 + mt * 16 + (lane >> 2) + rp * 8;
#pragma unroll
            for (int nt = 0; nt < 4; nt++) {
                const int colL = n0 + nt * 8 + (lane & 3) * 2;
                const float v0 = acc[mt][nt][rp * 2];
                const float v1 = acc[mt][nt][rp * 2 + 1];
                if (!iskw) {
                    const int col = nT * 64 + colL;
                    const int head = col >> 5;
                    const int d = col & 31;
                    uint32_t hi, lo;
                    split2(v0, v1, hi, lo);
                    char* dst = g_qext + ((size_t)mTile * 16 + head) * 16384;
                    *(uint32_t*)(dst + sw128((uint32_t)(r * 128 + d * 2)))      = hi;
                    *(uint32_t*)(dst + sw128((uint32_t)(r * 128 + 64 + d * 2))) = lo;
                } else if (colL < 32) {
                    uint32_t hi, lo;
                    split2(v0, v1, hi, lo);
                    char* dst = g_kext + (size_t)mTile * 16384;
                    *(uint32_t*)(dst + sw128((uint32_t)(r * 128 + colL * 2)))      = hi;
                    *(uint32_t*)(dst + sw128((uint32_t)(r * 128 + 64 + colL * 2))) = lo;
                } else if (colL < 48) {
                    *(float2*)(g_w + (size_t)(mTile * 128 + r) * H_ + (colL - 32)) =
                        make_float2(v0, v1);
                }
            }
        }
}

// ===========================================================================
// Fused scores+importance: out[b,q,k] = sum_h w[b,q,h]*relu(dot(q,k))
// CTA = 128(q) x 64(k), 256 threads, 8 warps 4(m)x2(n), 2 CTAs/SM.
// K 64-row slice (8KB) register-resident; Q head tiles 3-buffer cp.async.
// ===========================================================================
__global__ void __launch_bounds__(256, 2)
fused_mma_kernel(float* __restrict__ out)
{
    extern __shared__ char dsm_raw[];
    char* dsm = (char*)(((uintptr_t)dsm_raw + 1023) & ~(uintptr_t)1023);
    char* Ks   = dsm;                   // 8KB (64 rows)
    char* Qb   = dsm + 8192;            // 3 x 16KB
    float* w_s = (float*)(dsm + 57344); // 8KB

    const int tid  = threadIdx.x;
    const int wid  = tid >> 5;
    const int lane = tid & 31;
    const int b  = blockIdx.z;
    const int kT = blockIdx.x;          // 0..63 (64-col k tiles)
    const int q0 = blockIdx.y * 128;
    const int k0 = kT * 64;
    const int m0 = (wid & 3) * 32;
    const int n0 = (wid >> 2) * 32;     // 0 or 32 within the 64-col slice

    const int qTile = b * 32 + blockIdx.y;
    const char* qsrc = g_qext + (size_t)qTile * 16 * 16384;
    const char* ksrc = g_kext + (size_t)(b * 32 + (kT >> 1)) * 16384 + (kT & 1) * 8192;
    const float* wsrc = g_w + (size_t)(b * T_ + q0) * H_;

    const uint32_t ksb = smem_u32(Ks);
    const uint32_t wsb_smem = smem_u32(w_s);
    uint32_t qbase[3];
#pragma unroll
    for (int s = 0; s < 3; s++) qbase[s] = smem_u32(Qb + s * 16384);

    // prologue: G0 = {K, w, Q0}, G1 = {Q1}
#pragma unroll
    for (int j = 0; j < 2; j++) {
        uint32_t off = (uint32_t)(tid + j * 256) * 16;
        cp16(ksb + off, ksrc + off);
        cp16(wsb_smem + off, (const char*)wsrc + off);
    }
#pragma unroll
    for (int j = 0; j < 4; j++) {
        uint32_t off = (uint32_t)(tid + j * 256) * 16;
        cp16(qbase[0] + off, qsrc + off);
    }
    CP_COMMIT();
#pragma unroll
    for (int j = 0; j < 4; j++) {
        uint32_t off = (uint32_t)(tid + j * 256) * 16;
        cp16(qbase[1] + off, qsrc + 16384 + off);
    }
    CP_COMMIT();

    uint32_t aoff[2][4];
    uint32_t baddr[2][4];
    {
        const int arow = lane & 15, aseg = lane >> 4;
        const int brow = (lane & 7) + ((lane & 16) >> 1);
        const int bseg = (lane >> 3) & 1;
#pragma unroll
        for (int t = 0; t < 2; t++)
#pragma unroll
            for (int ks = 0; ks < 4; ks++) {
                aoff[t][ks] = sw128((uint32_t)((m0 + t * 16 + arow) * 128 +
                                               ks * 32 + aseg * 16));
                baddr[t][ks] = ksb + sw128((uint32_t)((n0 + t * 16 + brow) * 128 +
                                                      ks * 32 + bseg * 16));
            }
    }

    float acc[2][4][4];
#pragma unroll
    for (int mt = 0; mt < 2; mt++)
#pragma unroll
        for (int nt = 0; nt < 4; nt++)
#pragma unroll
            for (int c = 0; c < 4; c++) acc[mt][nt][c] = 0.f;

    CP_WAIT(1);       // G0 done: K, w, Q0
    __syncthreads();

    // K fragments register-resident (this warp's 32 n-cols of the 64-row slice)
    uint32_t bfr[2][4][4];
#pragma unroll
    for (int ntp = 0; ntp < 2; ntp++)
#pragma unroll
        for (int ks = 0; ks < 4; ks++) ldsm4(bfr[ntp][ks], baddr[ntp][ks]);

    const int wrow0 = m0 + (lane >> 2);

#pragma unroll 1
    for (int h = 0; h < H_; h++) {
        if (h > 0) {
            if (h == H_ - 1) CP_WAIT(0); else CP_WAIT(1);
            __syncthreads();
        }
        if (h + 2 < H_) {
            uint32_t qb = qbase[(h + 2) % 3];
            const char* src = qsrc + (size_t)(h + 2) * 16384;
#pragma unroll
            for (int j = 0; j < 4; j++) {
                uint32_t off = (uint32_t)(tid + j * 256) * 16;
                cp16(qb + off, src + off);
            }
        }
        CP_COMMIT();

        const uint32_t qb = qbase[h % 3];
#pragma unroll
        for (int mt = 0; mt < 2; mt++) {
            uint32_t af[4][4];
#pragma unroll
            for (int ks = 0; ks < 4; ks++) ldsm4(af[ks], qb + aoff[mt][ks]);

            const float wv0 = w_s[(wrow0 + mt * 16) * H_ + h];
            const float wv1 = w_s[(wrow0 + mt * 16 + 8) * H_ + h];

            float s[2][2][4];
#pragma unroll
            for (int ntp = 0; ntp < 2; ntp++)
#pragma unroll
                for (int q = 0; q < 2; q++)
#pragma unroll
                    for (int c = 0; c < 4; c++) s[ntp][q][c] = 0.f;

            mma_split3_x4(s[0][0], s[0][1], s[1][0], s[1][1], af, bfr[0], bfr[1]);

#pragma unroll
            for (int ntp = 0; ntp < 2; ntp++)
#pragma unroll
                for (int q = 0; q < 2; q++) {
                    float* a = acc[mt][ntp * 2 + q];
                    const float* sv = s[ntp][q];
                    a[0] += wv0 * fmaxf(sv[0], 0.f);
                    a[1] += wv0 * fmaxf(sv[1], 0.f);
                    a[2] += wv1 * fmaxf(sv[2], 0.f);
                    a[3] += wv1 * fmaxf(sv[3], 0.f);
                }
        }
    }

    // epilogue
#pragma unroll
    for (int mt = 0; mt < 2; mt++)
#pragma unroll
        for (int rp = 0; rp < 2; rp++) {
            const int row = q0 + m0 + mt * 16 + (lane >> 2) + rp * 8;
            float* op = out + (size_t)(b * T_ + row) * T_ + k0 + n0 + (lane & 3) * 2;
#pragma unroll
            for (int nt = 0; nt < 4; nt++)
                *(float2*)(op + nt * 8) =
                    make_float2(acc[mt][nt][rp * 2], acc[mt][nt][rp * 2 + 1]);
        }
}

// ===========================================================================
extern "C" void kernel_launch(void* const* d_in, const int* in_sizes, int n_in,
                              void* d_out, int out_size)
{
    (void)in_sizes; (void)n_in; (void)out_size;
    const float* x  = (const float*)d_in[0];
    const float* Wq = (const float*)d_in[1];
    const float* Wk = (const float*)d_in[2];
    const float* Ww = (const float*)d_in[3];
    float* out = (float*)d_out;

    static bool attr_done = false;
    if (!attr_done) {
        cudaFuncSetAttribute(proj_mma_kernel,
                             cudaFuncAttributeMaxDynamicSharedMemorySize, 74752);
        cudaFuncSetAttribute(fused_mma_kernel,
                             cudaFuncAttributeMaxDynamicSharedMemorySize, 66560);
        attr_done = true;
    }

    cvt_x_kernel<<<dim3(64, 64), 256>>>(x);
    cvt_wq_kernel<<<dim3(64, 4), 256>>>(Wq);
    cvt_wkw_kernel<<<64, 256>>>(Wk, Ww);

    proj_mma_kernel<<<dim3(9, 64), 256, 74752>>>();
    fused_mma_kernel<<<dim3(T_ / 64, T_ / 128, B_), 256, 66560>>>(out);
}

// round 9
// speedup vs baseline: 3.5237x; 1.0216x over previous
#include <cuda_runtime.h>
#include <cuda_bf16.h>
#include <cstdint>

// Problem constants
#define B_ 2
#define T_ 4096
#define C_ 2048
#define H_ 16
#define D_ 32

// ---------------------------------------------------------------------------
// Ext-bf16 tile format: a 128-row x 32-f32-col operand block is stored as
// 16384 bytes; logical (row r, ext col c in [0,64): c<32 = hi of d=c,
// c>=32 = lo of d=c-32) lives at byte offset sw128(r*128 + c*2).
// Gmem byte order == smem byte order -> plain 16B cp.async copies.
// ---------------------------------------------------------------------------
__device__ __align__(1024) char g_xext [(size_t)64 * 64 * 16384];  // [rowTile][kStep]
__device__ __align__(1024) char g_wqext[(size_t)4  * 64 * 16384];  // [nTile][kStep]
__device__ __align__(1024) char g_kwext[(size_t)64 * 6144];        // [kStep] 48 rows
__device__ __align__(1024) char g_qext [(size_t)64 * 16 * 16384];  // [qTile][head]
__device__ __align__(1024) char g_kext [(size_t)64 * 16384];       // [kTile]
__device__ __align__(1024) float g_w[(size_t)B_ * T_ * H_];        // [8192][16]

// ===========================================================================
// Helpers (base sm_103-safe: ldmatrix + mma.sync + cp.async)
// ===========================================================================
__device__ __forceinline__ uint32_t smem_u32(const void* p) {
    uint32_t a;
    asm("{ .reg .u64 t; cvta.to.shared.u64 t, %1; cvt.u32.u64 %0, t; }"
        : "=r"(a) : "l"(p));
    return a;
}

__device__ __forceinline__ uint32_t sw128(uint32_t o) { return o ^ ((o >> 3) & 0x70); }

__device__ __forceinline__ void ldsm4(uint32_t* r, uint32_t a) {
    asm volatile("ldmatrix.sync.aligned.m8n8.x4.shared.b16 {%0,%1,%2,%3}, [%4];"
                 : "=r"(r[0]), "=r"(r[1]), "=r"(r[2]), "=r"(r[3]) : "r"(a));
}

__device__ __forceinline__ void mma_bf16(float* d, const uint32_t* a, const uint32_t* b) {
    asm volatile(
        "mma.sync.aligned.m16n8k16.row.col.f32.bf16.bf16.f32 "
        "{%0,%1,%2,%3}, {%4,%5,%6,%7}, {%8,%9}, {%0,%1,%2,%3};"
        : "+f"(d[0]), "+f"(d[1]), "+f"(d[2]), "+f"(d[3])
        : "r"(a[0]), "r"(a[1]), "r"(a[2]), "r"(a[3]), "r"(b[0]), "r"(b[1]));
}

__device__ __forceinline__ void cp16(uint32_t s, const void* g) {
    asm volatile("cp.async.cg.shared.global [%0], [%1], 16;" :: "r"(s), "l"(g));
}
#define CP_COMMIT() asm volatile("cp.async.commit_group;" ::: "memory")
#define CP_WAIT(n)  asm volatile("cp.async.wait_group %0;" :: "n"(n) : "memory")

__device__ __forceinline__ uint32_t pack2bf(float x, float y) {
    __nv_bfloat16 bx = __float2bfloat16_rn(x), by = __float2bfloat16_rn(y);
    return ((uint32_t)__bfloat16_as_ushort(by) << 16) | (uint32_t)__bfloat16_as_ushort(bx);
}

__device__ __forceinline__ void split2(float v0, float v1, uint32_t& hi, uint32_t& lo) {
    __nv_bfloat16 h0 = __float2bfloat16_rn(v0), h1 = __float2bfloat16_rn(v1);
    hi = ((uint32_t)__bfloat16_as_ushort(h1) << 16) | (uint32_t)__bfloat16_as_ushort(h0);
    lo = pack2bf(v0 - __bfloat162float(h0), v1 - __bfloat162float(h1));
}

__device__ __forceinline__ void cvt_store4(char* tile, uint32_t base_off, float4 v) {
    uint32_t hi0, lo0, hi1, lo1;
    split2(v.x, v.y, hi0, lo0);
    split2(v.z, v.w, hi1, lo1);
    *(uint2*)(tile + sw128(base_off))      = make_uint2(hi0, hi1);
    *(uint2*)(tile + sw128(base_off + 64)) = make_uint2(lo0, lo1);
}

// 3-term split product over FOUR independent accumulator chains, issued
// round-robin so same-chain MMAs are 4 issues apart (hides HMMA RAW latency).
// frag 0,1 = hi k-steps; 2,3 = lo k-steps.  s = a_hi*b_hi + a_hi*b_lo + a_lo*b_hi
__device__ __forceinline__ void mma_split3_x4(float* s00, float* s01,
                                              float* s10, float* s11,
                                              const uint32_t af[4][4],
                                              const uint32_t b0[4][4],
                                              const uint32_t b1[4][4]) {
    const int PA[6] = {0, 1, 0, 1, 2, 3};
    const int PB[6] = {0, 1, 2, 3, 0, 1};
#pragma unroll
    for (int p = 0; p < 6; p++) {
        mma_bf16(s00, af[PA[p]], &b0[PB[p]][0]);
        mma_bf16(s01, af[PA[p]], &b0[PB[p]][2]);
        mma_bf16(s10, af[PA[p]], &b1[PB[p]][0]);
        mma_bf16(s11, af[PA[p]], &b1[PB[p]][2]);
    }
}

// ===========================================================================
// Merged conversion pass: f32 row-major -> ext-bf16 swizzled tiles in gmem.
// Linear grid: [0,4096) X tiles, [4096,4352) Wq tiles, [4352,4416) WkWw.
// ===========================================================================
__global__ void __launch_bounds__(256)
cvt_all_kernel(const float* __restrict__ X, const float* __restrict__ Wq,
               const float* __restrict__ Wk, const float* __restrict__ Ww)
{
    const int bid = blockIdx.x;
    const int tid = threadIdx.x;
    const int r  = tid >> 1;
    const int ce = (tid & 1) * 16;

    const float* src;
    char* dst;
    if (bid < 4096) {
        const int rowTile = bid >> 6, kStep = bid & 63;
        src = X + (size_t)(rowTile * 128 + r) * C_ + kStep * 32 + ce;
        dst = g_xext + ((size_t)rowTile * 64 + kStep) * 16384;
    } else if (bid < 4352) {
        const int t = bid - 4096;
        const int nTile = t >> 6, kStep = t & 63;
        src = Wq + (size_t)(nTile * 128 + r) * C_ + kStep * 32 + ce;
        dst = g_wqext + ((size_t)nTile * 64 + kStep) * 16384;
    } else {
        const int kStep = bid - 4352;
        if (tid >= 96) return;
        src = (r < 32) ? (Wk + (size_t)r * C_ + kStep * 32 + ce)
                       : (Ww + (size_t)(r - 32) * C_ + kStep * 32 + ce);
        dst = g_kwext + (size_t)kStep * 6144;
    }
#pragma unroll
    for (int i = 0; i < 4; i++)
        cvt_store4(dst, (uint32_t)(r * 128 + (ce + 4 * i) * 2), *(const float4*)(src + 4 * i));
}

// ===========================================================================
// Unified projection kernel. grid (9, 64):
//   nT in 0..7 : Q-proj, 64 output cols (nT*64..), writes g_qext
//   nT == 8    : K+W proj (48 cols from g_kwext), writes g_kext + g_w
// CTA: 128(m) x 64(n), 256 threads, 8 warps 4(m) x 2(n), warp tile 32x32.
// 3-stage cp.async (16KB X + 8KB W per stage = 72KB), 2 CTAs/SM.
// ===========================================================================
__global__ void __launch_bounds__(256, 2)
proj_mma_kernel()
{
    extern __shared__ char dsm_raw[];
    char* dsm = (char*)(((uintptr_t)dsm_raw + 1023) & ~(uintptr_t)1023);

    const int tid  = threadIdx.x;
    const int wid  = tid >> 5;
    const int lane = tid & 31;
    const int nT    = blockIdx.x;           // 0..8
    const int mTile = blockIdx.y;           // 0..63
    const int m0 = (wid & 3) * 32;
    const int n0 = (wid >> 2) * 32;
    const bool iskw = (nT == 8);

    const char* xsrc = g_xext + (size_t)mTile * 64 * 16384;
    const char* wsrc = iskw ? g_kwext
                            : g_wqext + (size_t)(nT >> 1) * 64 * 16384 + (nT & 1) * 8192;
    const uint32_t wstep  = iskw ? 6144u : 16384u;   // bytes per k-step in gmem
    const uint32_t wbytes = iskw ? 6144u : 8192u;    // bytes to copy per k-step

    uint32_t sbase[3];
#pragma unroll
    for (int s = 0; s < 3; s++) sbase[s] = smem_u32(dsm + s * 24576);

    uint32_t aoff[2][4], boff[2][4];
    {
        const int arow = lane & 15, aseg = lane >> 4;
        const int brow = (lane & 7) + ((lane & 16) >> 1);
        const int bseg = (lane >> 3) & 1;
#pragma unroll
        for (int t = 0; t < 2; t++)
#pragma unroll
            for (int ks = 0; ks < 4; ks++) {
                aoff[t][ks] = sw128((uint32_t)((m0 + t * 16 + arow) * 128 +
                                               ks * 32 + aseg * 16));
                boff[t][ks] = 16384u + sw128((uint32_t)((n0 + t * 16 + brow) * 128 +
                                                        ks * 32 + bseg * 16));
            }
    }

    // prologue: stages 0,1
#pragma unroll
    for (int s = 0; s < 2; s++) {
#pragma unroll
        for (int j = 0; j < 4; j++) {
            uint32_t off = (uint32_t)(tid + j * 256) * 16;
            cp16(sbase[s] + off, xsrc + (size_t)s * 16384 + off);
        }
#pragma unroll
        for (int j = 0; j < 2; j++) {
            uint32_t off = (uint32_t)(tid + j * 256) * 16;
            if (off < wbytes)
                cp16(sbase[s] + 16384 + off, wsrc + (size_t)s * wstep + off);
        }
        CP_COMMIT();
    }

    float acc[2][4][4];
#pragma unroll
    for (int mt = 0; mt < 2; mt++)
#pragma unroll
        for (int nt = 0; nt < 4; nt++)
#pragma unroll
            for (int c = 0; c < 4; c++) acc[mt][nt][c] = 0.f;

    CP_WAIT(1);
    __syncthreads();

#pragma unroll 1
    for (int it = 0; it < 64; it++) {
        if (it > 0) {
            if (it == 63) CP_WAIT(0); else CP_WAIT(1);
            __syncthreads();
        }
        if (it + 2 < 64) {
            uint32_t sb = sbase[(it + 2) % 3];
#pragma unroll
            for (int j = 0; j < 4; j++) {
                uint32_t off = (uint32_t)(tid + j * 256) * 16;
                cp16(sb + off, xsrc + (size_t)(it + 2) * 16384 + off);
            }
#pragma unroll
            for (int j = 0; j < 2; j++) {
                uint32_t off = (uint32_t)(tid + j * 256) * 16;
                if (off < wbytes)
                    cp16(sb + 16384 + off, wsrc + (size_t)(it + 2) * wstep + off);
            }
        }
        CP_COMMIT();

        const uint32_t cb = sbase[it % 3];
        uint32_t bfr[2][4][4];
#pragma unroll
        for (int ntp = 0; ntp < 2; ntp++)
#pragma unroll
            for (int ks = 0; ks < 4; ks++) ldsm4(bfr[ntp][ks], cb + boff[ntp][ks]);

#pragma unroll
        for (int mt = 0; mt < 2; mt++) {
            uint32_t af[4][4];
#pragma unroll
            for (int ks = 0; ks < 4; ks++) ldsm4(af[ks], cb + aoff[mt][ks]);
            mma_split3_x4(acc[mt][0], acc[mt][1], acc[mt][2], acc[mt][3],
                          af, bfr[0], bfr[1]);
        }
    }

    // epilogue
#pragma unroll
    for (int mt = 0; mt < 2; mt++)
#pragma unroll
        for (int rp = 0; rp < 2; rp++) {
            const int r = m0 + mt * 16 + (lane >> 2) + rp * 8;
#pragma unroll
            for (int nt = 0; nt < 4; nt++) {
                const int colL = n0 + nt * 8 + (lane & 3) * 2;
                const float v0 = acc[mt][nt][rp * 2];
                const float v1 = acc[mt][nt][rp * 2 + 1];
                if (!iskw) {
                    const int col = nT * 64 + colL;
                    const int head = col >> 5;
                    const int d = col & 31;
                    uint32_t hi, lo;
                    split2(v0, v1, hi, lo);
                    char* dst = g_qext + ((size_t)mTile * 16 + head) * 16384;
                    *(uint32_t*)(dst + sw128((uint32_t)(r * 128 + d * 2)))      = hi;
                    *(uint32_t*)(dst + sw128((uint32_t)(r * 128 + 64 + d * 2))) = lo;
                } else if (colL < 32) {
                    uint32_t hi, lo;
                    split2(v0, v1, hi, lo);
                    char* dst = g_kext + (size_t)mTile * 16384;
                    *(uint32_t*)(dst + sw128((uint32_t)(r * 128 + colL * 2)))      = hi;
                    *(uint32_t*)(dst + sw128((uint32_t)(r * 128 + 64 + colL * 2))) = lo;
                } else if (colL < 48) {
                    *(float2*)(g_w + (size_t)(mTile * 128 + r) * H_ + (colL - 32)) =
                        make_float2(v0, v1);
                }
            }
        }
}

// ===========================================================================
// Fused scores+importance: out[b,q,k] = sum_h w[b,q,h]*relu(dot(q,k))
// CTA = 128(q) x 64(k), 256 threads, 8 warps 4(m)x2(n), 2 CTAs/SM.
// K 64-row slice (8KB) register-resident; Q streamed 2 HEADS per stage
// (3 x 32KB ring) -> 8 sync points instead of 16.
// ===========================================================================
__global__ void __launch_bounds__(256, 2)
fused_mma_kernel(float* __restrict__ out)
{
    extern __shared__ char dsm_raw[];
    char* dsm = (char*)(((uintptr_t)dsm_raw + 1023) & ~(uintptr_t)1023);
    char* Ks   = dsm;                    // 8KB (64 rows)
    char* Qb   = dsm + 8192;             // 3 x 32KB (2 heads per stage)
    float* w_s = (float*)(dsm + 106496); // 8KB

    const int tid  = threadIdx.x;
    const int wid  = tid >> 5;
    const int lane = tid & 31;
    const int b  = blockIdx.z;
    const int kT = blockIdx.x;          // 0..63 (64-col k tiles)
    const int q0 = blockIdx.y * 128;
    const int k0 = kT * 64;
    const int m0 = (wid & 3) * 32;
    const int n0 = (wid >> 2) * 32;     // 0 or 32 within the 64-col slice

    const int qTile = b * 32 + blockIdx.y;
    const char* qsrc = g_qext + (size_t)qTile * 16 * 16384;
    const char* ksrc = g_kext + (size_t)(b * 32 + (kT >> 1)) * 16384 + (kT & 1) * 8192;
    const float* wsrc = g_w + (size_t)(b * T_ + q0) * H_;

    const uint32_t ksb = smem_u32(Ks);
    const uint32_t wsb_smem = smem_u32(w_s);
    uint32_t qbase[3];
#pragma unroll
    for (int s = 0; s < 3; s++) qbase[s] = smem_u32(Qb + s * 32768);

    // prologue: G0 = {K, w, headpair 0}, G1 = {headpair 1}
#pragma unroll
    for (int j = 0; j < 2; j++) {
        uint32_t off = (uint32_t)(tid + j * 256) * 16;
        cp16(ksb + off, ksrc + off);
        cp16(wsb_smem + off, (const char*)wsrc + off);
    }
#pragma unroll
    for (int j = 0; j < 8; j++) {
        uint32_t off = (uint32_t)(tid + j * 256) * 16;
        cp16(qbase[0] + off, qsrc + off);
    }
    CP_COMMIT();
#pragma unroll
    for (int j = 0; j < 8; j++) {
        uint32_t off = (uint32_t)(tid + j * 256) * 16;
        cp16(qbase[1] + off, qsrc + 32768 + off);
    }
    CP_COMMIT();

    uint32_t aoff[2][4];
    uint32_t baddr[2][4];
    {
        const int arow = lane & 15, aseg = lane >> 4;
        const int brow = (lane & 7) + ((lane & 16) >> 1);
        const int bseg = (lane >> 3) & 1;
#pragma unroll
        for (int t = 0; t < 2; t++)
#pragma unroll
            for (int ks = 0; ks < 4; ks++) {
                aoff[t][ks] = sw128((uint32_t)((m0 + t * 16 + arow) * 128 +
                                               ks * 32 + aseg * 16));
                baddr[t][ks] = ksb + sw128((uint32_t)((n0 + t * 16 + brow) * 128 +
                                                      ks * 32 + bseg * 16));
            }
    }

    float acc[2][4][4];
#pragma unroll
    for (int mt = 0; mt < 2; mt++)
#pragma unroll
        for (int nt = 0; nt < 4; nt++)
#pragma unroll
            for (int c = 0; c < 4; c++) acc[mt][nt][c] = 0.f;

    CP_WAIT(1);       // G0 done: K, w, headpair 0
    __syncthreads();

    // K fragments register-resident (this warp's 32 n-cols of the 64-row slice)
    uint32_t bfr[2][4][4];
#pragma unroll
    for (int ntp = 0; ntp < 2; ntp++)
#pragma unroll
        for (int ks = 0; ks < 4; ks++) ldsm4(bfr[ntp][ks], baddr[ntp][ks]);

    const int wrow0 = m0 + (lane >> 2);

#pragma unroll 1
    for (int p = 0; p < H_ / 2; p++) {      // head pairs
        if (p > 0) {
            if (p == H_ / 2 - 1) CP_WAIT(0); else CP_WAIT(1);
            __syncthreads();
        }
        if (p + 2 < H_ / 2) {
            uint32_t qb = qbase[(p + 2) % 3];
            const char* src = qsrc + (size_t)(p + 2) * 32768;
#pragma unroll
            for (int j = 0; j < 8; j++) {
                uint32_t off = (uint32_t)(tid + j * 256) * 16;
                cp16(qb + off, src + off);
            }
        }
        CP_COMMIT();

        const uint32_t qb = qbase[p % 3];
#pragma unroll
        for (int hh = 0; hh < 2; hh++) {
            const int h = p * 2 + hh;
            const uint32_t qbh = qb + (uint32_t)hh * 16384u;
#pragma unroll
            for (int mt = 0; mt < 2; mt++) {
                uint32_t af[4][4];
#pragma unroll
                for (int ks = 0; ks < 4; ks++) ldsm4(af[ks], qbh + aoff[mt][ks]);

                const float wv0 = w_s[(wrow0 + mt * 16) * H_ + h];
                const float wv1 = w_s[(wrow0 + mt * 16 + 8) * H_ + h];

                float s[2][2][4];
#pragma unroll
                for (int ntp = 0; ntp < 2; ntp++)
#pragma unroll
                    for (int q = 0; q < 2; q++)
#pragma unroll
                        for (int c = 0; c < 4; c++) s[ntp][q][c] = 0.f;

                mma_split3_x4(s[0][0], s[0][1], s[1][0], s[1][1], af, bfr[0], bfr[1]);

#pragma unroll
                for (int ntp = 0; ntp < 2; ntp++)
#pragma unroll
                    for (int q = 0; q < 2; q++) {
                        float* a = acc[mt][ntp * 2 + q];
                        const float* sv = s[ntp][q];
                        a[0] += wv0 * fmaxf(sv[0], 0.f);
                        a[1] += wv0 * fmaxf(sv[1], 0.f);
                        a[2] += wv1 * fmaxf(sv[2], 0.f);
                        a[3] += wv1 * fmaxf(sv[3], 0.f);
                    }
            }
        }
    }

    // epilogue
#pragma unroll
    for (int mt = 0; mt < 2; mt++)
#pragma unroll
        for (int rp = 0; rp < 2; rp++) {
            const int row = q0 + m0 + mt * 16 + (lane >> 2) + rp * 8;
            float* op = out + (size_t)(b * T_ + row) * T_ + k0 + n0 + (lane & 3) * 2;
#pragma unroll
            for (int nt = 0; nt < 4; nt++)
                *(float2*)(op + nt * 8) =
                    make_float2(acc[mt][nt][rp * 2], acc[mt][nt][rp * 2 + 1]);
        }
}

// ===========================================================================
extern "C" void kernel_launch(void* const* d_in, const int* in_sizes, int n_in,
                              void* d_out, int out_size)
{
    (void)in_sizes; (void)n_in; (void)out_size;
    const float* x  = (const float*)d_in[0];
    const float* Wq = (const float*)d_in[1];
    const float* Wk = (const float*)d_in[2];
    const float* Ww = (const float*)d_in[3];
    float* out = (float*)d_out;

    static bool attr_done = false;
    if (!attr_done) {
        cudaFuncSetAttribute(proj_mma_kernel,
                             cudaFuncAttributeMaxDynamicSharedMemorySize, 74752);
        cudaFuncSetAttribute(fused_mma_kernel,
                             cudaFuncAttributeMaxDynamicSharedMemorySize, 115712);
        attr_done = true;
    }

    cvt_all_kernel<<<4416, 256>>>(x, Wq, Wk, Ww);
    proj_mma_kernel<<<dim3(9, 64), 256, 74752>>>();
    fused_mma_kernel<<<dim3(T_ / 64, T_ / 128, B_), 256, 115712>>>(out);
}

// round 10
// speedup vs baseline: 3.7068x; 1.0520x over previous
#include <cuda_runtime.h>
#include <cuda_bf16.h>
#include <cstdint>

// Problem constants
#define B_ 2
#define T_ 4096
#define C_ 2048
#define H_ 16
#define D_ 32

// ---------------------------------------------------------------------------
// Ext-bf16 tile format: a 128-row x 32-f32-col operand block is stored as
// 16384 bytes; logical (row r, ext col c in [0,64): c<32 = hi of d=c,
// c>=32 = lo of d=c-32) lives at byte offset sw128(r*128 + c*2).
// Gmem byte order == smem byte order -> plain 16B cp.async copies.
// ---------------------------------------------------------------------------
__device__ __align__(1024) char g_xext [(size_t)64 * 64 * 16384];  // [rowTile][kStep]
__device__ __align__(1024) char g_wqext[(size_t)4  * 64 * 16384];  // [nTile][kStep]
__device__ __align__(1024) char g_kwext[(size_t)64 * 6144];        // [kStep] 48 rows
__device__ __align__(1024) char g_qext [(size_t)64 * 16 * 16384];  // [qTile][head]
__device__ __align__(1024) char g_kext [(size_t)64 * 16384];       // [kTile]
__device__ __align__(1024) float g_w[(size_t)B_ * T_ * H_];        // [8192][16]

// ===========================================================================
// Helpers (base sm_103-safe: ldmatrix + mma.sync + cp.async)
// ===========================================================================
__device__ __forceinline__ uint32_t smem_u32(const void* p) {
    uint32_t a;
    asm("{ .reg .u64 t; cvta.to.shared.u64 t, %1; cvt.u32.u64 %0, t; }"
        : "=r"(a) : "l"(p));
    return a;
}

__device__ __forceinline__ uint32_t sw128(uint32_t o) { return o ^ ((o >> 3) & 0x70); }

__device__ __forceinline__ void ldsm4(uint32_t* r, uint32_t a) {
    asm volatile("ldmatrix.sync.aligned.m8n8.x4.shared.b16 {%0,%1,%2,%3}, [%4];"
                 : "=r"(r[0]), "=r"(r[1]), "=r"(r[2]), "=r"(r[3]) : "r"(a));
}

__device__ __forceinline__ void mma_bf16(float* d, const uint32_t* a, const uint32_t* b) {
    asm volatile(
        "mma.sync.aligned.m16n8k16.row.col.f32.bf16.bf16.f32 "
        "{%0,%1,%2,%3}, {%4,%5,%6,%7}, {%8,%9}, {%0,%1,%2,%3};"
        : "+f"(d[0]), "+f"(d[1]), "+f"(d[2]), "+f"(d[3])
        : "r"(a[0]), "r"(a[1]), "r"(a[2]), "r"(a[3]), "r"(b[0]), "r"(b[1]));
}

__device__ __forceinline__ void cp16(uint32_t s, const void* g) {
    asm volatile("cp.async.cg.shared.global [%0], [%1], 16;" :: "r"(s), "l"(g));
}
#define CP_COMMIT() asm volatile("cp.async.commit_group;" ::: "memory")
#define CP_WAIT(n)  asm volatile("cp.async.wait_group %0;" :: "n"(n) : "memory")

__device__ __forceinline__ uint32_t pack2bf(float x, float y) {
    __nv_bfloat16 bx = __float2bfloat16_rn(x), by = __float2bfloat16_rn(y);
    return ((uint32_t)__bfloat16_as_ushort(by) << 16) | (uint32_t)__bfloat16_as_ushort(bx);
}

__device__ __forceinline__ void split2(float v0, float v1, uint32_t& hi, uint32_t& lo) {
    __nv_bfloat16 h0 = __float2bfloat16_rn(v0), h1 = __float2bfloat16_rn(v1);
    hi = ((uint32_t)__bfloat16_as_ushort(h1) << 16) | (uint32_t)__bfloat16_as_ushort(h0);
    lo = pack2bf(v0 - __bfloat162float(h0), v1 - __bfloat162float(h1));
}

__device__ __forceinline__ void cvt_store4(char* tile, uint32_t base_off, float4 v) {
    uint32_t hi0, lo0, hi1, lo1;
    split2(v.x, v.y, hi0, lo0);
    split2(v.z, v.w, hi1, lo1);
    *(uint2*)(tile + sw128(base_off))      = make_uint2(hi0, hi1);
    *(uint2*)(tile + sw128(base_off + 64)) = make_uint2(lo0, lo1);
}

// Vectorized: 8 consecutive f32 of one row -> one 16B hi store + one 16B lo
// store (STG.128 each). base_off = r*128 + c*2 with c multiple of 8.
__device__ __forceinline__ void cvt_store8(char* tile, uint32_t base_off,
                                           float4 a, float4 b) {
    uint4 hi, lo;
    split2(a.x, a.y, hi.x, lo.x);
    split2(a.z, a.w, hi.y, lo.y);
    split2(b.x, b.y, hi.z, lo.z);
    split2(b.z, b.w, hi.w, lo.w);
    *(uint4*)(tile + sw128(base_off))      = hi;
    *(uint4*)(tile + sw128(base_off + 64)) = lo;
}

// 3-term split product over FOUR independent accumulator chains, issued
// round-robin so same-chain MMAs are 4 issues apart (hides HMMA RAW latency).
// frag 0,1 = hi k-steps; 2,3 = lo k-steps.  s = a_hi*b_hi + a_hi*b_lo + a_lo*b_hi
__device__ __forceinline__ void mma_split3_x4(float* s00, float* s01,
                                              float* s10, float* s11,
                                              const uint32_t af[4][4],
                                              const uint32_t b0[4][4],
                                              const uint32_t b1[4][4]) {
    const int PA[6] = {0, 1, 0, 1, 2, 3};
    const int PB[6] = {0, 1, 2, 3, 0, 1};
#pragma unroll
    for (int p = 0; p < 6; p++) {
        mma_bf16(s00, af[PA[p]], &b0[PB[p]][0]);
        mma_bf16(s01, af[PA[p]], &b0[PB[p]][2]);
        mma_bf16(s10, af[PA[p]], &b1[PB[p]][0]);
        mma_bf16(s11, af[PA[p]], &b1[PB[p]][2]);
    }
}

// ===========================================================================
// Merged conversion pass (vectorized 16B stores).
// Linear grid: [0,4096) X tiles, [4096,4352) Wq tiles, [4352,4416) WkWw.
// Each chunk = 8 consecutive f32 of one tile row.
// ===========================================================================
__global__ void __launch_bounds__(256)
cvt_all_kernel(const float* __restrict__ X, const float* __restrict__ Wq,
               const float* __restrict__ Wk, const float* __restrict__ Ww)
{
    const int bid = blockIdx.x;
    const int tid = threadIdx.x;

    if (bid < 4096) {
        const int rowTile = bid >> 6, kStep = bid & 63;
        const float* srcb = X + (size_t)(rowTile * 128) * C_ + kStep * 32;
        char* dst = g_xext + ((size_t)rowTile * 64 + kStep) * 16384;
#pragma unroll
        for (int j = 0; j < 2; j++) {
            const int idx = tid + j * 256;          // 0..511
            const int r = idx >> 2, c8 = (idx & 3) * 8;
            const float* s = srcb + (size_t)r * C_ + c8;
            cvt_store8(dst, (uint32_t)(r * 128 + c8 * 2),
                       *(const float4*)s, *(const float4*)(s + 4));
        }
    } else if (bid < 4352) {
        const int t = bid - 4096;
        const int nTile = t >> 6, kStep = t & 63;
        const float* srcb = Wq + (size_t)(nTile * 128) * C_ + kStep * 32;
        char* dst = g_wqext + ((size_t)nTile * 64 + kStep) * 16384;
#pragma unroll
        for (int j = 0; j < 2; j++) {
            const int idx = tid + j * 256;
            const int r = idx >> 2, c8 = (idx & 3) * 8;
            const float* s = srcb + (size_t)r * C_ + c8;
            cvt_store8(dst, (uint32_t)(r * 128 + c8 * 2),
                       *(const float4*)s, *(const float4*)(s + 4));
        }
    } else {
        const int kStep = bid - 4352;
        if (tid >= 192) return;                     // 48 rows * 4 chunks
        const int r = tid >> 2, c8 = (tid & 3) * 8;
        const float* s = (r < 32) ? (Wk + (size_t)r * C_ + kStep * 32 + c8)
                                  : (Ww + (size_t)(r - 32) * C_ + kStep * 32 + c8);
        char* dst = g_kwext + (size_t)kStep * 6144;
        cvt_store8(dst, (uint32_t)(r * 128 + c8 * 2),
                   *(const float4*)s, *(const float4*)(s + 4));
    }
}

// ===========================================================================
// Unified projection kernel. grid (9, 64):
//   nT in 0..7 : Q-proj, 64 output cols (nT*64..), writes g_qext
//   nT == 8    : K+W proj (48 cols from g_kwext), writes g_kext + g_w
// CTA: 128(m) x 64(n), 256 threads, 8 warps 4(m) x 2(n), warp tile 32x32.
// k=64 stages (2 sub-tiles), 2-buffer cp.async (48KB/stage), 32 iterations,
// 2 CTAs/SM.
// ===========================================================================
__global__ void __launch_bounds__(256, 2)
proj_mma_kernel()
{
    extern __shared__ char dsm_raw[];
    char* dsm = (char*)(((uintptr_t)dsm_raw + 1023) & ~(uintptr_t)1023);
    // stage buffer: X0(16K) X1(16K) W0(8K) W1(8K) = 48KB; two buffers.

    const int tid  = threadIdx.x;
    const int wid  = tid >> 5;
    const int lane = tid & 31;
    const int nT    = blockIdx.x;           // 0..8
    const int mTile = blockIdx.y;           // 0..63
    const int m0 = (wid & 3) * 32;
    const int n0 = (wid >> 2) * 32;
    const bool iskw = (nT == 8);

    const char* xsrc = g_xext + (size_t)mTile * 64 * 16384;
    const char* wsrc = iskw ? g_kwext
                            : g_wqext + (size_t)(nT >> 1) * 64 * 16384 + (nT & 1) * 8192;
    const uint32_t wstep  = iskw ? 6144u : 16384u;   // bytes per k-step in gmem
    const uint32_t wbytes = iskw ? 6144u : 8192u;    // bytes to copy per k-step

    uint32_t sbase[2];
#pragma unroll
    for (int s = 0; s < 2; s++) sbase[s] = smem_u32(dsm + s * 49152);

    uint32_t aoff[2][4], boff[2][4];
    {
        const int arow = lane & 15, aseg = lane >> 4;
        const int brow = (lane & 7) + ((lane & 16) >> 1);
        const int bseg = (lane >> 3) & 1;
#pragma unroll
        for (int t = 0; t < 2; t++)
#pragma unroll
            for (int ks = 0; ks < 4; ks++) {
                aoff[t][ks] = sw128((uint32_t)((m0 + t * 16 + arow) * 128 +
                                               ks * 32 + aseg * 16));
                boff[t][ks] = 32768u + sw128((uint32_t)((n0 + t * 16 + brow) * 128 +
                                                        ks * 32 + bseg * 16));
            }
    }

    // issue one k=64 stage (2 k-steps) into buffer bb
    auto issue_stage = [&](int stage, int bb) {
        const uint32_t sb = sbase[bb];
#pragma unroll
        for (int t = 0; t < 2; t++) {
            const size_t ks = (size_t)(stage * 2 + t);
#pragma unroll
            for (int j = 0; j < 4; j++) {
                uint32_t off = (uint32_t)(tid + j * 256) * 16;
                cp16(sb + t * 16384u + off, xsrc + ks * 16384 + off);
            }
#pragma unroll
            for (int j = 0; j < 2; j++) {
                uint32_t off = (uint32_t)(tid + j * 256) * 16;
                if (off < wbytes)
                    cp16(sb + 32768u + t * 8192u + off, wsrc + ks * wstep + off);
            }
        }
    };

    // prologue: stage 0 -> buf 0
    issue_stage(0, 0);
    CP_COMMIT();

    float acc[2][4][4];
#pragma unroll
    for (int mt = 0; mt < 2; mt++)
#pragma unroll
        for (int nt = 0; nt < 4; nt++)
#pragma unroll
            for (int c = 0; c < 4; c++) acc[mt][nt][c] = 0.f;

#pragma unroll 1
    for (int it = 0; it < 32; it++) {
        CP_WAIT(0);          // stage it complete (only pending group)
        __syncthreads();     // all warps: data visible + prev compute retired
        if (it + 1 < 32) {
            issue_stage(it + 1, (it + 1) & 1);
            CP_COMMIT();
        }

        const uint32_t cb = sbase[it & 1];
#pragma unroll
        for (int t = 0; t < 2; t++) {
            const uint32_t xb = cb + (uint32_t)t * 16384u;
            const uint32_t wb = (uint32_t)t * 8192u;
            uint32_t bfr[2][4][4];
#pragma unroll
            for (int ntp = 0; ntp < 2; ntp++)
#pragma unroll
                for (int ks = 0; ks < 4; ks++)
                    ldsm4(bfr[ntp][ks], cb + wb + boff[ntp][ks]);

#pragma unroll
            for (int mt = 0; mt < 2; mt++) {
                uint32_t af[4][4];
#pragma unroll
                for (int ks = 0; ks < 4; ks++) ldsm4(af[ks], xb + aoff[mt][ks]);
                mma_split3_x4(acc[mt][0], acc[mt][1], acc[mt][2], acc[mt][3],
                              af, bfr[0], bfr[1]);
            }
        }
    }

    // epilogue
#pragma unroll
    for (int mt = 0; mt < 2; mt++)
#pragma unroll
        for (int rp = 0; rp < 2; rp++) {
            const int r = m0 + mt * 16 + (lane >> 2) + rp * 8;
#pragma unroll
            for (int nt = 0; nt < 4; nt++) {
                const int colL = n0 + nt * 8 + (lane & 3) * 2;
                const float v0 = acc[mt][nt][rp * 2];
                const float v1 = acc[mt][nt][rp * 2 + 1];
                if (!iskw) {
                    const int col = nT * 64 + colL;
                    const int head = col >> 5;
                    const int d = col & 31;
                    uint32_t hi, lo;
                    split2(v0, v1, hi, lo);
                    char* dst = g_qext + ((size_t)mTile * 16 + head) * 16384;
                    *(uint32_t*)(dst + sw128((uint32_t)(r * 128 + d * 2)))      = hi;
                    *(uint32_t*)(dst + sw128((uint32_t)(r * 128 + 64 + d * 2))) = lo;
                } else if (colL < 32) {
                    uint32_t hi, lo;
                    split2(v0, v1, hi, lo);
                    char* dst = g_kext + (size_t)mTile * 16384;
                    *(uint32_t*)(dst + sw128((uint32_t)(r * 128 + colL * 2)))      = hi;
                    *(uint32_t*)(dst + sw128((uint32_t)(r * 128 + 64 + colL * 2))) = lo;
                } else if (colL < 48) {
                    *(float2*)(g_w + (size_t)(mTile * 128 + r) * H_ + (colL - 32)) =
                        make_float2(v0, v1);
                }
            }
        }
}

// ===========================================================================
// Fused scores+importance: out[b,q,k] = sum_h w[b,q,h]*relu(dot(q,k))
// CTA = 128(q) x 64(k), 256 threads, 8 warps 4(m)x2(n), 2 CTAs/SM.
// K 64-row slice (8KB) register-resident; Q streamed 2 HEADS per stage
// (3 x 32KB ring) -> 8 sync points.
// ===========================================================================
__global__ void __launch_bounds__(256, 2)
fused_mma_kernel(float* __restrict__ out)
{
    extern __shared__ char dsm_raw[];
    char* dsm = (char*)(((uintptr_t)dsm_raw + 1023) & ~(uintptr_t)1023);
    char* Ks   = dsm;                    // 8KB (64 rows)
    char* Qb   = dsm + 8192;             // 3 x 32KB (2 heads per stage)
    float* w_s = (float*)(dsm + 106496); // 8KB

    const int tid  = threadIdx.x;
    const int wid  = tid >> 5;
    const int lane = tid & 31;
    const int b  = blockIdx.z;
    const int kT = blockIdx.x;          // 0..63 (64-col k tiles)
    const int q0 = blockIdx.y * 128;
    const int k0 = kT * 64;
    const int m0 = (wid & 3) * 32;
    const int n0 = (wid >> 2) * 32;     // 0 or 32 within the 64-col slice

    const int qTile = b * 32 + blockIdx.y;
    const char* qsrc = g_qext + (size_t)qTile * 16 * 16384;
    const char* ksrc = g_kext + (size_t)(b * 32 + (kT >> 1)) * 16384 + (kT & 1) * 8192;
    const float* wsrc = g_w + (size_t)(b * T_ + q0) * H_;

    const uint32_t ksb = smem_u32(Ks);
    const uint32_t wsb_smem = smem_u32(w_s);
    uint32_t qbase[3];
#pragma unroll
    for (int s = 0; s < 3; s++) qbase[s] = smem_u32(Qb + s * 32768);

    // prologue: G0 = {K, w, headpair 0}, G1 = {headpair 1}
#pragma unroll
    for (int j = 0; j < 2; j++) {
        uint32_t off = (uint32_t)(tid + j * 256) * 16;
        cp16(ksb + off, ksrc + off);
        cp16(wsb_smem + off, (const char*)wsrc + off);
    }
#pragma unroll
    for (int j = 0; j < 8; j++) {
        uint32_t off = (uint32_t)(tid + j * 256) * 16;
        cp16(qbase[0] + off, qsrc + off);
    }
    CP_COMMIT();
#pragma unroll
    for (int j = 0; j < 8; j++) {
        uint32_t off = (uint32_t)(tid + j * 256) * 16;
        cp16(qbase[1] + off, qsrc + 32768 + off);
    }
    CP_COMMIT();

    uint32_t aoff[2][4];
    uint32_t baddr[2][4];
    {
        const int arow = lane & 15, aseg = lane >> 4;
        const int brow = (lane & 7) + ((lane & 16) >> 1);
        const int bseg = (lane >> 3) & 1;
#pragma unroll
        for (int t = 0; t < 2; t++)
#pragma unroll
            for (int ks = 0; ks < 4; ks++) {
                aoff[t][ks] = sw128((uint32_t)((m0 + t * 16 + arow) * 128 +
                                               ks * 32 + aseg * 16));
                baddr[t][ks] = ksb + sw128((uint32_t)((n0 + t * 16 + brow) * 128 +
                                                      ks * 32 + bseg * 16));
            }
    }

    float acc[2][4][4];
#pragma unroll
    for (int mt = 0; mt < 2; mt++)
#pragma unroll
        for (int nt = 0; nt < 4; nt++)
#pragma unroll
            for (int c = 0; c < 4; c++) acc[mt][nt][c] = 0.f;

    CP_WAIT(1);       // G0 done: K, w, headpair 0
    __syncthreads();

    // K fragments register-resident (this warp's 32 n-cols of the 64-row slice)
    uint32_t bfr[2][4][4];
#pragma unroll
    for (int ntp = 0; ntp < 2; ntp++)
#pragma unroll
        for (int ks = 0; ks < 4; ks++) ldsm4(bfr[ntp][ks], baddr[ntp][ks]);

    const int wrow0 = m0 + (lane >> 2);

#pragma unroll 1
    for (int p = 0; p < H_ / 2; p++) {      // head pairs
        if (p > 0) {
            if (p == H_ / 2 - 1) CP_WAIT(0); else CP_WAIT(1);
            __syncthreads();
        }
        if (p + 2 < H_ / 2) {
            uint32_t qb = qbase[(p + 2) % 3];
            const char* src = qsrc + (size_t)(p + 2) * 32768;
#pragma unroll
            for (int j = 0; j < 8; j++) {
                uint32_t off = (uint32_t)(tid + j * 256) * 16;
                cp16(qb + off, src + off);
            }
        }
        CP_COMMIT();

        const uint32_t qb = qbase[p % 3];
#pragma unroll
        for (int hh = 0; hh < 2; hh++) {
            const int h = p * 2 + hh;
            const uint32_t qbh = qb + (uint32_t)hh * 16384u;
#pragma unroll
            for (int mt = 0; mt < 2; mt++) {
                uint32_t af[4][4];
#pragma unroll
                for (int ks = 0; ks < 4; ks++) ldsm4(af[ks], qbh + aoff[mt][ks]);

                const float wv0 = w_s[(wrow0 + mt * 16) * H_ + h];
                const float wv1 = w_s[(wrow0 + mt * 16 + 8) * H_ + h];

                float s[2][2][4];
#pragma unroll
                for (int ntp = 0; ntp < 2; ntp++)
#pragma unroll
                    for (int q = 0; q < 2; q++)
#pragma unroll
                        for (int c = 0; c < 4; c++) s[ntp][q][c] = 0.f;

                mma_split3_x4(s[0][0], s[0][1], s[1][0], s[1][1], af, bfr[0], bfr[1]);

#pragma unroll
                for (int ntp = 0; ntp < 2; ntp++)
#pragma unroll
                    for (int q = 0; q < 2; q++) {
                        float* a = acc[mt][ntp * 2 + q];
                        const float* sv = s[ntp][q];
                        a[0] += wv0 * fmaxf(sv[0], 0.f);
                        a[1] += wv0 * fmaxf(sv[1], 0.f);
                        a[2] += wv1 * fmaxf(sv[2], 0.f);
                        a[3] += wv1 * fmaxf(sv[3], 0.f);
                    }
            }
        }
    }

    // epilogue
#pragma unroll
    for (int mt = 0; mt < 2; mt++)
#pragma unroll
        for (int rp = 0; rp < 2; rp++) {
            const int row = q0 + m0 + mt * 16 + (lane >> 2) + rp * 8;
            float* op = out + (size_t)(b * T_ + row) * T_ + k0 + n0 + (lane & 3) * 2;
#pragma unroll
            for (int nt = 0; nt < 4; nt++)
                *(float2*)(op + nt * 8) =
                    make_float2(acc[mt][nt][rp * 2], acc[mt][nt][rp * 2 + 1]);
        }
}

// ===========================================================================
extern "C" void kernel_launch(void* const* d_in, const int* in_sizes, int n_in,
                              void* d_out, int out_size)
{
    (void)in_sizes; (void)n_in; (void)out_size;
    const float* x  = (const float*)d_in[0];
    const float* Wq = (const float*)d_in[1];
    const float* Wk = (const float*)d_in[2];
    const float* Ww = (const float*)d_in[3];
    float* out = (float*)d_out;

    static bool attr_done = false;
    if (!attr_done) {
        cudaFuncSetAttribute(proj_mma_kernel,
                             cudaFuncAttributeMaxDynamicSharedMemorySize, 99328);
        cudaFuncSetAttribute(fused_mma_kernel,
                             cudaFuncAttributeMaxDynamicSharedMemorySize, 115712);
        attr_done = true;
    }

    cvt_all_kernel<<<4416, 256>>>(x, Wq, Wk, Ww);
    proj_mma_kernel<<<dim3(9, 64), 256, 99328>>>();
    fused_mma_kernel<<<dim3(T_ / 64, T_ / 128, B_), 256, 115712>>>(out);
}

// round 11
// speedup vs baseline: 4.6247x; 1.2476x over previous
#include <cuda_runtime.h>
#include <cuda_fp16.h>
#include <cstdint>

// Problem constants
#define B_ 2
#define T_ 4096
#define C_ 2048
#define H_ 16
#define D_ 32

// ---------------------------------------------------------------------------
// Ext-fp16 tile format: a 128-row x 32-f32-col operand block is stored as
// 16384 bytes; logical (row r, ext col c in [0,64): c<32 = hi of d=c,
// c>=32 = lo of d=c-32) lives at byte offset sw128(r*128 + c*2).
// Gmem byte order == smem byte order -> plain 16B cp.async copies.
// Product scheme (4 MMAs): (a_hi + a_lo) * b_hi  ==  a * b_hi,
// dropping a*b_lo (~2^-12 relative).  A-side uses hi+lo, B-side hi only.
// ---------------------------------------------------------------------------
__device__ __align__(1024) char g_xext [(size_t)64 * 64 * 16384];  // [rowTile][kStep]
__device__ __align__(1024) char g_wqext[(size_t)4  * 64 * 16384];  // [nTile][kStep]
__device__ __align__(1024) char g_kwext[(size_t)64 * 6144];        // [kStep] 48 rows
__device__ __align__(1024) char g_qext [(size_t)64 * 16 * 16384];  // [qTile][head]
__device__ __align__(1024) char g_kext [(size_t)64 * 16384];       // [kTile]
__device__ __align__(1024) float g_w[(size_t)B_ * T_ * H_];        // [8192][16]

// ===========================================================================
// Helpers (base sm_103-safe: ldmatrix + mma.sync + cp.async)
// ===========================================================================
__device__ __forceinline__ uint32_t smem_u32(const void* p) {
    uint32_t a;
    asm("{ .reg .u64 t; cvta.to.shared.u64 t, %1; cvt.u32.u64 %0, t; }"
        : "=r"(a) : "l"(p));
    return a;
}

__device__ __forceinline__ uint32_t sw128(uint32_t o) { return o ^ ((o >> 3) & 0x70); }

__device__ __forceinline__ void ldsm4(uint32_t* r, uint32_t a) {
    asm volatile("ldmatrix.sync.aligned.m8n8.x4.shared.b16 {%0,%1,%2,%3}, [%4];"
                 : "=r"(r[0]), "=r"(r[1]), "=r"(r[2]), "=r"(r[3]) : "r"(a));
}

__device__ __forceinline__ void mma_f16(float* d, const uint32_t* a, const uint32_t* b) {
    asm volatile(
        "mma.sync.aligned.m16n8k16.row.col.f32.f16.f16.f32 "
        "{%0,%1,%2,%3}, {%4,%5,%6,%7}, {%8,%9}, {%0,%1,%2,%3};"
        : "+f"(d[0]), "+f"(d[1]), "+f"(d[2]), "+f"(d[3])
        : "r"(a[0]), "r"(a[1]), "r"(a[2]), "r"(a[3]), "r"(b[0]), "r"(b[1]));
}

__device__ __forceinline__ void cp16(uint32_t s, const void* g) {
    asm volatile("cp.async.cg.shared.global [%0], [%1], 16;" :: "r"(s), "l"(g));
}
#define CP_COMMIT() asm volatile("cp.async.commit_group;" ::: "memory")
#define CP_WAIT(n)  asm volatile("cp.async.wait_group %0;" :: "n"(n) : "memory")

// split two f32 into packed fp16 hi-pair and fp16 lo-pair (lo = residual)
__device__ __forceinline__ void split2(float v0, float v1, uint32_t& hi, uint32_t& lo) {
    __half h0 = __float2half_rn(v0), h1 = __float2half_rn(v1);
    hi = ((uint32_t)__half_as_ushort(h1) << 16) | (uint32_t)__half_as_ushort(h0);
    __half g0 = __float2half_rn(v0 - __half2float(h0));
    __half g1 = __float2half_rn(v1 - __half2float(h1));
    lo = ((uint32_t)__half_as_ushort(g1) << 16) | (uint32_t)__half_as_ushort(g0);
}

// Vectorized: 8 consecutive f32 of one row -> one 16B hi store + one 16B lo
// store (STG.128 each). base_off = r*128 + c*2 with c multiple of 8.
__device__ __forceinline__ void cvt_store8(char* tile, uint32_t base_off,
                                           float4 a, float4 b) {
    uint4 hi, lo;
    split2(a.x, a.y, hi.x, lo.x);
    split2(a.z, a.w, hi.y, lo.y);
    split2(b.x, b.y, hi.z, lo.z);
    split2(b.z, b.w, hi.w, lo.w);
    *(uint4*)(tile + sw128(base_off))      = hi;
    *(uint4*)(tile + sw128(base_off + 64)) = lo;
}

// 2-term fp16 product over FOUR independent accumulator chains:
//   s = (a_hi + a_lo) * b_hi = a * b_hi      (drops a*b_lo ~ 2^-12)
// A frags: 0,1 = hi k-steps, 2,3 = lo k-steps. B frags: hi only (0,1).
__device__ __forceinline__ void mma_split2_x4(float* s00, float* s01,
                                              float* s10, float* s11,
                                              const uint32_t af[4][4],
                                              const uint32_t b0[2][4],
                                              const uint32_t b1[2][4]) {
    const int PA[4] = {0, 1, 2, 3};
    const int PB[4] = {0, 1, 0, 1};
#pragma unroll
    for (int p = 0; p < 4; p++) {
        mma_f16(s00, af[PA[p]], &b0[PB[p]][0]);
        mma_f16(s01, af[PA[p]], &b0[PB[p]][2]);
        mma_f16(s10, af[PA[p]], &b1[PB[p]][0]);
        mma_f16(s11, af[PA[p]], &b1[PB[p]][2]);
    }
}

// ===========================================================================
// Merged conversion pass (vectorized 16B stores).
// Linear grid: [0,4096) X tiles, [4096,4352) Wq tiles, [4352,4416) WkWw.
// ===========================================================================
__global__ void __launch_bounds__(256)
cvt_all_kernel(const float* __restrict__ X, const float* __restrict__ Wq,
               const float* __restrict__ Wk, const float* __restrict__ Ww)
{
    const int bid = blockIdx.x;
    const int tid = threadIdx.x;

    if (bid < 4096) {
        const int rowTile = bid >> 6, kStep = bid & 63;
        const float* srcb = X + (size_t)(rowTile * 128) * C_ + kStep * 32;
        char* dst = g_xext + ((size_t)rowTile * 64 + kStep) * 16384;
#pragma unroll
        for (int j = 0; j < 2; j++) {
            const int idx = tid + j * 256;          // 0..511
            const int r = idx >> 2, c8 = (idx & 3) * 8;
            const float* s = srcb + (size_t)r * C_ + c8;
            cvt_store8(dst, (uint32_t)(r * 128 + c8 * 2),
                       *(const float4*)s, *(const float4*)(s + 4));
        }
    } else if (bid < 4352) {
        const int t = bid - 4096;
        const int nTile = t >> 6, kStep = t & 63;
        const float* srcb = Wq + (size_t)(nTile * 128) * C_ + kStep * 32;
        char* dst = g_wqext + ((size_t)nTile * 64 + kStep) * 16384;
#pragma unroll
        for (int j = 0; j < 2; j++) {
            const int idx = tid + j * 256;
            const int r = idx >> 2, c8 = (idx & 3) * 8;
            const float* s = srcb + (size_t)r * C_ + c8;
            cvt_store8(dst, (uint32_t)(r * 128 + c8 * 2),
                       *(const float4*)s, *(const float4*)(s + 4));
        }
    } else {
        const int kStep = bid - 4352;
        if (tid >= 192) return;                     // 48 rows * 4 chunks
        const int r = tid >> 2, c8 = (tid & 3) * 8;
        const float* s = (r < 32) ? (Wk + (size_t)r * C_ + kStep * 32 + c8)
                                  : (Ww + (size_t)(r - 32) * C_ + kStep * 32 + c8);
        char* dst = g_kwext + (size_t)kStep * 6144;
        cvt_store8(dst, (uint32_t)(r * 128 + c8 * 2),
                   *(const float4*)s, *(const float4*)(s + 4));
    }
}

// ===========================================================================
// Unified projection kernel. grid (9, 64):
//   nT in 0..7 : Q-proj, 64 output cols (nT*64..), writes g_qext
//   nT == 8    : K+W proj (48 cols from g_kwext), writes g_kext + g_w
// CTA: 128(m) x 64(n), 256 threads, 8 warps 4(m) x 2(n), warp tile 32x32.
// k=64 stages (2 sub-tiles), 2-buffer cp.async (48KB/stage), 32 iterations,
// 2 CTAs/SM.  A = X (hi+lo frags), B = W (hi frags only).
// ===========================================================================
__global__ void __launch_bounds__(256, 2)
proj_mma_kernel()
{
    extern __shared__ char dsm_raw[];
    char* dsm = (char*)(((uintptr_t)dsm_raw + 1023) & ~(uintptr_t)1023);
    // stage buffer: X0(16K) X1(16K) W0(8K) W1(8K) = 48KB; two buffers.

    const int tid  = threadIdx.x;
    const int wid  = tid >> 5;
    const int lane = tid & 31;
    const int nT    = blockIdx.x;           // 0..8
    const int mTile = blockIdx.y;           // 0..63
    const int m0 = (wid & 3) * 32;
    const int n0 = (wid >> 2) * 32;
    const bool iskw = (nT == 8);

    const char* xsrc = g_xext + (size_t)mTile * 64 * 16384;
    const char* wsrc = iskw ? g_kwext
                            : g_wqext + (size_t)(nT >> 1) * 64 * 16384 + (nT & 1) * 8192;
    const uint32_t wstep  = iskw ? 6144u : 16384u;   // bytes per k-step in gmem
    const uint32_t wbytes = iskw ? 6144u : 8192u;    // bytes to copy per k-step

    uint32_t sbase[2];
#pragma unroll
    for (int s = 0; s < 2; s++) sbase[s] = smem_u32(dsm + s * 49152);

    uint32_t aoff[2][4], boff[2][2];
    {
        const int arow = lane & 15, aseg = lane >> 4;
        const int brow = (lane & 7) + ((lane & 16) >> 1);
        const int bseg = (lane >> 3) & 1;
#pragma unroll
        for (int t = 0; t < 2; t++) {
#pragma unroll
            for (int ks = 0; ks < 4; ks++)
                aoff[t][ks] = sw128((uint32_t)((m0 + t * 16 + arow) * 128 +
                                               ks * 32 + aseg * 16));
#pragma unroll
            for (int ks = 0; ks < 2; ks++)       // B: hi frags only
                boff[t][ks] = 32768u + sw128((uint32_t)((n0 + t * 16 + brow) * 128 +
                                                        ks * 32 + bseg * 16));
        }
    }

    // issue one k=64 stage (2 k-steps) into buffer bb
    auto issue_stage = [&](int stage, int bb) {
        const uint32_t sb = sbase[bb];
#pragma unroll
        for (int t = 0; t < 2; t++) {
            const size_t ks = (size_t)(stage * 2 + t);
#pragma unroll
            for (int j = 0; j < 4; j++) {
                uint32_t off = (uint32_t)(tid + j * 256) * 16;
                cp16(sb + t * 16384u + off, xsrc + ks * 16384 + off);
            }
#pragma unroll
            for (int j = 0; j < 2; j++) {
                uint32_t off = (uint32_t)(tid + j * 256) * 16;
                if (off < wbytes)
                    cp16(sb + 32768u + t * 8192u + off, wsrc + ks * wstep + off);
            }
        }
    };

    // prologue: stage 0 -> buf 0
    issue_stage(0, 0);
    CP_COMMIT();

    float acc[2][4][4];
#pragma unroll
    for (int mt = 0; mt < 2; mt++)
#pragma unroll
        for (int nt = 0; nt < 4; nt++)
#pragma unroll
            for (int c = 0; c < 4; c++) acc[mt][nt][c] = 0.f;

#pragma unroll 1
    for (int it = 0; it < 32; it++) {
        CP_WAIT(0);          // stage it complete (only pending group)
        __syncthreads();     // all warps: data visible + prev compute retired
        if (it + 1 < 32) {
            issue_stage(it + 1, (it + 1) & 1);
            CP_COMMIT();
        }

        const uint32_t cb = sbase[it & 1];
#pragma unroll
        for (int t = 0; t < 2; t++) {
            const uint32_t xb = cb + (uint32_t)t * 16384u;
            const uint32_t wb = (uint32_t)t * 8192u;
            uint32_t bfr[2][2][4];
#pragma unroll
            for (int ntp = 0; ntp < 2; ntp++)
#pragma unroll
                for (int ks = 0; ks < 2; ks++)
                    ldsm4(bfr[ntp][ks], cb + wb + boff[ntp][ks]);

#pragma unroll
            for (int mt = 0; mt < 2; mt++) {
                uint32_t af[4][4];
#pragma unroll
                for (int ks = 0; ks < 4; ks++) ldsm4(af[ks], xb + aoff[mt][ks]);
                mma_split2_x4(acc[mt][0], acc[mt][1], acc[mt][2], acc[mt][3],
                              af, bfr[0], bfr[1]);
            }
        }
    }

    // epilogue
#pragma unroll
    for (int mt = 0; mt < 2; mt++)
#pragma unroll
        for (int rp = 0; rp < 2; rp++) {
            const int r = m0 + mt * 16 + (lane >> 2) + rp * 8;
#pragma unroll
            for (int nt = 0; nt < 4; nt++) {
                const int colL = n0 + nt * 8 + (lane & 3) * 2;
                const float v0 = acc[mt][nt][rp * 2];
                const float v1 = acc[mt][nt][rp * 2 + 1];
                if (!iskw) {
                    const int col = nT * 64 + colL;
                    const int head = col >> 5;
                    const int d = col & 31;
                    uint32_t hi, lo;
                    split2(v0, v1, hi, lo);
                    char* dst = g_qext + ((size_t)mTile * 16 + head) * 16384;
                    *(uint32_t*)(dst + sw128((uint32_t)(r * 128 + d * 2)))      = hi;
                    *(uint32_t*)(dst + sw128((uint32_t)(r * 128 + 64 + d * 2))) = lo;
                } else if (colL < 32) {
                    uint32_t hi, lo;
                    split2(v0, v1, hi, lo);
                    char* dst = g_kext + (size_t)mTile * 16384;
                    *(uint32_t*)(dst + sw128((uint32_t)(r * 128 + colL * 2)))      = hi;
                    *(uint32_t*)(dst + sw128((uint32_t)(r * 128 + 64 + colL * 2))) = lo;
                } else if (colL < 48) {
                    *(float2*)(g_w + (size_t)(mTile * 128 + r) * H_ + (colL - 32)) =
                        make_float2(v0, v1);
                }
            }
        }
}

// ===========================================================================
// Fused scores+importance: out[b,q,k] = sum_h w[b,q,h]*relu(dot(q,k))
// CTA = 128(q) x 64(k), 256 threads, 8 warps 4(m)x2(n), 2 CTAs/SM.
// A = Q (hi+lo), B = K (hi frags only, register-resident).
// Q streamed 2 HEADS per stage (3 x 32KB ring) -> 8 sync points.
// ===========================================================================
__global__ void __launch_bounds__(256, 2)
fused_mma_kernel(float* __restrict__ out)
{
    extern __shared__ char dsm_raw[];
    char* dsm = (char*)(((uintptr_t)dsm_raw + 1023) & ~(uintptr_t)1023);
    char* Ks   = dsm;                    // 8KB (64 rows)
    char* Qb   = dsm + 8192;             // 3 x 32KB (2 heads per stage)
    float* w_s = (float*)(dsm + 106496); // 8KB

    const int tid  = threadIdx.x;
    const int wid  = tid >> 5;
    const int lane = tid & 31;
    const int b  = blockIdx.z;
    const int kT = blockIdx.x;          // 0..63 (64-col k tiles)
    const int q0 = blockIdx.y * 128;
    const int k0 = kT * 64;
    const int m0 = (wid & 3) * 32;
    const int n0 = (wid >> 2) * 32;     // 0 or 32 within the 64-col slice

    const int qTile = b * 32 + blockIdx.y;
    const char* qsrc = g_qext + (size_t)qTile * 16 * 16384;
    const char* ksrc = g_kext + (size_t)(b * 32 + (kT >> 1)) * 16384 + (kT & 1) * 8192;
    const float* wsrc = g_w + (size_t)(b * T_ + q0) * H_;

    const uint32_t ksb = smem_u32(Ks);
    const uint32_t wsb_smem = smem_u32(w_s);
    uint32_t qbase[3];
#pragma unroll
    for (int s = 0; s < 3; s++) qbase[s] = smem_u32(Qb + s * 32768);

    // prologue: G0 = {K, w, headpair 0}, G1 = {headpair 1}
#pragma unroll
    for (int j = 0; j < 2; j++) {
        uint32_t off = (uint32_t)(tid + j * 256) * 16;
        cp16(ksb + off, ksrc + off);
        cp16(wsb_smem + off, (const char*)wsrc + off);
    }
#pragma unroll
    for (int j = 0; j < 8; j++) {
        uint32_t off = (uint32_t)(tid + j * 256) * 16;
        cp16(qbase[0] + off, qsrc + off);
    }
    CP_COMMIT();
#pragma unroll
    for (int j = 0; j < 8; j++) {
        uint32_t off = (uint32_t)(tid + j * 256) * 16;
        cp16(qbase[1] + off, qsrc + 32768 + off);
    }
    CP_COMMIT();

    uint32_t aoff[2][4];
    uint32_t baddr[2][2];
    {
        const int arow = lane & 15, aseg = lane >> 4;
        const int brow = (lane & 7) + ((lane & 16) >> 1);
        const int bseg = (lane >> 3) & 1;
#pragma unroll
        for (int t = 0; t < 2; t++) {
#pragma unroll
            for (int ks = 0; ks < 4; ks++)
                aoff[t][ks] = sw128((uint32_t)((m0 + t * 16 + arow) * 128 +
                                               ks * 32 + aseg * 16));
#pragma unroll
            for (int ks = 0; ks < 2; ks++)       // K: hi frags only
                baddr[t][ks] = ksb + sw128((uint32_t)((n0 + t * 16 + brow) * 128 +
                                                      ks * 32 + bseg * 16));
        }
    }

    float acc[2][4][4];
#pragma unroll
    for (int mt = 0; mt < 2; mt++)
#pragma unroll
        for (int nt = 0; nt < 4; nt++)
#pragma unroll
            for (int c = 0; c < 4; c++) acc[mt][nt][c] = 0.f;

    CP_WAIT(1);       // G0 done: K, w, headpair 0
    __syncthreads();

    // K hi fragments register-resident (this warp's 32 n-cols)
    uint32_t bfr[2][2][4];
#pragma unroll
    for (int ntp = 0; ntp < 2; ntp++)
#pragma unroll
        for (int ks = 0; ks < 2; ks++) ldsm4(bfr[ntp][ks], baddr[ntp][ks]);

    const int wrow0 = m0 + (lane >> 2);

#pragma unroll 1
    for (int p = 0; p < H_ / 2; p++) {      // head pairs
        if (p > 0) {
            if (p == H_ / 2 - 1) CP_WAIT(0); else CP_WAIT(1);
            __syncthreads();
        }
        if (p + 2 < H_ / 2) {
            uint32_t qb = qbase[(p + 2) % 3];
            const char* src = qsrc + (size_t)(p + 2) * 32768;
#pragma unroll
            for (int j = 0; j < 8; j++) {
                uint32_t off = (uint32_t)(tid + j * 256) * 16;
                cp16(qb + off, src + off);
            }
        }
        CP_COMMIT();

        const uint32_t qb = qbase[p % 3];
#pragma unroll
        for (int hh = 0; hh < 2; hh++) {
            const int h = p * 2 + hh;
            const uint32_t qbh = qb + (uint32_t)hh * 16384u;
#pragma unroll
            for (int mt = 0; mt < 2; mt++) {
                uint32_t af[4][4];
#pragma unroll
                for (int ks = 0; ks < 4; ks++) ldsm4(af[ks], qbh + aoff[mt][ks]);

                const float wv0 = w_s[(wrow0 + mt * 16) * H_ + h];
                const float wv1 = w_s[(wrow0 + mt * 16 + 8) * H_ + h];

                float s[2][2][4];
#pragma unroll
                for (int ntp = 0; ntp < 2; ntp++)
#pragma unroll
                    for (int q = 0; q < 2; q++)
#pragma unroll
                        for (int c = 0; c < 4; c++) s[ntp][q][c] = 0.f;

                mma_split2_x4(s[0][0], s[0][1], s[1][0], s[1][1], af, bfr[0], bfr[1]);

#pragma unroll
                for (int ntp = 0; ntp < 2; ntp++)
#pragma unroll
                    for (int q = 0; q < 2; q++) {
                        float* a = acc[mt][ntp * 2 + q];
                        const float* sv = s[ntp][q];
                        a[0] += wv0 * fmaxf(sv[0], 0.f);
                        a[1] += wv0 * fmaxf(sv[1], 0.f);
                        a[2] += wv1 * fmaxf(sv[2], 0.f);
                        a[3] += wv1 * fmaxf(sv[3], 0.f);
                    }
            }
        }
    }

    // epilogue
#pragma unroll
    for (int mt = 0; mt < 2; mt++)
#pragma unroll
        for (int rp = 0; rp < 2; rp++) {
            const int row = q0 + m0 + mt * 16 + (lane >> 2) + rp * 8;
            float* op = out + (size_t)(b * T_ + row) * T_ + k0 + n0 + (lane & 3) * 2;
#pragma unroll
            for (int nt = 0; nt < 4; nt++)
                *(float2*)(op + nt * 8) =
                    make_float2(acc[mt][nt][rp * 2], acc[mt][nt][rp * 2 + 1]);
        }
}

// ===========================================================================
extern "C" void kernel_launch(void* const* d_in, const int* in_sizes, int n_in,
                              void* d_out, int out_size)
{
    (void)in_sizes; (void)n_in; (void)out_size;
    const float* x  = (const float*)d_in[0];
    const float* Wq = (const float*)d_in[1];
    const float* Wk = (const float*)d_in[2];
    const float* Ww = (const float*)d_in[3];
    float* out = (float*)d_out;

    static bool attr_done = false;
    if (!attr_done) {
        cudaFuncSetAttribute(proj_mma_kernel,
                             cudaFuncAttributeMaxDynamicSharedMemorySize, 99328);
        cudaFuncSetAttribute(fused_mma_kernel,
                             cudaFuncAttributeMaxDynamicSharedMemorySize, 115712);
        attr_done = true;
    }

    cvt_all_kernel<<<4416, 256>>>(x, Wq, Wk, Ww);
    proj_mma_kernel<<<dim3(9, 64), 256, 99328>>>();
    fused_mma_kernel<<<dim3(T_ / 64, T_ / 128, B_), 256, 115712>>>(out);
}

// round 12
// speedup vs baseline: 4.7963x; 1.0371x over previous
#include <cuda_runtime.h>
#include <cuda_fp16.h>
#include <cstdint>

// Problem constants
#define B_ 2
#define T_ 4096
#define C_ 2048
#define H_ 16
#define D_ 32

// ---------------------------------------------------------------------------
// Ext-fp16 tile formats (sw128-swizzled, 128B physical rows):
//  FULL tile (16KB/128rows): row r, ext col c in [0,64): c<32 = hi of d=c,
//    c>=32 = lo of d=c-32, at byte sw128(r*128 + c*2).  (W, K tiles)
//  HI-ONLY tile: same addressing, lo half never written/read (holes).
//    Under sw128 the hi chunks {0,16,32,48}^rot of each row form one aligned
//    64B half -> hi-only copies stay sector-coalesced.   (X, Q tiles)
// Product scheme (4 MMAs): a_hi * (b_hi + b_lo) == a_hi * b,
// dropping a_lo*b (~2^-12 relative).  A-side hi-only, B-side split.
// ---------------------------------------------------------------------------
__device__ __align__(1024) char g_xext [(size_t)64 * 64 * 16384];  // [rowTile][kStep] hi-only
__device__ __align__(1024) char g_wqext[(size_t)4  * 64 * 16384];  // [nTile][kStep] full
__device__ __align__(1024) char g_kwext[(size_t)64 * 6144];        // [kStep] 48 rows, full
__device__ __align__(1024) char g_qext [(size_t)64 * 16 * 16384];  // [qTile][head] hi-only
__device__ __align__(1024) char g_kext [(size_t)64 * 16384];       // [kTile] full
__device__ __align__(1024) float g_w[(size_t)B_ * T_ * H_];        // [8192][16]

// ===========================================================================
// Helpers (base sm_103-safe: ldmatrix + mma.sync + cp.async)
// ===========================================================================
__device__ __forceinline__ uint32_t smem_u32(const void* p) {
    uint32_t a;
    asm("{ .reg .u64 t; cvta.to.shared.u64 t, %1; cvt.u32.u64 %0, t; }"
        : "=r"(a) : "l"(p));
    return a;
}

__device__ __forceinline__ uint32_t sw128(uint32_t o) { return o ^ ((o >> 3) & 0x70); }

__device__ __forceinline__ void ldsm4(uint32_t* r, uint32_t a) {
    asm volatile("ldmatrix.sync.aligned.m8n8.x4.shared.b16 {%0,%1,%2,%3}, [%4];"
                 : "=r"(r[0]), "=r"(r[1]), "=r"(r[2]), "=r"(r[3]) : "r"(a));
}

__device__ __forceinline__ void mma_f16(float* d, const uint32_t* a, const uint32_t* b) {
    asm volatile(
        "mma.sync.aligned.m16n8k16.row.col.f32.f16.f16.f32 "
        "{%0,%1,%2,%3}, {%4,%5,%6,%7}, {%8,%9}, {%0,%1,%2,%3};"
        : "+f"(d[0]), "+f"(d[1]), "+f"(d[2]), "+f"(d[3])
        : "r"(a[0]), "r"(a[1]), "r"(a[2]), "r"(a[3]), "r"(b[0]), "r"(b[1]));
}

__device__ __forceinline__ void cp16(uint32_t s, const void* g) {
    asm volatile("cp.async.cg.shared.global [%0], [%1], 16;" :: "r"(s), "l"(g));
}
#define CP_COMMIT() asm volatile("cp.async.commit_group;" ::: "memory")
#define CP_WAIT(n)  asm volatile("cp.async.wait_group %0;" :: "n"(n) : "memory")

__device__ __forceinline__ uint32_t pack2h(float x, float y) {
    __half h0 = __float2half_rn(x), h1 = __float2half_rn(y);
    return ((uint32_t)__half_as_ushort(h1) << 16) | (uint32_t)__half_as_ushort(h0);
}

// split two f32 into packed fp16 hi-pair and fp16 lo-pair (lo = residual)
__device__ __forceinline__ void split2(float v0, float v1, uint32_t& hi, uint32_t& lo) {
    __half h0 = __float2half_rn(v0), h1 = __float2half_rn(v1);
    hi = ((uint32_t)__half_as_ushort(h1) << 16) | (uint32_t)__half_as_ushort(h0);
    __half g0 = __float2half_rn(v0 - __half2float(h0));
    __half g1 = __float2half_rn(v1 - __half2float(h1));
    lo = ((uint32_t)__half_as_ushort(g1) << 16) | (uint32_t)__half_as_ushort(g0);
}

// 8 consecutive f32 -> full tile: 16B hi + 16B lo stores
__device__ __forceinline__ void cvt_store8(char* tile, uint32_t base_off,
                                           float4 a, float4 b) {
    uint4 hi, lo;
    split2(a.x, a.y, hi.x, lo.x);
    split2(a.z, a.w, hi.y, lo.y);
    split2(b.x, b.y, hi.z, lo.z);
    split2(b.z, b.w, hi.w, lo.w);
    *(uint4*)(tile + sw128(base_off))      = hi;
    *(uint4*)(tile + sw128(base_off + 64)) = lo;
}

// 8 consecutive f32 -> hi-only tile: single 16B store
__device__ __forceinline__ void cvt_store8_hi(char* tile, uint32_t base_off,
                                              float4 a, float4 b) {
    uint4 hi;
    hi.x = pack2h(a.x, a.y);
    hi.y = pack2h(a.z, a.w);
    hi.z = pack2h(b.x, b.y);
    hi.w = pack2h(b.z, b.w);
    *(uint4*)(tile + sw128(base_off)) = hi;
}

// 2-term fp16 product over FOUR independent accumulator chains:
//   s = a_hi * (b_hi + b_lo) = a_hi * b     (drops a_lo*b ~ 2^-12)
// A frags: hi k-steps 0,1 only. B frags: 0,1 = hi, 2,3 = lo.
__device__ __forceinline__ void mma_split2b_x4(float* s00, float* s01,
                                               float* s10, float* s11,
                                               const uint32_t af[2][4],
                                               const uint32_t b0[4][4],
                                               const uint32_t b1[4][4]) {
    const int PA[4] = {0, 1, 0, 1};
    const int PB[4] = {0, 1, 2, 3};
#pragma unroll
    for (int p = 0; p < 4; p++) {
        mma_f16(s00, af[PA[p]], &b0[PB[p]][0]);
        mma_f16(s01, af[PA[p]], &b0[PB[p]][2]);
        mma_f16(s10, af[PA[p]], &b1[PB[p]][0]);
        mma_f16(s11, af[PA[p]], &b1[PB[p]][2]);
    }
}

// ===========================================================================
// Merged conversion pass.
// Linear grid: [0,4096) X tiles (hi-only), [4096,4352) Wq (full),
// [4352,4416) WkWw (full).
// ===========================================================================
__global__ void __launch_bounds__(256)
cvt_all_kernel(const float* __restrict__ X, const float* __restrict__ Wq,
               const float* __restrict__ Wk, const float* __restrict__ Ww)
{
    const int bid = blockIdx.x;
    const int tid = threadIdx.x;

    if (bid < 4096) {
        // X: hi-only, 512 chunks (128 rows x 4)
        const int rowTile = bid >> 6, kStep = bid & 63;
        const float* srcb = X + (size_t)(rowTile * 128) * C_ + kStep * 32;
        char* dst = g_xext + ((size_t)rowTile * 64 + kStep) * 16384;
#pragma unroll
        for (int j = 0; j < 2; j++) {
            const int idx = tid + j * 256;          // 0..511
            const int r = idx >> 2, c8 = (idx & 3) * 8;
            const float* s = srcb + (size_t)r * C_ + c8;
            cvt_store8_hi(dst, (uint32_t)(r * 128 + c8 * 2),
                          *(const float4*)s, *(const float4*)(s + 4));
        }
    } else if (bid < 4352) {
        const int t = bid - 4096;
        const int nTile = t >> 6, kStep = t & 63;
        const float* srcb = Wq + (size_t)(nTile * 128) * C_ + kStep * 32;
        char* dst = g_wqext + ((size_t)nTile * 64 + kStep) * 16384;
#pragma unroll
        for (int j = 0; j < 2; j++) {
            const int idx = tid + j * 256;
            const int r = idx >> 2, c8 = (idx & 3) * 8;
            const float* s = srcb + (size_t)r * C_ + c8;
            cvt_store8(dst, (uint32_t)(r * 128 + c8 * 2),
                       *(const float4*)s, *(const float4*)(s + 4));
        }
    } else {
        const int kStep = bid - 4352;
        if (tid >= 192) return;                     // 48 rows * 4 chunks
        const int r = tid >> 2, c8 = (tid & 3) * 8;
        const float* s = (r < 32) ? (Wk + (size_t)r * C_ + kStep * 32 + c8)
                                  : (Ww + (size_t)(r - 32) * C_ + kStep * 32 + c8);
        char* dst = g_kwext + (size_t)kStep * 6144;
        cvt_store8(dst, (uint32_t)(r * 128 + c8 * 2),
                   *(const float4*)s, *(const float4*)(s + 4));
    }
}

// ===========================================================================
// Unified projection kernel. grid (9, 64):
//   nT in 0..7 : Q-proj, 64 output cols (nT*64..), writes g_qext (hi-only)
//   nT == 8    : K+W proj (48 cols from g_kwext), writes g_kext (full) + g_w
// CTA: 128(m) x 64(n), 256 threads, 8 warps 4(m) x 2(n), warp tile 32x32.
// k=64 stages (2 sub-tiles), 2-buffer cp.async, 32 iterations, 2 CTAs/SM.
// A = X hi-only (half traffic), B = W full split.
// ===========================================================================
__global__ void __launch_bounds__(256, 2)
proj_mma_kernel()
{
    extern __shared__ char dsm_raw[];
    char* dsm = (char*)(((uintptr_t)dsm_raw + 1023) & ~(uintptr_t)1023);
    // stage buffer: X0(16K fp) X1(16K fp) W0(8K) W1(8K) = 48KB; two buffers.

    const int tid  = threadIdx.x;
    const int wid  = tid >> 5;
    const int lane = tid & 31;
    const int nT    = blockIdx.x;           // 0..8
    const int mTile = blockIdx.y;           // 0..63
    const int m0 = (wid & 3) * 32;
    const int n0 = (wid >> 2) * 32;
    const bool iskw = (nT == 8);

    const char* xsrc = g_xext + (size_t)mTile * 64 * 16384;
    const char* wsrc = iskw ? g_kwext
                            : g_wqext + (size_t)(nT >> 1) * 64 * 16384 + (nT & 1) * 8192;
    const uint32_t wstep  = iskw ? 6144u : 16384u;   // bytes per k-step in gmem
    const uint32_t wbytes = iskw ? 6144u : 8192u;    // bytes to copy per k-step

    uint32_t sbase[2];
#pragma unroll
    for (int s = 0; s < 2; s++) sbase[s] = smem_u32(dsm + s * 49152);

    uint32_t aoff[2][2], boff[2][4];
    {
        const int arow = lane & 15, aseg = lane >> 4;
        const int brow = (lane & 7) + ((lane & 16) >> 1);
        const int bseg = (lane >> 3) & 1;
#pragma unroll
        for (int t = 0; t < 2; t++) {
#pragma unroll
            for (int ks = 0; ks < 2; ks++)       // A: hi frags only
                aoff[t][ks] = sw128((uint32_t)((m0 + t * 16 + arow) * 128 +
                                               ks * 32 + aseg * 16));
#pragma unroll
            for (int ks = 0; ks < 4; ks++)       // B: hi(0,1) + lo(2,3)
                boff[t][ks] = 32768u + sw128((uint32_t)((n0 + t * 16 + brow) * 128 +
                                                        ks * 32 + bseg * 16));
        }
    }

    // issue one k=64 stage (2 k-steps) into buffer bb; X hi chunks only
    auto issue_stage = [&](int stage, int bb) {
        const uint32_t sb = sbase[bb];
#pragma unroll
        for (int t = 0; t < 2; t++) {
            const size_t ks = (size_t)(stage * 2 + t);
            // X: 512 hi chunks (row, 4 chunks of 16B)
#pragma unroll
            for (int j = 0; j < 2; j++) {
                const int idx = tid + j * 256;
                const uint32_t off = sw128((uint32_t)((idx >> 2) * 128 + (idx & 3) * 16));
                cp16(sb + t * 16384u + off, xsrc + ks * 16384 + off);
            }
            // W: full
#pragma unroll
            for (int j = 0; j < 2; j++) {
                uint32_t off = (uint32_t)(tid + j * 256) * 16;
                if (off < wbytes)
                    cp16(sb + 32768u + t * 8192u + off, wsrc + ks * wstep + off);
            }
        }
    };

    // prologue: stage 0 -> buf 0
    issue_stage(0, 0);
    CP_COMMIT();

    float acc[2][4][4];
#pragma unroll
    for (int mt = 0; mt < 2; mt++)
#pragma unroll
        for (int nt = 0; nt < 4; nt++)
#pragma unroll
            for (int c = 0; c < 4; c++) acc[mt][nt][c] = 0.f;

#pragma unroll 1
    for (int it = 0; it < 32; it++) {
        CP_WAIT(0);          // stage it complete (only pending group)
        __syncthreads();     // all warps: data visible + prev compute retired
        if (it + 1 < 32) {
            issue_stage(it + 1, (it + 1) & 1);
            CP_COMMIT();
        }

        const uint32_t cb = sbase[it & 1];
#pragma unroll
        for (int t = 0; t < 2; t++) {
            const uint32_t xb = cb + (uint32_t)t * 16384u;
            const uint32_t wb = (uint32_t)t * 8192u;
            uint32_t bfr[2][4][4];
#pragma unroll
            for (int ntp = 0; ntp < 2; ntp++)
#pragma unroll
                for (int ks = 0; ks < 4; ks++)
                    ldsm4(bfr[ntp][ks], cb + wb + boff[ntp][ks]);

#pragma unroll
            for (int mt = 0; mt < 2; mt++) {
                uint32_t af[2][4];
#pragma unroll
                for (int ks = 0; ks < 2; ks++) ldsm4(af[ks], xb + aoff[mt][ks]);
                mma_split2b_x4(acc[mt][0], acc[mt][1], acc[mt][2], acc[mt][3],
                               af, bfr[0], bfr[1]);
            }
        }
    }

    // epilogue
#pragma unroll
    for (int mt = 0; mt < 2; mt++)
#pragma unroll
        for (int rp = 0; rp < 2; rp++) {
            const int r = m0 + mt * 16 + (lane >> 2) + rp * 8;
#pragma unroll
            for (int nt = 0; nt < 4; nt++) {
                const int colL = n0 + nt * 8 + (lane & 3) * 2;
                const float v0 = acc[mt][nt][rp * 2];
                const float v1 = acc[mt][nt][rp * 2 + 1];
                if (!iskw) {
                    const int col = nT * 64 + colL;
                    const int head = col >> 5;
                    const int d = col & 31;
                    char* dst = g_qext + ((size_t)mTile * 16 + head) * 16384;
                    *(uint32_t*)(dst + sw128((uint32_t)(r * 128 + d * 2))) =
                        pack2h(v0, v1);                       // hi-only
                } else if (colL < 32) {
                    uint32_t hi, lo;
                    split2(v0, v1, hi, lo);
                    char* dst = g_kext + (size_t)mTile * 16384;
                    *(uint32_t*)(dst + sw128((uint32_t)(r * 128 + colL * 2)))      = hi;
                    *(uint32_t*)(dst + sw128((uint32_t)(r * 128 + 64 + colL * 2))) = lo;
                } else if (colL < 48) {
                    *(float2*)(g_w + (size_t)(mTile * 128 + r) * H_ + (colL - 32)) =
                        make_float2(v0, v1);
                }
            }
        }
}

// ===========================================================================
// Fused scores+importance: out[b,q,k] = sum_h w[b,q,h]*relu(dot(q,k))
// CTA = 128(q) x 64(k), 256 threads, 8 warps 4(m)x2(n), 2 CTAs/SM.
// A = Q hi-only (streamed, half traffic); B = K full split (resident).
// Q streamed 2 HEADS per stage (3 x 32KB ring footprint, 16KB copied).
// ===========================================================================
__global__ void __launch_bounds__(256, 2)
fused_mma_kernel(float* __restrict__ out)
{
    extern __shared__ char dsm_raw[];
    char* dsm = (char*)(((uintptr_t)dsm_raw + 1023) & ~(uintptr_t)1023);
    char* Ks   = dsm;                    // 8KB (64 rows, full hi+lo)
    char* Qb   = dsm + 8192;             // 3 x 32KB (2 head tiles per stage)
    float* w_s = (float*)(dsm + 106496); // 8KB

    const int tid  = threadIdx.x;
    const int wid  = tid >> 5;
    const int lane = tid & 31;
    const int b  = blockIdx.z;
    const int kT = blockIdx.x;          // 0..63 (64-col k tiles)
    const int q0 = blockIdx.y * 128;
    const int k0 = kT * 64;
    const int m0 = (wid & 3) * 32;
    const int n0 = (wid >> 2) * 32;     // 0 or 32 within the 64-col slice

    const int qTile = b * 32 + blockIdx.y;
    const char* qsrc = g_qext + (size_t)qTile * 16 * 16384;
    const char* ksrc = g_kext + (size_t)(b * 32 + (kT >> 1)) * 16384 + (kT & 1) * 8192;
    const float* wsrc = g_w + (size_t)(b * T_ + q0) * H_;

    const uint32_t ksb = smem_u32(Ks);
    const uint32_t wsb_smem = smem_u32(w_s);
    uint32_t qbase[3];
#pragma unroll
    for (int s = 0; s < 3; s++) qbase[s] = smem_u32(Qb + s * 32768);

    // Q head-pair loader: 1024 hi chunks (2 heads x 128 rows x 4)
    auto load_qpair = [&](uint32_t qb, const char* src) {
#pragma unroll
        for (int j = 0; j < 4; j++) {
            const int idx = tid + j * 256;          // 0..1023
            const int rem = idx & 511;
            const uint32_t off = (uint32_t)(idx >> 9) * 16384u +
                                 sw128((uint32_t)((rem >> 2) * 128 + (rem & 3) * 16));
            cp16(qb + off, src + off);
        }
    };

    // prologue: G0 = {K, w, headpair 0}, G1 = {headpair 1}
#pragma unroll
    for (int j = 0; j < 2; j++) {
        uint32_t off = (uint32_t)(tid + j * 256) * 16;
        cp16(ksb + off, ksrc + off);
        cp16(wsb_smem + off, (const char*)wsrc + off);
    }
    load_qpair(qbase[0], qsrc);
    CP_COMMIT();
    load_qpair(qbase[1], qsrc + 32768);
    CP_COMMIT();

    uint32_t aoff[2][2];
    uint32_t baddr[2][4];
    {
        const int arow = lane & 15, aseg = lane >> 4;
        const int brow = (lane & 7) + ((lane & 16) >> 1);
        const int bseg = (lane >> 3) & 1;
#pragma unroll
        for (int t = 0; t < 2; t++) {
#pragma unroll
            for (int ks = 0; ks < 2; ks++)       // Q: hi frags only
                aoff[t][ks] = sw128((uint32_t)((m0 + t * 16 + arow) * 128 +
                                               ks * 32 + aseg * 16));
#pragma unroll
            for (int ks = 0; ks < 4; ks++)       // K: hi(0,1) + lo(2,3)
                baddr[t][ks] = ksb + sw128((uint32_t)((n0 + t * 16 + brow) * 128 +
                                                      ks * 32 + bseg * 16));
        }
    }

    float acc[2][4][4];
#pragma unroll
    for (int mt = 0; mt < 2; mt++)
#pragma unroll
        for (int nt = 0; nt < 4; nt++)
#pragma unroll
            for (int c = 0; c < 4; c++) acc[mt][nt][c] = 0.f;

    CP_WAIT(1);       // G0 done: K, w, headpair 0
    __syncthreads();

    // K full fragments register-resident (this warp's 32 n-cols)
    uint32_t bfr[2][4][4];
#pragma unroll
    for (int ntp = 0; ntp < 2; ntp++)
#pragma unroll
        for (int ks = 0; ks < 4; ks++) ldsm4(bfr[ntp][ks], baddr[ntp][ks]);

    const int wrow0 = m0 + (lane >> 2);

#pragma unroll 1
    for (int p = 0; p < H_ / 2; p++) {      // head pairs
        if (p > 0) {
            if (p == H_ / 2 - 1) CP_WAIT(0); else CP_WAIT(1);
            __syncthreads();
        }
        if (p + 2 < H_ / 2)
            load_qpair(qbase[(p + 2) % 3], qsrc + (size_t)(p + 2) * 32768);
        CP_COMMIT();

        const uint32_t qb = qbase[p % 3];
#pragma unroll
        for (int hh = 0; hh < 2; hh++) {
            const int h = p * 2 + hh;
            const uint32_t qbh = qb + (uint32_t)hh * 16384u;
#pragma unroll
            for (int mt = 0; mt < 2; mt++) {
                uint32_t af[2][4];
#pragma unroll
                for (int ks = 0; ks < 2; ks++) ldsm4(af[ks], qbh + aoff[mt][ks]);

                const float wv0 = w_s[(wrow0 + mt * 16) * H_ + h];
                const float wv1 = w_s[(wrow0 + mt * 16 + 8) * H_ + h];

                float s[2][2][4];
#pragma unroll
                for (int ntp = 0; ntp < 2; ntp++)
#pragma unroll
                    for (int q = 0; q < 2; q++)
#pragma unroll
                        for (int c = 0; c < 4; c++) s[ntp][q][c] = 0.f;

                mma_split2b_x4(s[0][0], s[0][1], s[1][0], s[1][1],
                               af, bfr[0], bfr[1]);

#pragma unroll
                for (int ntp = 0; ntp < 2; ntp++)
#pragma unroll
                    for (int q = 0; q < 2; q++) {
                        float* a = acc[mt][ntp * 2 + q];
                        const float* sv = s[ntp][q];
                        a[0] += wv0 * fmaxf(sv[0], 0.f);
                        a[1] += wv0 * fmaxf(sv[1], 0.f);
                        a[2] += wv1 * fmaxf(sv[2], 0.f);
                        a[3] += wv1 * fmaxf(sv[3], 0.f);
                    }
            }
        }
    }

    // epilogue
#pragma unroll
    for (int mt = 0; mt < 2; mt++)
#pragma unroll
        for (int rp = 0; rp < 2; rp++) {
            const int row = q0 + m0 + mt * 16 + (lane >> 2) + rp * 8;
            float* op = out + (size_t)(b * T_ + row) * T_ + k0 + n0 + (lane & 3) * 2;
#pragma unroll
            for (int nt = 0; nt < 4; nt++)
                *(float2*)(op + nt * 8) =
                    make_float2(acc[mt][nt][rp * 2], acc[mt][nt][rp * 2 + 1]);
        }
}

// ===========================================================================
extern "C" void kernel_launch(void* const* d_in, const int* in_sizes, int n_in,
                              void* d_out, int out_size)
{
    (void)in_sizes; (void)n_in; (void)out_size;
    const float* x  = (const float*)d_in[0];
    const float* Wq = (const float*)d_in[1];
    const float* Wk = (const float*)d_in[2];
    const float* Ww = (const float*)d_in[3];
    float* out = (float*)d_out;

    static bool attr_done = false;
    if (!attr_done) {
        cudaFuncSetAttribute(proj_mma_kernel,
                             cudaFuncAttributeMaxDynamicSharedMemorySize, 99328);
        cudaFuncSetAttribute(fused_mma_kernel,
                             cudaFuncAttributeMaxDynamicSharedMemorySize, 115712);
        attr_done = true;
    }

    cvt_all_kernel<<<4416, 256>>>(x, Wq, Wk, Ww);
    proj_mma_kernel<<<dim3(9, 64), 256, 99328>>>();
    fused_mma_kernel<<<dim3(T_ / 64, T_ / 128, B_), 256, 115712>>>(out);
}

// round 13
// speedup vs baseline: 5.9167x; 1.2336x over previous
#include <cuda_runtime.h>
#include <cuda_fp16.h>
#include <cstdint>

// Problem constants
#define B_ 2
#define T_ 4096
#define C_ 2048
#define H_ 16
#define D_ 32

// ---------------------------------------------------------------------------
// Ext-fp16 tile formats (sw128-swizzled, 128B physical rows):
//  FULL tile (16KB/128rows): row r, ext col c in [0,64): c<32 = hi of d=c,
//    c>=32 = lo of d=c-32, at byte sw128(r*128 + c*2).  (W, K tiles)
//  HI-ONLY tile: same addressing, lo half never written/read (holes).
// Proj product (4 MMAs): x_hi * (w_hi + w_lo)   drops x_lo*w (~2^-12)
// Fused product (2 MMAs): q_hi * k_hi           drops q_hi*k_lo (~2^-12)
// ---------------------------------------------------------------------------
__device__ __align__(1024) char g_xext [(size_t)64 * 64 * 16384];  // [rowTile][kStep] hi-only
__device__ __align__(1024) char g_wqext[(size_t)4  * 64 * 16384];  // [nTile][kStep] full
__device__ __align__(1024) char g_kwext[(size_t)64 * 6144];        // [kStep] 48 rows, full
__device__ __align__(1024) char g_qext [(size_t)64 * 16 * 16384];  // [qTile][head] hi-only
__device__ __align__(1024) char g_kext [(size_t)64 * 16384];       // [kTile] full (fused reads hi)
__device__ __align__(1024) float g_w[(size_t)B_ * T_ * H_];        // [8192][16]

// ===========================================================================
// Helpers (base sm_103-safe: ldmatrix + mma.sync + cp.async)
// ===========================================================================
__device__ __forceinline__ uint32_t smem_u32(const void* p) {
    uint32_t a;
    asm("{ .reg .u64 t; cvta.to.shared.u64 t, %1; cvt.u32.u64 %0, t; }"
        : "=r"(a) : "l"(p));
    return a;
}

__device__ __forceinline__ uint32_t sw128(uint32_t o) { return o ^ ((o >> 3) & 0x70); }

__device__ __forceinline__ void ldsm4(uint32_t* r, uint32_t a) {
    asm volatile("ldmatrix.sync.aligned.m8n8.x4.shared.b16 {%0,%1,%2,%3}, [%4];"
                 : "=r"(r[0]), "=r"(r[1]), "=r"(r[2]), "=r"(r[3]) : "r"(a));
}

__device__ __forceinline__ void mma_f16(float* d, const uint32_t* a, const uint32_t* b) {
    asm volatile(
        "mma.sync.aligned.m16n8k16.row.col.f32.f16.f16.f32 "
        "{%0,%1,%2,%3}, {%4,%5,%6,%7}, {%8,%9}, {%0,%1,%2,%3};"
        : "+f"(d[0]), "+f"(d[1]), "+f"(d[2]), "+f"(d[3])
        : "r"(a[0]), "r"(a[1]), "r"(a[2]), "r"(a[3]), "r"(b[0]), "r"(b[1]));
}

__device__ __forceinline__ void cp16(uint32_t s, const void* g) {
    asm volatile("cp.async.cg.shared.global [%0], [%1], 16;" :: "r"(s), "l"(g));
}
#define CP_COMMIT() asm volatile("cp.async.commit_group;" ::: "memory")
#define CP_WAIT(n)  asm volatile("cp.async.wait_group %0;" :: "n"(n) : "memory")

__device__ __forceinline__ uint32_t pack2h(float x, float y) {
    __half h0 = __float2half_rn(x), h1 = __float2half_rn(y);
    return ((uint32_t)__half_as_ushort(h1) << 16) | (uint32_t)__half_as_ushort(h0);
}

// split two f32 into packed fp16 hi-pair and fp16 lo-pair (lo = residual)
__device__ __forceinline__ void split2(float v0, float v1, uint32_t& hi, uint32_t& lo) {
    __half h0 = __float2half_rn(v0), h1 = __float2half_rn(v1);
    hi = ((uint32_t)__half_as_ushort(h1) << 16) | (uint32_t)__half_as_ushort(h0);
    __half g0 = __float2half_rn(v0 - __half2float(h0));
    __half g1 = __float2half_rn(v1 - __half2float(h1));
    lo = ((uint32_t)__half_as_ushort(g1) << 16) | (uint32_t)__half_as_ushort(g0);
}

// 8 consecutive f32 -> full tile: 16B hi + 16B lo stores
__device__ __forceinline__ void cvt_store8(char* tile, uint32_t base_off,
                                           float4 a, float4 b) {
    uint4 hi, lo;
    split2(a.x, a.y, hi.x, lo.x);
    split2(a.z, a.w, hi.y, lo.y);
    split2(b.x, b.y, hi.z, lo.z);
    split2(b.z, b.w, hi.w, lo.w);
    *(uint4*)(tile + sw128(base_off))      = hi;
    *(uint4*)(tile + sw128(base_off + 64)) = lo;
}

// 8 consecutive f32 -> hi-only tile: single 16B store
__device__ __forceinline__ void cvt_store8_hi(char* tile, uint32_t base_off,
                                              float4 a, float4 b) {
    uint4 hi;
    hi.x = pack2h(a.x, a.y);
    hi.y = pack2h(a.z, a.w);
    hi.z = pack2h(b.x, b.y);
    hi.w = pack2h(b.z, b.w);
    *(uint4*)(tile + sw128(base_off)) = hi;
}

// Proj product: s = a_hi * (b_hi + b_lo), 4 MMAs over four chains.
__device__ __forceinline__ void mma_split2b_x4(float* s00, float* s01,
                                               float* s10, float* s11,
                                               const uint32_t af[2][4],
                                               const uint32_t b0[4][4],
                                               const uint32_t b1[4][4]) {
    const int PA[4] = {0, 1, 0, 1};
    const int PB[4] = {0, 1, 2, 3};
#pragma unroll
    for (int p = 0; p < 4; p++) {
        mma_f16(s00, af[PA[p]], &b0[PB[p]][0]);
        mma_f16(s01, af[PA[p]], &b0[PB[p]][2]);
        mma_f16(s10, af[PA[p]], &b1[PB[p]][0]);
        mma_f16(s11, af[PA[p]], &b1[PB[p]][2]);
    }
}

// Fused product: s = a_hi * b_hi, 2 MMAs over four chains.
__device__ __forceinline__ void mma_hh_x4(float* s00, float* s01,
                                          float* s10, float* s11,
                                          const uint32_t af[2][4],
                                          const uint32_t b0[2][4],
                                          const uint32_t b1[2][4]) {
#pragma unroll
    for (int p = 0; p < 2; p++) {
        mma_f16(s00, af[p], &b0[p][0]);
        mma_f16(s01, af[p], &b0[p][2]);
        mma_f16(s10, af[p], &b1[p][0]);
        mma_f16(s11, af[p], &b1[p][2]);
    }
}

// ===========================================================================
// Merged conversion pass.
// Linear grid: [0,4096) X tiles (hi-only), [4096,4352) Wq (full),
// [4352,4416) WkWw (full).
// ===========================================================================
__global__ void __launch_bounds__(256)
cvt_all_kernel(const float* __restrict__ X, const float* __restrict__ Wq,
               const float* __restrict__ Wk, const float* __restrict__ Ww)
{
    const int bid = blockIdx.x;
    const int tid = threadIdx.x;

    if (bid < 4096) {
        const int rowTile = bid >> 6, kStep = bid & 63;
        const float* srcb = X + (size_t)(rowTile * 128) * C_ + kStep * 32;
        char* dst = g_xext + ((size_t)rowTile * 64 + kStep) * 16384;
#pragma unroll
        for (int j = 0; j < 2; j++) {
            const int idx = tid + j * 256;          // 0..511
            const int r = idx >> 2, c8 = (idx & 3) * 8;
            const float* s = srcb + (size_t)r * C_ + c8;
            cvt_store8_hi(dst, (uint32_t)(r * 128 + c8 * 2),
                          *(const float4*)s, *(const float4*)(s + 4));
        }
    } else if (bid < 4352) {
        const int t = bid - 4096;
        const int nTile = t >> 6, kStep = t & 63;
        const float* srcb = Wq + (size_t)(nTile * 128) * C_ + kStep * 32;
        char* dst = g_wqext + ((size_t)nTile * 64 + kStep) * 16384;
#pragma unroll
        for (int j = 0; j < 2; j++) {
            const int idx = tid + j * 256;
            const int r = idx >> 2, c8 = (idx & 3) * 8;
            const float* s = srcb + (size_t)r * C_ + c8;
            cvt_store8(dst, (uint32_t)(r * 128 + c8 * 2),
                       *(const float4*)s, *(const float4*)(s + 4));
        }
    } else {
        const int kStep = bid - 4352;
        if (tid >= 192) return;                     // 48 rows * 4 chunks
        const int r = tid >> 2, c8 = (tid & 3) * 8;
        const float* s = (r < 32) ? (Wk + (size_t)r * C_ + kStep * 32 + c8)
                                  : (Ww + (size_t)(r - 32) * C_ + kStep * 32 + c8);
        char* dst = g_kwext + (size_t)kStep * 6144;
        cvt_store8(dst, (uint32_t)(r * 128 + c8 * 2),
                   *(const float4*)s, *(const float4*)(s + 4));
    }
}

// ===========================================================================
// Unified projection kernel. grid (9, 64):
//   nT in 0..7 : Q-proj, 64 output cols (nT*64..), writes g_qext (hi-only)
//   nT == 8    : K+W proj (48 cols from g_kwext), writes g_kext (full) + g_w
// CTA: 128(m) x 64(n), 256 threads, 8 warps 4(m) x 2(n), warp tile 32x32.
// k=64 stages (2 sub-tiles), 2-buffer cp.async, 32 iterations, 2 CTAs/SM.
// A = X hi-only (half traffic), B = W full split.
// ===========================================================================
__global__ void __launch_bounds__(256, 2)
proj_mma_kernel()
{
    extern __shared__ char dsm_raw[];
    char* dsm = (char*)(((uintptr_t)dsm_raw + 1023) & ~(uintptr_t)1023);
    // stage buffer: X0(16K fp) X1(16K fp) W0(8K) W1(8K) = 48KB; two buffers.

    const int tid  = threadIdx.x;
    const int wid  = tid >> 5;
    const int lane = tid & 31;
    const int nT    = blockIdx.x;           // 0..8
    const int mTile = blockIdx.y;           // 0..63
    const int m0 = (wid & 3) * 32;
    const int n0 = (wid >> 2) * 32;
    const bool iskw = (nT == 8);

    const char* xsrc = g_xext + (size_t)mTile * 64 * 16384;
    const char* wsrc = iskw ? g_kwext
                            : g_wqext + (size_t)(nT >> 1) * 64 * 16384 + (nT & 1) * 8192;
    const uint32_t wstep  = iskw ? 6144u : 16384u;   // bytes per k-step in gmem
    const uint32_t wbytes = iskw ? 6144u : 8192u;    // bytes to copy per k-step

    uint32_t sbase[2];
#pragma unroll
    for (int s = 0; s < 2; s++) sbase[s] = smem_u32(dsm + s * 49152);

    uint32_t aoff[2][2], boff[2][4];
    {
        const int arow = lane & 15, aseg = lane >> 4;
        const int brow = (lane & 7) + ((lane & 16) >> 1);
        const int bseg = (lane >> 3) & 1;
#pragma unroll
        for (int t = 0; t < 2; t++) {
#pragma unroll
            for (int ks = 0; ks < 2; ks++)       // A: hi frags only
                aoff[t][ks] = sw128((uint32_t)((m0 + t * 16 + arow) * 128 +
                                               ks * 32 + aseg * 16));
#pragma unroll
            for (int ks = 0; ks < 4; ks++)       // B: hi(0,1) + lo(2,3)
                boff[t][ks] = 32768u + sw128((uint32_t)((n0 + t * 16 + brow) * 128 +
                                                        ks * 32 + bseg * 16));
        }
    }

    // issue one k=64 stage (2 k-steps) into buffer bb; X hi chunks only
    auto issue_stage = [&](int stage, int bb) {
        const uint32_t sb = sbase[bb];
#pragma unroll
        for (int t = 0; t < 2; t++) {
            const size_t ks = (size_t)(stage * 2 + t);
            // X: 512 hi chunks (row, 4 chunks of 16B)
#pragma unroll
            for (int j = 0; j < 2; j++) {
                const int idx = tid + j * 256;
                const uint32_t off = sw128((uint32_t)((idx >> 2) * 128 + (idx & 3) * 16));
                cp16(sb + t * 16384u + off, xsrc + ks * 16384 + off);
            }
            // W: full
#pragma unroll
            for (int j = 0; j < 2; j++) {
                uint32_t off = (uint32_t)(tid + j * 256) * 16;
                if (off < wbytes)
                    cp16(sb + 32768u + t * 8192u + off, wsrc + ks * wstep + off);
            }
        }
    };

    // prologue: stage 0 -> buf 0
    issue_stage(0, 0);
    CP_COMMIT();

    float acc[2][4][4];
#pragma unroll
    for (int mt = 0; mt < 2; mt++)
#pragma unroll
        for (int nt = 0; nt < 4; nt++)
#pragma unroll
            for (int c = 0; c < 4; c++) acc[mt][nt][c] = 0.f;

#pragma unroll 1
    for (int it = 0; it < 32; it++) {
        CP_WAIT(0);          // stage it complete (only pending group)
        __syncthreads();     // all warps: data visible + prev compute retired
        if (it + 1 < 32) {
            issue_stage(it + 1, (it + 1) & 1);
            CP_COMMIT();
        }

        const uint32_t cb = sbase[it & 1];
#pragma unroll
        for (int t = 0; t < 2; t++) {
            const uint32_t xb = cb + (uint32_t)t * 16384u;
            const uint32_t wb = (uint32_t)t * 8192u;
            uint32_t bfr[2][4][4];
#pragma unroll
            for (int ntp = 0; ntp < 2; ntp++)
#pragma unroll
                for (int ks = 0; ks < 4; ks++)
                    ldsm4(bfr[ntp][ks], cb + wb + boff[ntp][ks]);

#pragma unroll
            for (int mt = 0; mt < 2; mt++) {
                uint32_t af[2][4];
#pragma unroll
                for (int ks = 0; ks < 2; ks++) ldsm4(af[ks], xb + aoff[mt][ks]);
                mma_split2b_x4(acc[mt][0], acc[mt][1], acc[mt][2], acc[mt][3],
                               af, bfr[0], bfr[1]);
            }
        }
    }

    // epilogue
#pragma unroll
    for (int mt = 0; mt < 2; mt++)
#pragma unroll
        for (int rp = 0; rp < 2; rp++) {
            const int r = m0 + mt * 16 + (lane >> 2) + rp * 8;
#pragma unroll
            for (int nt = 0; nt < 4; nt++) {
                const int colL = n0 + nt * 8 + (lane & 3) * 2;
                const float v0 = acc[mt][nt][rp * 2];
                const float v1 = acc[mt][nt][rp * 2 + 1];
                if (!iskw) {
                    const int col = nT * 64 + colL;
                    const int head = col >> 5;
                    const int d = col & 31;
                    char* dst = g_qext + ((size_t)mTile * 16 + head) * 16384;
                    *(uint32_t*)(dst + sw128((uint32_t)(r * 128 + d * 2))) =
                        pack2h(v0, v1);                       // hi-only
                } else if (colL < 32) {
                    uint32_t hi, lo;
                    split2(v0, v1, hi, lo);
                    char* dst = g_kext + (size_t)mTile * 16384;
                    *(uint32_t*)(dst + sw128((uint32_t)(r * 128 + colL * 2)))      = hi;
                    *(uint32_t*)(dst + sw128((uint32_t)(r * 128 + 64 + colL * 2))) = lo;
                } else if (colL < 48) {
                    *(float2*)(g_w + (size_t)(mTile * 128 + r) * H_ + (colL - 32)) =
                        make_float2(v0, v1);
                }
            }
        }
}

// ===========================================================================
// Fused scores+importance: out[b,q,k] = sum_h w[b,q,h]*relu(dot(q,k))
// CTA = 128(q) x 64(k), 256 threads, 8 warps 4(m)x2(n), 2 CTAs/SM.
// A = Q hi-only (streamed); B = K hi-only frags (resident, lo ignored).
// Product = q_hi * k_hi (2 MMAs/frag-pair).
// Q streamed 2 HEADS per stage (3 x 32KB ring footprint, 16KB copied).
// ===========================================================================
__global__ void __launch_bounds__(256, 2)
fused_mma_kernel(float* __restrict__ out)
{
    extern __shared__ char dsm_raw[];
    char* dsm = (char*)(((uintptr_t)dsm_raw + 1023) & ~(uintptr_t)1023);
    char* Ks   = dsm;                    // 8KB (64 rows, full hi+lo stored)
    char* Qb   = dsm + 8192;             // 3 x 32KB (2 head tiles per stage)
    float* w_s = (float*)(dsm + 106496); // 8KB

    const int tid  = threadIdx.x;
    const int wid  = tid >> 5;
    const int lane = tid & 31;
    const int b  = blockIdx.z;
    const int kT = blockIdx.x;          // 0..63 (64-col k tiles)
    const int q0 = blockIdx.y * 128;
    const int k0 = kT * 64;
    const int m0 = (wid & 3) * 32;
    const int n0 = (wid >> 2) * 32;     // 0 or 32 within the 64-col slice

    const int qTile = b * 32 + blockIdx.y;
    const char* qsrc = g_qext + (size_t)qTile * 16 * 16384;
    const char* ksrc = g_kext + (size_t)(b * 32 + (kT >> 1)) * 16384 + (kT & 1) * 8192;
    const float* wsrc = g_w + (size_t)(b * T_ + q0) * H_;

    const uint32_t ksb = smem_u32(Ks);
    const uint32_t wsb_smem = smem_u32(w_s);
    uint32_t qbase[3];
#pragma unroll
    for (int s = 0; s < 3; s++) qbase[s] = smem_u32(Qb + s * 32768);

    // Q head-pair loader: 1024 hi chunks (2 heads x 128 rows x 4)
    auto load_qpair = [&](uint32_t qb, const char* src) {
#pragma unroll
        for (int j = 0; j < 4; j++) {
            const int idx = tid + j * 256;          // 0..1023
            const int rem = idx & 511;
            const uint32_t off = (uint32_t)(idx >> 9) * 16384u +
                                 sw128((uint32_t)((rem >> 2) * 128 + (rem & 3) * 16));
            cp16(qb + off, src + off);
        }
    };

    // prologue: G0 = {K, w, headpair 0}, G1 = {headpair 1}
#pragma unroll
    for (int j = 0; j < 2; j++) {
        uint32_t off = (uint32_t)(tid + j * 256) * 16;
        cp16(ksb + off, ksrc + off);
        cp16(wsb_smem + off, (const char*)wsrc + off);
    }
    load_qpair(qbase[0], qsrc);
    CP_COMMIT();
    load_qpair(qbase[1], qsrc + 32768);
    CP_COMMIT();

    uint32_t aoff[2][2];
    uint32_t baddr[2][2];
    {
        const int arow = lane & 15, aseg = lane >> 4;
        const int brow = (lane & 7) + ((lane & 16) >> 1);
        const int bseg = (lane >> 3) & 1;
#pragma unroll
        for (int t = 0; t < 2; t++) {
#pragma unroll
            for (int ks = 0; ks < 2; ks++) {     // hi frags only, both sides
                aoff[t][ks] = sw128((uint32_t)((m0 + t * 16 + arow) * 128 +
                                               ks * 32 + aseg * 16));
                baddr[t][ks] = ksb + sw128((uint32_t)((n0 + t * 16 + brow) * 128 +
                                                      ks * 32 + bseg * 16));
            }
        }
    }

    float acc[2][4][4];
#pragma unroll
    for (int mt = 0; mt < 2; mt++)
#pragma unroll
        for (int nt = 0; nt < 4; nt++)
#pragma unroll
            for (int c = 0; c < 4; c++) acc[mt][nt][c] = 0.f;

    CP_WAIT(1);       // G0 done: K, w, headpair 0
    __syncthreads();

    // K hi fragments register-resident (this warp's 32 n-cols)
    uint32_t bfr[2][2][4];
#pragma unroll
    for (int ntp = 0; ntp < 2; ntp++)
#pragma unroll
        for (int ks = 0; ks < 2; ks++) ldsm4(bfr[ntp][ks], baddr[ntp][ks]);

    const int wrow0 = m0 + (lane >> 2);

#pragma unroll 1
    for (int p = 0; p < H_ / 2; p++) {      // head pairs
        if (p > 0) {
            if (p == H_ / 2 - 1) CP_WAIT(0); else CP_WAIT(1);
            __syncthreads();
        }
        if (p + 2 < H_ / 2)
            load_qpair(qbase[(p + 2) % 3], qsrc + (size_t)(p + 2) * 32768);
        CP_COMMIT();

        const uint32_t qb = qbase[p % 3];
#pragma unroll
        for (int hh = 0; hh < 2; hh++) {
            const int h = p * 2 + hh;
            const uint32_t qbh = qb + (uint32_t)hh * 16384u;
#pragma unroll
            for (int mt = 0; mt < 2; mt++) {
                uint32_t af[2][4];
#pragma unroll
                for (int ks = 0; ks < 2; ks++) ldsm4(af[ks], qbh + aoff[mt][ks]);

                const float wv0 = w_s[(wrow0 + mt * 16) * H_ + h];
                const float wv1 = w_s[(wrow0 + mt * 16 + 8) * H_ + h];

                float s[2][2][4];
#pragma unroll
                for (int ntp = 0; ntp < 2; ntp++)
#pragma unroll
                    for (int q = 0; q < 2; q++)
#pragma unroll
                        for (int c = 0; c < 4; c++) s[ntp][q][c] = 0.f;

                mma_hh_x4(s[0][0], s[0][1], s[1][0], s[1][1],
                          af, bfr[0], bfr[1]);

#pragma unroll
                for (int ntp = 0; ntp < 2; ntp++)
#pragma unroll
                    for (int q = 0; q < 2; q++) {
                        float* a = acc[mt][ntp * 2 + q];
                        const float* sv = s[ntp][q];
                        a[0] += wv0 * fmaxf(sv[0], 0.f);
                        a[1] += wv0 * fmaxf(sv[1], 0.f);
                        a[2] += wv1 * fmaxf(sv[2], 0.f);
                        a[3] += wv1 * fmaxf(sv[3], 0.f);
                    }
            }
        }
    }

    // epilogue
#pragma unroll
    for (int mt = 0; mt < 2; mt++)
#pragma unroll
        for (int rp = 0; rp < 2; rp++) {
            const int row = q0 + m0 + mt * 16 + (lane >> 2) + rp * 8;
            float* op = out + (size_t)(b * T_ + row) * T_ + k0 + n0 + (lane & 3) * 2;
#pragma unroll
            for (int nt = 0; nt < 4; nt++)
                *(float2*)(op + nt * 8) =
                    make_float2(acc[mt][nt][rp * 2], acc[mt][nt][rp * 2 + 1]);
        }
}

// ===========================================================================
extern "C" void kernel_launch(void* const* d_in, const int* in_sizes, int n_in,
                              void* d_out, int out_size)
{
    (void)in_sizes; (void)n_in; (void)out_size;
    const float* x  = (const float*)d_in[0];
    const float* Wq = (const float*)d_in[1];
    const float* Wk = (const float*)d_in[2];
    const float* Ww = (const float*)d_in[3];
    float* out = (float*)d_out;

    static bool attr_done = false;
    if (!attr_done) {
        cudaFuncSetAttribute(proj_mma_kernel,
                             cudaFuncAttributeMaxDynamicSharedMemorySize, 99328);
        cudaFuncSetAttribute(fused_mma_kernel,
                             cudaFuncAttributeMaxDynamicSharedMemorySize, 115712);
        attr_done = true;
    }

    cvt_all_kernel<<<4416, 256>>>(x, Wq, Wk, Ww);
    proj_mma_kernel<<<dim3(9, 64), 256, 99328>>>();
    fused_mma_kernel<<<dim3(T_ / 64, T_ / 128, B_), 256, 115712>>>(out);
}

// round 14
// speedup vs baseline: 6.8565x; 1.1588x over previous
#include <cuda_runtime.h>
#include <cuda_fp16.h>
#include <cstdint>

// Problem constants
#define B_ 2
#define T_ 4096
#define C_ 2048
#define H_ 16
#define D_ 32

// ---------------------------------------------------------------------------
// Ext-fp16 tile formats (sw128-swizzled, 128B physical rows):
//  FULL tile (16KB/128rows): row r, ext col c in [0,64): c<32 = hi of d=c,
//    c>=32 = lo of d=c-32, at byte sw128(r*128 + c*2).
//  HI-ONLY tile: same addressing, lo half never written/read (holes).
// All products now pure hi x hi (2 MMAs per 16x16 frag-pair); dropped terms
// are each ~2^-12 relative and compose ~RSS (measured rounds 11-13).
// ---------------------------------------------------------------------------
__device__ __align__(1024) char g_xext [(size_t)64 * 64 * 16384];  // [rowTile][kStep] hi-only
__device__ __align__(1024) char g_wqext[(size_t)4  * 64 * 16384];  // [nTile][kStep] full (hi read)
__device__ __align__(1024) char g_kwext[(size_t)64 * 6144];        // [kStep] 48 rows, full (hi read)
__device__ __align__(1024) char g_qext [(size_t)64 * 16 * 16384];  // [qTile][head] hi-only
__device__ __align__(1024) char g_kext [(size_t)64 * 16384];       // [kTile] hi-only
__device__ __align__(1024) float g_w[(size_t)B_ * T_ * H_];        // [8192][16]

// ===========================================================================
// Helpers (base sm_103-safe: ldmatrix + mma.sync + cp.async)
// ===========================================================================
__device__ __forceinline__ uint32_t smem_u32(const void* p) {
    uint32_t a;
    asm("{ .reg .u64 t; cvta.to.shared.u64 t, %1; cvt.u32.u64 %0, t; }"
        : "=r"(a) : "l"(p));
    return a;
}

__device__ __forceinline__ uint32_t sw128(uint32_t o) { return o ^ ((o >> 3) & 0x70); }

__device__ __forceinline__ void ldsm4(uint32_t* r, uint32_t a) {
    asm volatile("ldmatrix.sync.aligned.m8n8.x4.shared.b16 {%0,%1,%2,%3}, [%4];"
                 : "=r"(r[0]), "=r"(r[1]), "=r"(r[2]), "=r"(r[3]) : "r"(a));
}

__device__ __forceinline__ void mma_f16(float* d, const uint32_t* a, const uint32_t* b) {
    asm volatile(
        "mma.sync.aligned.m16n8k16.row.col.f32.f16.f16.f32 "
        "{%0,%1,%2,%3}, {%4,%5,%6,%7}, {%8,%9}, {%0,%1,%2,%3};"
        : "+f"(d[0]), "+f"(d[1]), "+f"(d[2]), "+f"(d[3])
        : "r"(a[0]), "r"(a[1]), "r"(a[2]), "r"(a[3]), "r"(b[0]), "r"(b[1]));
}

__device__ __forceinline__ void cp16(uint32_t s, const void* g) {
    asm volatile("cp.async.cg.shared.global [%0], [%1], 16;" :: "r"(s), "l"(g));
}
#define CP_COMMIT() asm volatile("cp.async.commit_group;" ::: "memory")
#define CP_WAIT(n)  asm volatile("cp.async.wait_group %0;" :: "n"(n) : "memory")

__device__ __forceinline__ uint32_t pack2h(float x, float y) {
    __half h0 = __float2half_rn(x), h1 = __float2half_rn(y);
    return ((uint32_t)__half_as_ushort(h1) << 16) | (uint32_t)__half_as_ushort(h0);
}

// split two f32 into packed fp16 hi-pair and fp16 lo-pair (lo = residual)
__device__ __forceinline__ void split2(float v0, float v1, uint32_t& hi, uint32_t& lo) {
    __half h0 = __float2half_rn(v0), h1 = __float2half_rn(v1);
    hi = ((uint32_t)__half_as_ushort(h1) << 16) | (uint32_t)__half_as_ushort(h0);
    __half g0 = __float2half_rn(v0 - __half2float(h0));
    __half g1 = __float2half_rn(v1 - __half2float(h1));
    lo = ((uint32_t)__half_as_ushort(g1) << 16) | (uint32_t)__half_as_ushort(g0);
}

// 8 consecutive f32 -> full tile: 16B hi + 16B lo stores
__device__ __forceinline__ void cvt_store8(char* tile, uint32_t base_off,
                                           float4 a, float4 b) {
    uint4 hi, lo;
    split2(a.x, a.y, hi.x, lo.x);
    split2(a.z, a.w, hi.y, lo.y);
    split2(b.x, b.y, hi.z, lo.z);
    split2(b.z, b.w, hi.w, lo.w);
    *(uint4*)(tile + sw128(base_off))      = hi;
    *(uint4*)(tile + sw128(base_off + 64)) = lo;
}

// 8 consecutive f32 -> hi-only tile: single 16B store
__device__ __forceinline__ void cvt_store8_hi(char* tile, uint32_t base_off,
                                              float4 a, float4 b) {
    uint4 hi;
    hi.x = pack2h(a.x, a.y);
    hi.y = pack2h(a.z, a.w);
    hi.z = pack2h(b.x, b.y);
    hi.w = pack2h(b.z, b.w);
    *(uint4*)(tile + sw128(base_off)) = hi;
}

// Pure hi x hi product: 2 MMAs over four chains.
__device__ __forceinline__ void mma_hh_x4(float* s00, float* s01,
                                          float* s10, float* s11,
                                          const uint32_t af[2][4],
                                          const uint32_t b0[2][4],
                                          const uint32_t b1[2][4]) {
#pragma unroll
    for (int p = 0; p < 2; p++) {
        mma_f16(s00, af[p], &b0[p][0]);
        mma_f16(s01, af[p], &b0[p][2]);
        mma_f16(s10, af[p], &b1[p][0]);
        mma_f16(s11, af[p], &b1[p][2]);
    }
}

// ===========================================================================
// Merged conversion pass.
// Linear grid: [0,4096) X tiles (hi-only), [4096,4352) Wq (full),
// [4352,4416) WkWw (full).
// ===========================================================================
__global__ void __launch_bounds__(256)
cvt_all_kernel(const float* __restrict__ X, const float* __restrict__ Wq,
               const float* __restrict__ Wk, const float* __restrict__ Ww)
{
    const int bid = blockIdx.x;
    const int tid = threadIdx.x;

    if (bid < 4096) {
        const int rowTile = bid >> 6, kStep = bid & 63;
        const float* srcb = X + (size_t)(rowTile * 128) * C_ + kStep * 32;
        char* dst = g_xext + ((size_t)rowTile * 64 + kStep) * 16384;
#pragma unroll
        for (int j = 0; j < 2; j++) {
            const int idx = tid + j * 256;          // 0..511
            const int r = idx >> 2, c8 = (idx & 3) * 8;
            const float* s = srcb + (size_t)r * C_ + c8;
            cvt_store8_hi(dst, (uint32_t)(r * 128 + c8 * 2),
                          *(const float4*)s, *(const float4*)(s + 4));
        }
    } else if (bid < 4352) {
        const int t = bid - 4096;
        const int nTile = t >> 6, kStep = t & 63;
        const float* srcb = Wq + (size_t)(nTile * 128) * C_ + kStep * 32;
        char* dst = g_wqext + ((size_t)nTile * 64 + kStep) * 16384;
#pragma unroll
        for (int j = 0; j < 2; j++) {
            const int idx = tid + j * 256;
            const int r = idx >> 2, c8 = (idx & 3) * 8;
            const float* s = srcb + (size_t)r * C_ + c8;
            cvt_store8(dst, (uint32_t)(r * 128 + c8 * 2),
                       *(const float4*)s, *(const float4*)(s + 4));
        }
    } else {
        const int kStep = bid - 4352;
        if (tid >= 192) return;                     // 48 rows * 4 chunks
        const int r = tid >> 2, c8 = (tid & 3) * 8;
        const float* s = (r < 32) ? (Wk + (size_t)r * C_ + kStep * 32 + c8)
                                  : (Ww + (size_t)(r - 32) * C_ + kStep * 32 + c8);
        char* dst = g_kwext + (size_t)kStep * 6144;
        cvt_store8(dst, (uint32_t)(r * 128 + c8 * 2),
                   *(const float4*)s, *(const float4*)(s + 4));
    }
}

// ===========================================================================
// Unified projection kernel. grid (9, 64):
//   nT in 0..7 : Q-proj, 64 output cols (nT*64..), writes g_qext (hi-only)
//   nT == 8    : K+W proj (48 cols from g_kwext), writes g_kext (hi) + g_w
// CTA: 128(m) x 64(n), 256 threads, 8 warps 4(m) x 2(n), warp tile 32x32.
// k=64 stages (2 sub-tiles), 2-buffer cp.async, 32 iterations, 2 CTAs/SM.
// Pure hi x hi product; W hi chunks only are copied.
// ===========================================================================
__global__ void __launch_bounds__(256, 2)
proj_mma_kernel()
{
    extern __shared__ char dsm_raw[];
    char* dsm = (char*)(((uintptr_t)dsm_raw + 1023) & ~(uintptr_t)1023);
    // stage buffer: X0(16K) X1(16K) W0(8K) W1(8K) = 48KB; two buffers.
    // (lo halves of W slots are holes, never touched.)

    const int tid  = threadIdx.x;
    const int wid  = tid >> 5;
    const int lane = tid & 31;
    const int nT    = blockIdx.x;           // 0..8
    const int mTile = blockIdx.y;           // 0..63
    const int m0 = (wid & 3) * 32;
    const int n0 = (wid >> 2) * 32;
    const bool iskw = (nT == 8);

    const char* xsrc = g_xext + (size_t)mTile * 64 * 16384;
    const char* wsrc = iskw ? g_kwext
                            : g_wqext + (size_t)(nT >> 1) * 64 * 16384 + (nT & 1) * 8192;
    const uint32_t wstep   = iskw ? 6144u : 16384u;  // bytes per k-step in gmem
    const int      wchunks = iskw ? 192 : 256;       // hi 16B chunks per k-step

    uint32_t sbase[2];
#pragma unroll
    for (int s = 0; s < 2; s++) sbase[s] = smem_u32(dsm + s * 49152);

    uint32_t aoff[2][2], boff[2][2];
    {
        const int arow = lane & 15, aseg = lane >> 4;
        const int brow = (lane & 7) + ((lane & 16) >> 1);
        const int bseg = (lane >> 3) & 1;
#pragma unroll
        for (int t = 0; t < 2; t++) {
#pragma unroll
            for (int ks = 0; ks < 2; ks++) {     // hi frags only, both sides
                aoff[t][ks] = sw128((uint32_t)((m0 + t * 16 + arow) * 128 +
                                               ks * 32 + aseg * 16));
                boff[t][ks] = 32768u + sw128((uint32_t)((n0 + t * 16 + brow) * 128 +
                                                        ks * 32 + bseg * 16));
            }
        }
    }

    // issue one k=64 stage (2 k-steps) into buffer bb; hi chunks only
    auto issue_stage = [&](int stage, int bb) {
        const uint32_t sb = sbase[bb];
#pragma unroll
        for (int t = 0; t < 2; t++) {
            const size_t ks = (size_t)(stage * 2 + t);
            // X: 512 hi chunks (128 rows x 4 chunks of 16B)
#pragma unroll
            for (int j = 0; j < 2; j++) {
                const int idx = tid + j * 256;
                const uint32_t off = sw128((uint32_t)((idx >> 2) * 128 + (idx & 3) * 16));
                cp16(sb + t * 16384u + off, xsrc + ks * 16384 + off);
            }
            // W: hi chunks only (wchunks of 16B)
            if (tid < wchunks) {
                const uint32_t off = sw128((uint32_t)((tid >> 2) * 128 + (tid & 3) * 16));
                cp16(sb + 32768u + t * 8192u + off, wsrc + ks * wstep + off);
            }
        }
    };

    // prologue: stage 0 -> buf 0
    issue_stage(0, 0);
    CP_COMMIT();

    float acc[2][4][4];
#pragma unroll
    for (int mt = 0; mt < 2; mt++)
#pragma unroll
        for (int nt = 0; nt < 4; nt++)
#pragma unroll
            for (int c = 0; c < 4; c++) acc[mt][nt][c] = 0.f;

#pragma unroll 1
    for (int it = 0; it < 32; it++) {
        CP_WAIT(0);          // stage it complete (only pending group)
        __syncthreads();     // all warps: data visible + prev compute retired
        if (it + 1 < 32) {
            issue_stage(it + 1, (it + 1) & 1);
            CP_COMMIT();
        }

        const uint32_t cb = sbase[it & 1];
#pragma unroll
        for (int t = 0; t < 2; t++) {
            const uint32_t xb = cb + (uint32_t)t * 16384u;
            const uint32_t wb = (uint32_t)t * 8192u;
            uint32_t bfr[2][2][4];
#pragma unroll
            for (int ntp = 0; ntp < 2; ntp++)
#pragma unroll
                for (int ks = 0; ks < 2; ks++)
                    ldsm4(bfr[ntp][ks], cb + wb + boff[ntp][ks]);

#pragma unroll
            for (int mt = 0; mt < 2; mt++) {
                uint32_t af[2][4];
#pragma unroll
                for (int ks = 0; ks < 2; ks++) ldsm4(af[ks], xb + aoff[mt][ks]);
                mma_hh_x4(acc[mt][0], acc[mt][1], acc[mt][2], acc[mt][3],
                          af, bfr[0], bfr[1]);
            }
        }
    }

    // epilogue
#pragma unroll
    for (int mt = 0; mt < 2; mt++)
#pragma unroll
        for (int rp = 0; rp < 2; rp++) {
            const int r = m0 + mt * 16 + (lane >> 2) + rp * 8;
#pragma unroll
            for (int nt = 0; nt < 4; nt++) {
                const int colL = n0 + nt * 8 + (lane & 3) * 2;
                const float v0 = acc[mt][nt][rp * 2];
                const float v1 = acc[mt][nt][rp * 2 + 1];
                if (!iskw) {
                    const int col = nT * 64 + colL;
                    const int head = col >> 5;
                    const int d = col & 31;
                    char* dst = g_qext + ((size_t)mTile * 16 + head) * 16384;
                    *(uint32_t*)(dst + sw128((uint32_t)(r * 128 + d * 2))) =
                        pack2h(v0, v1);                       // hi-only
                } else if (colL < 32) {
                    char* dst = g_kext + (size_t)mTile * 16384;
                    *(uint32_t*)(dst + sw128((uint32_t)(r * 128 + colL * 2))) =
                        pack2h(v0, v1);                       // hi-only
                } else if (colL < 48) {
                    *(float2*)(g_w + (size_t)(mTile * 128 + r) * H_ + (colL - 32)) =
                        make_float2(v0, v1);
                }
            }
        }
}

// ===========================================================================
// Fused scores+importance: out[b,q,k] = sum_h w[b,q,h]*relu(dot(q,k))
// CTA = 128(q) x 64(k), 256 threads, 8 warps 4(m)x2(n), 2 CTAs/SM.
// A = Q hi-only (streamed); B = K hi-only frags (resident).
// Product = q_hi * k_hi (2 MMAs/frag-pair).
// Q streamed 2 HEADS per stage (3 x 32KB ring footprint, 16KB copied).
// ===========================================================================
__global__ void __launch_bounds__(256, 2)
fused_mma_kernel(float* __restrict__ out)
{
    extern __shared__ char dsm_raw[];
    char* dsm = (char*)(((uintptr_t)dsm_raw + 1023) & ~(uintptr_t)1023);
    char* Ks   = dsm;                    // 8KB (64 rows)
    char* Qb   = dsm + 8192;             // 3 x 32KB (2 head tiles per stage)
    float* w_s = (float*)(dsm + 106496); // 8KB

    const int tid  = threadIdx.x;
    const int wid  = tid >> 5;
    const int lane = tid & 31;
    const int b  = blockIdx.z;
    const int kT = blockIdx.x;          // 0..63 (64-col k tiles)
    const int q0 = blockIdx.y * 128;
    const int k0 = kT * 64;
    const int m0 = (wid & 3) * 32;
    const int n0 = (wid >> 2) * 32;     // 0 or 32 within the 64-col slice

    const int qTile = b * 32 + blockIdx.y;
    const char* qsrc = g_qext + (size_t)qTile * 16 * 16384;
    const char* ksrc = g_kext + (size_t)(b * 32 + (kT >> 1)) * 16384 + (kT & 1) * 8192;
    const float* wsrc = g_w + (size_t)(b * T_ + q0) * H_;

    const uint32_t ksb = smem_u32(Ks);
    const uint32_t wsb_smem = smem_u32(w_s);
    uint32_t qbase[3];
#pragma unroll
    for (int s = 0; s < 3; s++) qbase[s] = smem_u32(Qb + s * 32768);

    // Q head-pair loader: 1024 hi chunks (2 heads x 128 rows x 4)
    auto load_qpair = [&](uint32_t qb, const char* src) {
#pragma unroll
        for (int j = 0; j < 4; j++) {
            const int idx = tid + j * 256;          // 0..1023
            const int rem = idx & 511;
            const uint32_t off = (uint32_t)(idx >> 9) * 16384u +
                                 sw128((uint32_t)((rem >> 2) * 128 + (rem & 3) * 16));
            cp16(qb + off, src + off);
        }
    };

    // prologue: G0 = {K, w, headpair 0}, G1 = {headpair 1}
#pragma unroll
    for (int j = 0; j < 2; j++) {
        uint32_t off = (uint32_t)(tid + j * 256) * 16;
        cp16(ksb + off, ksrc + off);
        cp16(wsb_smem + off, (const char*)wsrc + off);
    }
    load_qpair(qbase[0], qsrc);
    CP_COMMIT();
    load_qpair(qbase[1], qsrc + 32768);
    CP_COMMIT();

    uint32_t aoff[2][2];
    uint32_t baddr[2][2];
    {
        const int arow = lane & 15, aseg = lane >> 4;
        const int brow = (lane & 7) + ((lane & 16) >> 1);
        const int bseg = (lane >> 3) & 1;
#pragma unroll
        for (int t = 0; t < 2; t++) {
#pragma unroll
            for (int ks = 0; ks < 2; ks++) {     // hi frags only, both sides
                aoff[t][ks] = sw128((uint32_t)((m0 + t * 16 + arow) * 128 +
                                               ks * 32 + aseg * 16));
                baddr[t][ks] = ksb + sw128((uint32_t)((n0 + t * 16 + brow) * 128 +
                                                      ks * 32 + bseg * 16));
            }
        }
    }

    float acc[2][4][4];
#pragma unroll
    for (int mt = 0; mt < 2; mt++)
#pragma unroll
        for (int nt = 0; nt < 4; nt++)
#pragma unroll
            for (int c = 0; c < 4; c++) acc[mt][nt][c] = 0.f;

    CP_WAIT(1);       // G0 done: K, w, headpair 0
    __syncthreads();

    // K hi fragments register-resident (this warp's 32 n-cols)
    uint32_t bfr[2][2][4];
#pragma unroll
    for (int ntp = 0; ntp < 2; ntp++)
#pragma unroll
        for (int ks = 0; ks < 2; ks++) ldsm4(bfr[ntp][ks], baddr[ntp][ks]);

    const int wrow0 = m0 + (lane >> 2);

#pragma unroll 1
    for (int p = 0; p < H_ / 2; p++) {      // head pairs
        if (p > 0) {
            if (p == H_ / 2 - 1) CP_WAIT(0); else CP_WAIT(1);
            __syncthreads();
        }
        if (p + 2 < H_ / 2)
            load_qpair(qbase[(p + 2) % 3], qsrc + (size_t)(p + 2) * 32768);
        CP_COMMIT();

        const uint32_t qb = qbase[p % 3];
#pragma unroll
        for (int hh = 0; hh < 2; hh++) {
            const int h = p * 2 + hh;
            const uint32_t qbh = qb + (uint32_t)hh * 16384u;
#pragma unroll
            for (int mt = 0; mt < 2; mt++) {
                uint32_t af[2][4];
#pragma unroll
                for (int ks = 0; ks < 2; ks++) ldsm4(af[ks], qbh + aoff[mt][ks]);

                const float wv0 = w_s[(wrow0 + mt * 16) * H_ + h];
                const float wv1 = w_s[(wrow0 + mt * 16 + 8) * H_ + h];

                float s[2][2][4];
#pragma unroll
                for (int ntp = 0; ntp < 2; ntp++)
#pragma unroll
                    for (int q = 0; q < 2; q++)
#pragma unroll
                        for (int c = 0; c < 4; c++) s[ntp][q][c] = 0.f;

                mma_hh_x4(s[0][0], s[0][1], s[1][0], s[1][1],
                          af, bfr[0], bfr[1]);

#pragma unroll
                for (int ntp = 0; ntp < 2; ntp++)
#pragma unroll
                    for (int q = 0; q < 2; q++) {
                        float* a = acc[mt][ntp * 2 + q];
                        const float* sv = s[ntp][q];
                        a[0] += wv0 * fmaxf(sv[0], 0.f);
                        a[1] += wv0 * fmaxf(sv[1], 0.f);
                        a[2] += wv1 * fmaxf(sv[2], 0.f);
                        a[3] += wv1 * fmaxf(sv[3], 0.f);
                    }
            }
        }
    }

    // epilogue
#pragma unroll
    for (int mt = 0; mt < 2; mt++)
#pragma unroll
        for (int rp = 0; rp < 2; rp++) {
            const int row = q0 + m0 + mt * 16 + (lane >> 2) + rp * 8;
            float* op = out + (size_t)(b * T_ + row) * T_ + k0 + n0 + (lane & 3) * 2;
#pragma unroll
            for (int nt = 0; nt < 4; nt++)
                *(float2*)(op + nt * 8) =
                    make_float2(acc[mt][nt][rp * 2], acc[mt][nt][rp * 2 + 1]);
        }
}

// ===========================================================================
extern "C" void kernel_launch(void* const* d_in, const int* in_sizes, int n_in,
                              void* d_out, int out_size)
{
    (void)in_sizes; (void)n_in; (void)out_size;
    const float* x  = (const float*)d_in[0];
    const float* Wq = (const float*)d_in[1];
    const float* Wk = (const float*)d_in[2];
    const float* Ww = (const float*)d_in[3];
    float* out = (float*)d_out;

    static bool attr_done = false;
    if (!attr_done) {
        cudaFuncSetAttribute(proj_mma_kernel,
                             cudaFuncAttributeMaxDynamicSharedMemorySize, 99328);
        cudaFuncSetAttribute(fused_mma_kernel,
                             cudaFuncAttributeMaxDynamicSharedMemorySize, 115712);
        attr_done = true;
    }

    cvt_all_kernel<<<4416, 256>>>(x, Wq, Wk, Ww);
    proj_mma_kernel<<<dim3(9, 64), 256, 99328>>>();
    fused_mma_kernel<<<dim3(T_ / 64, T_ / 128, B_), 256, 115712>>>(out);
}

// round 15
// speedup vs baseline: 7.1306x; 1.0400x over previous
#include <cuda_runtime.h>
#include <cuda_fp16.h>
#include <cstdint>

// Problem constants
#define B_ 2
#define T_ 4096
#define C_ 2048
#define H_ 16
#define D_ 32

// ---------------------------------------------------------------------------
// Ext-fp16 tile formats (sw128-swizzled, 128B physical rows):
//  FULL tile (16KB/128rows): row r, ext col c in [0,64): c<32 = hi of d=c,
//    c>=32 = lo of d=c-32, at byte sw128(r*128 + c*2).
//  HI-ONLY tile: same addressing, lo half never written/read (holes).
// All products pure hi x hi (2 MMAs per 16x16 frag-pair); dropped terms
// are each ~2^-12 relative and compose ~RSS (measured rounds 11-14).
// ---------------------------------------------------------------------------
__device__ __align__(1024) char g_xext [(size_t)64 * 64 * 16384];  // [rowTile][kStep] hi-only
__device__ __align__(1024) char g_wqext[(size_t)4  * 64 * 16384];  // [nTile][kStep] full (hi read)
__device__ __align__(1024) char g_kwext[(size_t)64 * 6144];        // [kStep] 48 rows, full (hi read)
__device__ __align__(1024) char g_qext [(size_t)64 * 16 * 16384];  // [qTile][head] hi-only
__device__ __align__(1024) char g_kext [(size_t)64 * 16384];       // [kTile] hi-only
__device__ __align__(1024) float g_w[(size_t)B_ * T_ * H_];        // [8192][16]

// ===========================================================================
// Helpers (base sm_103-safe: ldmatrix + mma.sync + cp.async)
// ===========================================================================
__device__ __forceinline__ uint32_t smem_u32(const void* p) {
    uint32_t a;
    asm("{ .reg .u64 t; cvta.to.shared.u64 t, %1; cvt.u32.u64 %0, t; }"
        : "=r"(a) : "l"(p));
    return a;
}

__device__ __forceinline__ uint32_t sw128(uint32_t o) { return o ^ ((o >> 3) & 0x70); }

__device__ __forceinline__ void ldsm4(uint32_t* r, uint32_t a) {
    asm volatile("ldmatrix.sync.aligned.m8n8.x4.shared.b16 {%0,%1,%2,%3}, [%4];"
                 : "=r"(r[0]), "=r"(r[1]), "=r"(r[2]), "=r"(r[3]) : "r"(a));
}

__device__ __forceinline__ void mma_f16(float* d, const uint32_t* a, const uint32_t* b) {
    asm volatile(
        "mma.sync.aligned.m16n8k16.row.col.f32.f16.f16.f32 "
        "{%0,%1,%2,%3}, {%4,%5,%6,%7}, {%8,%9}, {%0,%1,%2,%3};"
        : "+f"(d[0]), "+f"(d[1]), "+f"(d[2]), "+f"(d[3])
        : "r"(a[0]), "r"(a[1]), "r"(a[2]), "r"(a[3]), "r"(b[0]), "r"(b[1]));
}

// Non-accumulating variant: d = a*b + 0 (c = constant zeros, no init MOVs).
__device__ __forceinline__ void mma_f16_z(float* d, const uint32_t* a, const uint32_t* b) {
    asm volatile(
        "mma.sync.aligned.m16n8k16.row.col.f32.f16.f16.f32 "
        "{%0,%1,%2,%3}, {%4,%5,%6,%7}, {%8,%9}, {%10,%10,%10,%10};"
        : "=f"(d[0]), "=f"(d[1]), "=f"(d[2]), "=f"(d[3])
        : "r"(a[0]), "r"(a[1]), "r"(a[2]), "r"(a[3]), "r"(b[0]), "r"(b[1]),
          "f"(0.f));
}

__device__ __forceinline__ void cp16(uint32_t s, const void* g) {
    asm volatile("cp.async.cg.shared.global [%0], [%1], 16;" :: "r"(s), "l"(g));
}
#define CP_COMMIT() asm volatile("cp.async.commit_group;" ::: "memory")
#define CP_WAIT(n)  asm volatile("cp.async.wait_group %0;" :: "n"(n) : "memory")

__device__ __forceinline__ uint32_t pack2h(float x, float y) {
    __half h0 = __float2half_rn(x), h1 = __float2half_rn(y);
    return ((uint32_t)__half_as_ushort(h1) << 16) | (uint32_t)__half_as_ushort(h0);
}

// split two f32 into packed fp16 hi-pair and fp16 lo-pair (lo = residual)
__device__ __forceinline__ void split2(float v0, float v1, uint32_t& hi, uint32_t& lo) {
    __half h0 = __float2half_rn(v0), h1 = __float2half_rn(v1);
    hi = ((uint32_t)__half_as_ushort(h1) << 16) | (uint32_t)__half_as_ushort(h0);
    __half g0 = __float2half_rn(v0 - __half2float(h0));
    __half g1 = __float2half_rn(v1 - __half2float(h1));
    lo = ((uint32_t)__half_as_ushort(g1) << 16) | (uint32_t)__half_as_ushort(g0);
}

// 8 consecutive f32 -> full tile: 16B hi + 16B lo stores
__device__ __forceinline__ void cvt_store8(char* tile, uint32_t base_off,
                                           float4 a, float4 b) {
    uint4 hi, lo;
    split2(a.x, a.y, hi.x, lo.x);
    split2(a.z, a.w, hi.y, lo.y);
    split2(b.x, b.y, hi.z, lo.z);
    split2(b.z, b.w, hi.w, lo.w);
    *(uint4*)(tile + sw128(base_off))      = hi;
    *(uint4*)(tile + sw128(base_off + 64)) = lo;
}

// 8 consecutive f32 -> hi-only tile: single 16B store
__device__ __forceinline__ void cvt_store8_hi(char* tile, uint32_t base_off,
                                              float4 a, float4 b) {
    uint4 hi;
    hi.x = pack2h(a.x, a.y);
    hi.y = pack2h(a.z, a.w);
    hi.z = pack2h(b.x, b.y);
    hi.w = pack2h(b.z, b.w);
    *(uint4*)(tile + sw128(base_off)) = hi;
}

// Pure hi x hi product accumulating into existing acc: 2 MMAs over four chains.
__device__ __forceinline__ void mma_hh_x4(float* s00, float* s01,
                                          float* s10, float* s11,
                                          const uint32_t af[2][4],
                                          const uint32_t b0[2][4],
                                          const uint32_t b1[2][4]) {
#pragma unroll
    for (int p = 0; p < 2; p++) {
        mma_f16(s00, af[p], &b0[p][0]);
        mma_f16(s01, af[p], &b0[p][2]);
        mma_f16(s10, af[p], &b1[p][0]);
        mma_f16(s11, af[p], &b1[p][2]);
    }
}

// Same but FIRST step writes fresh (zero-c) — no accumulator init needed.
__device__ __forceinline__ void mma_hh_x4_z(float* s00, float* s01,
                                            float* s10, float* s11,
                                            const uint32_t af[2][4],
                                            const uint32_t b0[2][4],
                                            const uint32_t b1[2][4]) {
    mma_f16_z(s00, af[0], &b0[0][0]);
    mma_f16_z(s01, af[0], &b0[0][2]);
    mma_f16_z(s10, af[0], &b1[0][0]);
    mma_f16_z(s11, af[0], &b1[0][2]);
    mma_f16(s00, af[1], &b0[1][0]);
    mma_f16(s01, af[1], &b0[1][2]);
    mma_f16(s10, af[1], &b1[1][0]);
    mma_f16(s11, af[1], &b1[1][2]);
}

// ===========================================================================
// Merged conversion pass.
// Linear grid: [0,4096) X tiles (hi-only), [4096,4352) Wq (full),
// [4352,4416) WkWw (full).
// ===========================================================================
__global__ void __launch_bounds__(256)
cvt_all_kernel(const float* __restrict__ X, const float* __restrict__ Wq,
               const float* __restrict__ Wk, const float* __restrict__ Ww)
{
    const int bid = blockIdx.x;
    const int tid = threadIdx.x;

    if (bid < 4096) {
        const int rowTile = bid >> 6, kStep = bid & 63;
        const float* srcb = X + (size_t)(rowTile * 128) * C_ + kStep * 32;
        char* dst = g_xext + ((size_t)rowTile * 64 + kStep) * 16384;
#pragma unroll
        for (int j = 0; j < 2; j++) {
            const int idx = tid + j * 256;          // 0..511
            const int r = idx >> 2, c8 = (idx & 3) * 8;
            const float* s = srcb + (size_t)r * C_ + c8;
            cvt_store8_hi(dst, (uint32_t)(r * 128 + c8 * 2),
                          *(const float4*)s, *(const float4*)(s + 4));
        }
    } else if (bid < 4352) {
        const int t = bid - 4096;
        const int nTile = t >> 6, kStep = t & 63;
        const float* srcb = Wq + (size_t)(nTile * 128) * C_ + kStep * 32;
        char* dst = g_wqext + ((size_t)nTile * 64 + kStep) * 16384;
#pragma unroll
        for (int j = 0; j < 2; j++) {
            const int idx = tid + j * 256;
            const int r = idx >> 2, c8 = (idx & 3) * 8;
            const float* s = srcb + (size_t)r * C_ + c8;
            cvt_store8(dst, (uint32_t)(r * 128 + c8 * 2),
                       *(const float4*)s, *(const float4*)(s + 4));
        }
    } else {
        const int kStep = bid - 4352;
        if (tid >= 192) return;                     // 48 rows * 4 chunks
        const int r = tid >> 2, c8 = (tid & 3) * 8;
        const float* s = (r < 32) ? (Wk + (size_t)r * C_ + kStep * 32 + c8)
                                  : (Ww + (size_t)(r - 32) * C_ + kStep * 32 + c8);
        char* dst = g_kwext + (size_t)kStep * 6144;
        cvt_store8(dst, (uint32_t)(r * 128 + c8 * 2),
                   *(const float4*)s, *(const float4*)(s + 4));
    }
}

// ===========================================================================
// Unified projection kernel. grid (9, 64):
//   nT in 0..7 : Q-proj, 64 output cols (nT*64..), writes g_qext (hi-only)
//   nT == 8    : K+W proj (48 cols from g_kwext), writes g_kext (hi) + g_w
// CTA: 128(m) x 64(n), 256 threads, 8 warps 4(m) x 2(n), warp tile 32x32.
// 4-deep k=32 pipeline (4 x 24KB buffers, 3 cp groups in flight), 64 iters,
// 2 CTAs/SM.  Pure hi x hi; hi chunks only copied.
// ===========================================================================
__global__ void __launch_bounds__(256, 2)
proj_mma_kernel()
{
    extern __shared__ char dsm_raw[];
    char* dsm = (char*)(((uintptr_t)dsm_raw + 1023) & ~(uintptr_t)1023);
    // stage buffer: X slot 16KB (hi holes) + W slot 8KB (hi holes) = 24KB; x4.

    const int tid  = threadIdx.x;
    const int wid  = tid >> 5;
    const int lane = tid & 31;
    const int nT    = blockIdx.x;           // 0..8
    const int mTile = blockIdx.y;           // 0..63
    const int m0 = (wid & 3) * 32;
    const int n0 = (wid >> 2) * 32;
    const bool iskw = (nT == 8);

    const char* xsrc = g_xext + (size_t)mTile * 64 * 16384;
    const char* wsrc = iskw ? g_kwext
                            : g_wqext + (size_t)(nT >> 1) * 64 * 16384 + (nT & 1) * 8192;
    const uint32_t wstep   = iskw ? 6144u : 16384u;  // bytes per k-step in gmem
    const int      wchunks = iskw ? 192 : 256;       // hi 16B chunks per k-step

    uint32_t sbase[4];
#pragma unroll
    for (int s = 0; s < 4; s++) sbase[s] = smem_u32(dsm + s * 24576);

    uint32_t aoff[2][2], boff[2][2];
    {
        const int arow = lane & 15, aseg = lane >> 4;
        const int brow = (lane & 7) + ((lane & 16) >> 1);
        const int bseg = (lane >> 3) & 1;
#pragma unroll
        for (int t = 0; t < 2; t++) {
#pragma unroll
            for (int ks = 0; ks < 2; ks++) {     // hi frags only, both sides
                aoff[t][ks] = sw128((uint32_t)((m0 + t * 16 + arow) * 128 +
                                               ks * 32 + aseg * 16));
                boff[t][ks] = 16384u + sw128((uint32_t)((n0 + t * 16 + brow) * 128 +
                                                        ks * 32 + bseg * 16));
            }
        }
    }

    // issue one k=32 stage into buffer stage&3; hi chunks only
    auto issue_stage = [&](int stage) {
        const uint32_t sb = sbase[stage & 3];
        const size_t ks = (size_t)stage;
        // X: 512 hi chunks (128 rows x 4 chunks of 16B)
#pragma unroll
        for (int j = 0; j < 2; j++) {
            const int idx = tid + j * 256;
            const uint32_t off = sw128((uint32_t)((idx >> 2) * 128 + (idx & 3) * 16));
            cp16(sb + off, xsrc + ks * 16384 + off);
        }
        // W: hi chunks only
        if (tid < wchunks) {
            const uint32_t off = sw128((uint32_t)((tid >> 2) * 128 + (tid & 3) * 16));
            cp16(sb + 16384u + off, wsrc + ks * wstep + off);
        }
    };

    // prologue: stages 0,1,2 (three groups in flight)
#pragma unroll
    for (int s = 0; s < 3; s++) {
        issue_stage(s);
        CP_COMMIT();
    }

    float acc[2][4][4];
#pragma unroll
    for (int mt = 0; mt < 2; mt++)
#pragma unroll
        for (int nt = 0; nt < 4; nt++)
#pragma unroll
            for (int c = 0; c < 4; c++) acc[mt][nt][c] = 0.f;

#pragma unroll 1
    for (int it = 0; it < 64; it++) {
        CP_WAIT(2);          // all but newest 2 groups done => stage it done
        __syncthreads();     // data visible + all warps done with buf (it+3)&3
        if (it + 3 < 64) issue_stage(it + 3);
        CP_COMMIT();         // unconditional: keeps group count uniform

        const uint32_t cb = sbase[it & 3];
        uint32_t bfr[2][2][4];
#pragma unroll
        for (int ntp = 0; ntp < 2; ntp++)
#pragma unroll
            for (int ks = 0; ks < 2; ks++)
                ldsm4(bfr[ntp][ks], cb + boff[ntp][ks]);

#pragma unroll
        for (int mt = 0; mt < 2; mt++) {
            uint32_t af[2][4];
#pragma unroll
            for (int ks = 0; ks < 2; ks++) ldsm4(af[ks], cb + aoff[mt][ks]);
            mma_hh_x4(acc[mt][0], acc[mt][1], acc[mt][2], acc[mt][3],
                      af, bfr[0], bfr[1]);
        }
    }

    // epilogue
#pragma unroll
    for (int mt = 0; mt < 2; mt++)
#pragma unroll
        for (int rp = 0; rp < 2; rp++) {
            const int r = m0 + mt * 16 + (lane >> 2) + rp * 8;
#pragma unroll
            for (int nt = 0; nt < 4; nt++) {
                const int colL = n0 + nt * 8 + (lane & 3) * 2;
                const float v0 = acc[mt][nt][rp * 2];
                const float v1 = acc[mt][nt][rp * 2 + 1];
                if (!iskw) {
                    const int col = nT * 64 + colL;
                    const int head = col >> 5;
                    const int d = col & 31;
                    char* dst = g_qext + ((size_t)mTile * 16 + head) * 16384;
                    *(uint32_t*)(dst + sw128((uint32_t)(r * 128 + d * 2))) =
                        pack2h(v0, v1);                       // hi-only
                } else if (colL < 32) {
                    char* dst = g_kext + (size_t)mTile * 16384;
                    *(uint32_t*)(dst + sw128((uint32_t)(r * 128 + colL * 2))) =
                        pack2h(v0, v1);                       // hi-only
                } else if (colL < 48) {
                    *(float2*)(g_w + (size_t)(mTile * 128 + r) * H_ + (colL - 32)) =
                        make_float2(v0, v1);
                }
            }
        }
}

// ===========================================================================
// Fused scores+importance: out[b,q,k] = sum_h w[b,q,h]*relu(dot(q,k))
// CTA = 128(q) x 64(k), 256 threads, 8 warps 4(m)x2(n), 2 CTAs/SM.
// A = Q hi-only (streamed); B = K hi-only frags (resident).
// Product = q_hi * k_hi (2 MMAs/frag-pair, first non-accumulating).
// Q streamed 2 HEADS per stage (3 x 32KB ring footprint, 16KB copied).
// ===========================================================================
__global__ void __launch_bounds__(256, 2)
fused_mma_kernel(float* __restrict__ out)
{
    extern __shared__ char dsm_raw[];
    char* dsm = (char*)(((uintptr_t)dsm_raw + 1023) & ~(uintptr_t)1023);
    char* Ks   = dsm;                    // 8KB (64 rows)
    char* Qb   = dsm + 8192;             // 3 x 32KB (2 head tiles per stage)
    float* w_s = (float*)(dsm + 106496); // 8KB

    const int tid  = threadIdx.x;
    const int wid  = tid >> 5;
    const int lane = tid & 31;
    const int b  = blockIdx.z;
    const int kT = blockIdx.x;          // 0..63 (64-col k tiles)
    const int q0 = blockIdx.y * 128;
    const int k0 = kT * 64;
    const int m0 = (wid & 3) * 32;
    const int n0 = (wid >> 2) * 32;     // 0 or 32 within the 64-col slice

    const int qTile = b * 32 + blockIdx.y;
    const char* qsrc = g_qext + (size_t)qTile * 16 * 16384;
    const char* ksrc = g_kext + (size_t)(b * 32 + (kT >> 1)) * 16384 + (kT & 1) * 8192;
    const float* wsrc = g_w + (size_t)(b * T_ + q0) * H_;

    const uint32_t ksb = smem_u32(Ks);
    const uint32_t wsb_smem = smem_u32(w_s);
    uint32_t qbase[3];
#pragma unroll
    for (int s = 0; s < 3; s++) qbase[s] = smem_u32(Qb + s * 32768);

    // Q head-pair loader: 1024 hi chunks (2 heads x 128 rows x 4)
    auto load_qpair = [&](uint32_t qb, const char* src) {
#pragma unroll
        for (int j = 0; j < 4; j++) {
            const int idx = tid + j * 256;          // 0..1023
            const int rem = idx & 511;
            const uint32_t off = (uint32_t)(idx >> 9) * 16384u +
                                 sw128((uint32_t)((rem >> 2) * 128 + (rem & 3) * 16));
            cp16(qb + off, src + off);
        }
    };

    // prologue: G0 = {K, w, headpair 0}, G1 = {headpair 1}
#pragma unroll
    for (int j = 0; j < 2; j++) {
        uint32_t off = (uint32_t)(tid + j * 256) * 16;
        cp16(ksb + off, ksrc + off);
        cp16(wsb_smem + off, (const char*)wsrc + off);
    }
    load_qpair(qbase[0], qsrc);
    CP_COMMIT();
    load_qpair(qbase[1], qsrc + 32768);
    CP_COMMIT();

    uint32_t aoff[2][2];
    uint32_t baddr[2][2];
    {
        const int arow = lane & 15, aseg = lane >> 4;
        const int brow = (lane & 7) + ((lane & 16) >> 1);
        const int bseg = (lane >> 3) & 1;
#pragma unroll
        for (int t = 0; t < 2; t++) {
#pragma unroll
            for (int ks = 0; ks < 2; ks++) {     // hi frags only, both sides
                aoff[t][ks] = sw128((uint32_t)((m0 + t * 16 + arow) * 128 +
                                               ks * 32 + aseg * 16));
                baddr[t][ks] = ksb + sw128((uint32_t)((n0 + t * 16 + brow) * 128 +
                                                      ks * 32 + bseg * 16));
            }
        }
    }

    float acc[2][4][4];
#pragma unroll
    for (int mt = 0; mt < 2; mt++)
#pragma unroll
        for (int nt = 0; nt < 4; nt++)
#pragma unroll
            for (int c = 0; c < 4; c++) acc[mt][nt][c] = 0.f;

    CP_WAIT(1);       // G0 done: K, w, headpair 0
    __syncthreads();

    // K hi fragments register-resident (this warp's 32 n-cols)
    uint32_t bfr[2][2][4];
#pragma unroll
    for (int ntp = 0; ntp < 2; ntp++)
#pragma unroll
        for (int ks = 0; ks < 2; ks++) ldsm4(bfr[ntp][ks], baddr[ntp][ks]);

    const int wrow0 = m0 + (lane >> 2);

#pragma unroll 1
    for (int p = 0; p < H_ / 2; p++) {      // head pairs
        if (p > 0) {
            if (p == H_ / 2 - 1) CP_WAIT(0); else CP_WAIT(1);
            __syncthreads();
        }
        if (p + 2 < H_ / 2)
            load_qpair(qbase[(p + 2) % 3], qsrc + (size_t)(p + 2) * 32768);
        CP_COMMIT();

        const uint32_t qb = qbase[p % 3];
#pragma unroll
        for (int hh = 0; hh < 2; hh++) {
            const int h = p * 2 + hh;
            const uint32_t qbh = qb + (uint32_t)hh * 16384u;
#pragma unroll
            for (int mt = 0; mt < 2; mt++) {
                uint32_t af[2][4];
#pragma unroll
                for (int ks = 0; ks < 2; ks++) ldsm4(af[ks], qbh + aoff[mt][ks]);

                const float wv0 = w_s[(wrow0 + mt * 16) * H_ + h];
                const float wv1 = w_s[(wrow0 + mt * 16 + 8) * H_ + h];

                float s[2][2][4];
                mma_hh_x4_z(s[0][0], s[0][1], s[1][0], s[1][1],
                            af, bfr[0], bfr[1]);

#pragma unroll
                for (int ntp = 0; ntp < 2; ntp++)
#pragma unroll
                    for (int q = 0; q < 2; q++) {
                        float* a = acc[mt][ntp * 2 + q];
                        const float* sv = s[ntp][q];
                        a[0] += wv0 * fmaxf(sv[0], 0.f);
                        a[1] += wv0 * fmaxf(sv[1], 0.f);
                        a[2] += wv1 * fmaxf(sv[2], 0.f);
                        a[3] += wv1 * fmaxf(sv[3], 0.f);
                    }
            }
        }
    }

    // epilogue
#pragma unroll
    for (int mt = 0; mt < 2; mt++)
#pragma unroll
        for (int rp = 0; rp < 2; rp++) {
            const int row = q0 + m0 + mt * 16 + (lane >> 2) + rp * 8;
            float* op = out + (size_t)(b * T_ + row) * T_ + k0 + n0 + (lane & 3) * 2;
#pragma unroll
            for (int nt = 0; nt < 4; nt++)
                *(float2*)(op + nt * 8) =
                    make_float2(acc[mt][nt][rp * 2], acc[mt][nt][rp * 2 + 1]);
        }
}

// ===========================================================================
extern "C" void kernel_launch(void* const* d_in, const int* in_sizes, int n_in,
                              void* d_out, int out_size)
{
    (void)in_sizes; (void)n_in; (void)out_size;
    const float* x  = (const float*)d_in[0];
    const float* Wq = (const float*)d_in[1];
    const float* Wk = (const float*)d_in[2];
    const float* Ww = (const float*)d_in[3];
    float* out = (float*)d_out;

    static bool attr_done = false;
    if (!attr_done) {
        cudaFuncSetAttribute(proj_mma_kernel,
                             cudaFuncAttributeMaxDynamicSharedMemorySize, 99328);
        cudaFuncSetAttribute(fused_mma_kernel,
                             cudaFuncAttributeMaxDynamicSharedMemorySize, 115712);
        attr_done = true;
    }

    cvt_all_kernel<<<4416, 256>>>(x, Wq, Wk, Ww);
    proj_mma_kernel<<<dim3(9, 64), 256, 99328>>>();
    fused_mma_kernel<<<dim3(T_ / 64, T_ / 128, B_), 256, 115712>>>(out);
}

// round 16
// speedup vs baseline: 7.3210x; 1.0267x over previous
#include <cuda_runtime.h>
#include <cuda_fp16.h>
#include <cstdint>

// Problem constants
#define B_ 2
#define T_ 4096
#define C_ 2048
#define H_ 16
#define D_ 32

// ---------------------------------------------------------------------------
// Ext-fp16 tile formats (sw128-swizzled, 128B physical rows):
//  FULL tile (16KB/128rows): row r, ext col c in [0,64): c<32 = hi of d=c,
//    c>=32 = lo of d=c-32, at byte sw128(r*128 + c*2).
//  HI-ONLY tile: same addressing, lo half never written/read (holes).
// All products pure hi x hi (2 MMAs per 16x16 frag-pair); dropped terms
// are each ~2^-12 relative and compose ~RSS (measured rounds 11-14).
// ---------------------------------------------------------------------------
__device__ __align__(1024) char g_xext [(size_t)64 * 64 * 16384];  // [rowTile][kStep] hi-only
__device__ __align__(1024) char g_wqext[(size_t)4  * 64 * 16384];  // [nTile][kStep] full (hi read)
__device__ __align__(1024) char g_kwext[(size_t)64 * 6144];        // [kStep] 48 rows, full (hi read)
__device__ __align__(1024) char g_qext [(size_t)64 * 16 * 16384];  // [qTile][head] hi-only
__device__ __align__(1024) char g_kext [(size_t)64 * 16384];       // [kTile] hi-only
__device__ __align__(1024) float g_w[(size_t)B_ * T_ * H_];        // [8192][16]

// ===========================================================================
// Helpers (base sm_103-safe: ldmatrix + mma.sync + cp.async)
// ===========================================================================
__device__ __forceinline__ uint32_t smem_u32(const void* p) {
    uint32_t a;
    asm("{ .reg .u64 t; cvta.to.shared.u64 t, %1; cvt.u32.u64 %0, t; }"
        : "=r"(a) : "l"(p));
    return a;
}

__device__ __forceinline__ uint32_t sw128(uint32_t o) { return o ^ ((o >> 3) & 0x70); }

__device__ __forceinline__ void ldsm4(uint32_t* r, uint32_t a) {
    asm volatile("ldmatrix.sync.aligned.m8n8.x4.shared.b16 {%0,%1,%2,%3}, [%4];"
                 : "=r"(r[0]), "=r"(r[1]), "=r"(r[2]), "=r"(r[3]) : "r"(a));
}

__device__ __forceinline__ void mma_f16(float* d, const uint32_t* a, const uint32_t* b) {
    asm volatile(
        "mma.sync.aligned.m16n8k16.row.col.f32.f16.f16.f32 "
        "{%0,%1,%2,%3}, {%4,%5,%6,%7}, {%8,%9}, {%0,%1,%2,%3};"
        : "+f"(d[0]), "+f"(d[1]), "+f"(d[2]), "+f"(d[3])
        : "r"(a[0]), "r"(a[1]), "r"(a[2]), "r"(a[3]), "r"(b[0]), "r"(b[1]));
}

// Non-accumulating variant: d = a*b + 0 (c = constant zeros, no init MOVs).
__device__ __forceinline__ void mma_f16_z(float* d, const uint32_t* a, const uint32_t* b) {
    asm volatile(
        "mma.sync.aligned.m16n8k16.row.col.f32.f16.f16.f32 "
        "{%0,%1,%2,%3}, {%4,%5,%6,%7}, {%8,%9}, {%10,%10,%10,%10};"
        : "=f"(d[0]), "=f"(d[1]), "=f"(d[2]), "=f"(d[3])
        : "r"(a[0]), "r"(a[1]), "r"(a[2]), "r"(a[3]), "r"(b[0]), "r"(b[1]),
          "f"(0.f));
}

__device__ __forceinline__ void cp16(uint32_t s, const void* g) {
    asm volatile("cp.async.cg.shared.global [%0], [%1], 16;" :: "r"(s), "l"(g));
}
#define CP_COMMIT() asm volatile("cp.async.commit_group;" ::: "memory")
#define CP_WAIT(n)  asm volatile("cp.async.wait_group %0;" :: "n"(n) : "memory")

__device__ __forceinline__ uint32_t pack2h(float x, float y) {
    __half h0 = __float2half_rn(x), h1 = __float2half_rn(y);
    return ((uint32_t)__half_as_ushort(h1) << 16) | (uint32_t)__half_as_ushort(h0);
}

// split two f32 into packed fp16 hi-pair and fp16 lo-pair (lo = residual)
__device__ __forceinline__ void split2(float v0, float v1, uint32_t& hi, uint32_t& lo) {
    __half h0 = __float2half_rn(v0), h1 = __float2half_rn(v1);
    hi = ((uint32_t)__half_as_ushort(h1) << 16) | (uint32_t)__half_as_ushort(h0);
    __half g0 = __float2half_rn(v0 - __half2float(h0));
    __half g1 = __float2half_rn(v1 - __half2float(h1));
    lo = ((uint32_t)__half_as_ushort(g1) << 16) | (uint32_t)__half_as_ushort(g0);
}

// 8 consecutive f32 -> full tile: 16B hi + 16B lo stores
__device__ __forceinline__ void cvt_store8(char* tile, uint32_t base_off,
                                           float4 a, float4 b) {
    uint4 hi, lo;
    split2(a.x, a.y, hi.x, lo.x);
    split2(a.z, a.w, hi.y, lo.y);
    split2(b.x, b.y, hi.z, lo.z);
    split2(b.z, b.w, hi.w, lo.w);
    *(uint4*)(tile + sw128(base_off))      = hi;
    *(uint4*)(tile + sw128(base_off + 64)) = lo;
}

// 8 consecutive f32 -> hi-only tile: single 16B store
__device__ __forceinline__ void cvt_store8_hi(char* tile, uint32_t base_off,
                                              float4 a, float4 b) {
    uint4 hi;
    hi.x = pack2h(a.x, a.y);
    hi.y = pack2h(a.z, a.w);
    hi.z = pack2h(b.x, b.y);
    hi.w = pack2h(b.z, b.w);
    *(uint4*)(tile + sw128(base_off)) = hi;
}

// Pure hi x hi product accumulating into existing acc: 2 MMAs over four chains.
__device__ __forceinline__ void mma_hh_x4(float* s00, float* s01,
                                          float* s10, float* s11,
                                          const uint32_t af[2][4],
                                          const uint32_t b0[2][4],
                                          const uint32_t b1[2][4]) {
#pragma unroll
    for (int p = 0; p < 2; p++) {
        mma_f16(s00, af[p], &b0[p][0]);
        mma_f16(s01, af[p], &b0[p][2]);
        mma_f16(s10, af[p], &b1[p][0]);
        mma_f16(s11, af[p], &b1[p][2]);
    }
}

// Same but FIRST step writes fresh (zero-c) — no accumulator init needed.
__device__ __forceinline__ void mma_hh_x4_z(float* s00, float* s01,
                                            float* s10, float* s11,
                                            const uint32_t af[2][4],
                                            const uint32_t b0[2][4],
                                            const uint32_t b1[2][4]) {
    mma_f16_z(s00, af[0], &b0[0][0]);
    mma_f16_z(s01, af[0], &b0[0][2]);
    mma_f16_z(s10, af[0], &b1[0][0]);
    mma_f16_z(s11, af[0], &b1[0][2]);
    mma_f16(s00, af[1], &b0[1][0]);
    mma_f16(s01, af[1], &b0[1][2]);
    mma_f16(s10, af[1], &b1[1][0]);
    mma_f16(s11, af[1], &b1[1][2]);
}

// ===========================================================================
// Merged conversion pass.
// Linear grid: [0,4096) X tiles (hi-only), [4096,4352) Wq (full),
// [4352,4416) WkWw (full).
// ===========================================================================
__global__ void __launch_bounds__(256)
cvt_all_kernel(const float* __restrict__ X, const float* __restrict__ Wq,
               const float* __restrict__ Wk, const float* __restrict__ Ww)
{
    const int bid = blockIdx.x;
    const int tid = threadIdx.x;

    if (bid < 4096) {
        const int rowTile = bid >> 6, kStep = bid & 63;
        const float* srcb = X + (size_t)(rowTile * 128) * C_ + kStep * 32;
        char* dst = g_xext + ((size_t)rowTile * 64 + kStep) * 16384;
#pragma unroll
        for (int j = 0; j < 2; j++) {
            const int idx = tid + j * 256;          // 0..511
            const int r = idx >> 2, c8 = (idx & 3) * 8;
            const float* s = srcb + (size_t)r * C_ + c8;
            cvt_store8_hi(dst, (uint32_t)(r * 128 + c8 * 2),
                          *(const float4*)s, *(const float4*)(s + 4));
        }
    } else if (bid < 4352) {
        const int t = bid - 4096;
        const int nTile = t >> 6, kStep = t & 63;
        const float* srcb = Wq + (size_t)(nTile * 128) * C_ + kStep * 32;
        char* dst = g_wqext + ((size_t)nTile * 64 + kStep) * 16384;
#pragma unroll
        for (int j = 0; j < 2; j++) {
            const int idx = tid + j * 256;
            const int r = idx >> 2, c8 = (idx & 3) * 8;
            const float* s = srcb + (size_t)r * C_ + c8;
            cvt_store8(dst, (uint32_t)(r * 128 + c8 * 2),
                       *(const float4*)s, *(const float4*)(s + 4));
        }
    } else {
        const int kStep = bid - 4352;
        if (tid >= 192) return;                     // 48 rows * 4 chunks
        const int r = tid >> 2, c8 = (tid & 3) * 8;
        const float* s = (r < 32) ? (Wk + (size_t)r * C_ + kStep * 32 + c8)
                                  : (Ww + (size_t)(r - 32) * C_ + kStep * 32 + c8);
        char* dst = g_kwext + (size_t)kStep * 6144;
        cvt_store8(dst, (uint32_t)(r * 128 + c8 * 2),
                   *(const float4*)s, *(const float4*)(s + 4));
    }
}

// ===========================================================================
// Unified projection kernel. grid (9, 64):
//   nT in 0..7 : Q-proj, 64 output cols (nT*64..), writes g_qext (hi-only)
//   nT == 8    : K+W proj (48 cols from g_kwext), writes g_kext (hi) + g_w
// CTA: 128(m) x 64(n), 256 threads, 8 warps 4(m) x 2(n), warp tile 32x32.
// 4-deep k=32 pipeline (4 x 24KB buffers, 3 cp groups in flight), 64 iters,
// 2 CTAs/SM.  Pure hi x hi; hi chunks only copied.
// ===========================================================================
__global__ void __launch_bounds__(256, 2)
proj_mma_kernel()
{
    extern __shared__ char dsm_raw[];
    char* dsm = (char*)(((uintptr_t)dsm_raw + 1023) & ~(uintptr_t)1023);

    const int tid  = threadIdx.x;
    const int wid  = tid >> 5;
    const int lane = tid & 31;
    const int nT    = blockIdx.x;           // 0..8
    const int mTile = blockIdx.y;           // 0..63
    const int m0 = (wid & 3) * 32;
    const int n0 = (wid >> 2) * 32;
    const bool iskw = (nT == 8);

    const char* xsrc = g_xext + (size_t)mTile * 64 * 16384;
    const char* wsrc = iskw ? g_kwext
                            : g_wqext + (size_t)(nT >> 1) * 64 * 16384 + (nT & 1) * 8192;
    const uint32_t wstep   = iskw ? 6144u : 16384u;  // bytes per k-step in gmem
    const int      wchunks = iskw ? 192 : 256;       // hi 16B chunks per k-step

    uint32_t sbase[4];
#pragma unroll
    for (int s = 0; s < 4; s++) sbase[s] = smem_u32(dsm + s * 24576);

    uint32_t aoff[2][2], boff[2][2];
    {
        const int arow = lane & 15, aseg = lane >> 4;
        const int brow = (lane & 7) + ((lane & 16) >> 1);
        const int bseg = (lane >> 3) & 1;
#pragma unroll
        for (int t = 0; t < 2; t++) {
#pragma unroll
            for (int ks = 0; ks < 2; ks++) {     // hi frags only, both sides
                aoff[t][ks] = sw128((uint32_t)((m0 + t * 16 + arow) * 128 +
                                               ks * 32 + aseg * 16));
                boff[t][ks] = 16384u + sw128((uint32_t)((n0 + t * 16 + brow) * 128 +
                                                        ks * 32 + bseg * 16));
            }
        }
    }

    // issue one k=32 stage into buffer stage&3; hi chunks only
    auto issue_stage = [&](int stage) {
        const uint32_t sb = sbase[stage & 3];
        const size_t ks = (size_t)stage;
#pragma unroll
        for (int j = 0; j < 2; j++) {
            const int idx = tid + j * 256;
            const uint32_t off = sw128((uint32_t)((idx >> 2) * 128 + (idx & 3) * 16));
            cp16(sb + off, xsrc + ks * 16384 + off);
        }
        if (tid < wchunks) {
            const uint32_t off = sw128((uint32_t)((tid >> 2) * 128 + (tid & 3) * 16));
            cp16(sb + 16384u + off, wsrc + ks * wstep + off);
        }
    };

    // prologue: stages 0,1,2 (three groups in flight)
#pragma unroll
    for (int s = 0; s < 3; s++) {
        issue_stage(s);
        CP_COMMIT();
    }

    float acc[2][4][4];
#pragma unroll
    for (int mt = 0; mt < 2; mt++)
#pragma unroll
        for (int nt = 0; nt < 4; nt++)
#pragma unroll
            for (int c = 0; c < 4; c++) acc[mt][nt][c] = 0.f;

#pragma unroll 1
    for (int it = 0; it < 64; it++) {
        CP_WAIT(2);          // all but newest 2 groups done => stage it done
        __syncthreads();     // data visible + all warps done with buf (it+3)&3
        if (it + 3 < 64) issue_stage(it + 3);
        CP_COMMIT();         // unconditional: keeps group count uniform

        const uint32_t cb = sbase[it & 3];
        uint32_t bfr[2][2][4];
#pragma unroll
        for (int ntp = 0; ntp < 2; ntp++)
#pragma unroll
            for (int ks = 0; ks < 2; ks++)
                ldsm4(bfr[ntp][ks], cb + boff[ntp][ks]);

#pragma unroll
        for (int mt = 0; mt < 2; mt++) {
            uint32_t af[2][4];
#pragma unroll
            for (int ks = 0; ks < 2; ks++) ldsm4(af[ks], cb + aoff[mt][ks]);
            mma_hh_x4(acc[mt][0], acc[mt][1], acc[mt][2], acc[mt][3],
                      af, bfr[0], bfr[1]);
        }
    }

    // epilogue
#pragma unroll
    for (int mt = 0; mt < 2; mt++)
#pragma unroll
        for (int rp = 0; rp < 2; rp++) {
            const int r = m0 + mt * 16 + (lane >> 2) + rp * 8;
#pragma unroll
            for (int nt = 0; nt < 4; nt++) {
                const int colL = n0 + nt * 8 + (lane & 3) * 2;
                const float v0 = acc[mt][nt][rp * 2];
                const float v1 = acc[mt][nt][rp * 2 + 1];
                if (!iskw) {
                    const int col = nT * 64 + colL;
                    const int head = col >> 5;
                    const int d = col & 31;
                    char* dst = g_qext + ((size_t)mTile * 16 + head) * 16384;
                    *(uint32_t*)(dst + sw128((uint32_t)(r * 128 + d * 2))) =
                        pack2h(v0, v1);                       // hi-only
                } else if (colL < 32) {
                    char* dst = g_kext + (size_t)mTile * 16384;
                    *(uint32_t*)(dst + sw128((uint32_t)(r * 128 + colL * 2))) =
                        pack2h(v0, v1);                       // hi-only
                } else if (colL < 48) {
                    *(float2*)(g_w + (size_t)(mTile * 128 + r) * H_ + (colL - 32)) =
                        make_float2(v0, v1);
                }
            }
        }
}

// ===========================================================================
// Fused scores+importance: out[b,q,k] = sum_h w[b,q,h]*relu(dot(q,k))
// TRANSPOSED TILING: CTA = 64(q) x 128(k), 256 threads, 8 warps 2(m)x4(n),
// warp tile 32x32, 2 CTAs/SM.  K 128-row hi tile resident; Q 64-row half
// tiles streamed 2 heads per stage (3 x 16KB ring) -> Q L2 traffic halved.
// Product = q_hi * k_hi (2 MMAs/frag-pair, first non-accumulating).
// ===========================================================================
__global__ void __launch_bounds__(256, 2)
fused_mma_kernel(float* __restrict__ out)
{
    extern __shared__ char dsm_raw[];
    char* dsm = (char*)(((uintptr_t)dsm_raw + 1023) & ~(uintptr_t)1023);
    char* Ks   = dsm;                   // 16KB (128 rows, hi holes)
    char* Qb   = dsm + 16384;           // 3 x 16KB (2 x 64-row head halves)
    float* w_s = (float*)(dsm + 65536); // 4KB (64 rows x 16)

    const int tid  = threadIdx.x;
    const int wid  = tid >> 5;
    const int lane = tid & 31;
    const int b  = blockIdx.z;
    const int kT = blockIdx.x;          // 0..31 (128-col k tiles)
    const int qT = blockIdx.y;          // 0..63 (64-row q tiles)
    const int q0 = qT * 64;
    const int k0 = kT * 128;
    const int m0 = (wid & 1) * 32;      // 2 warps in m (64 rows)
    const int n0 = (wid >> 1) * 32;     // 4 warps in n (128 cols)

    const char* qsrc = g_qext + (size_t)(b * 32 + (qT >> 1)) * 16 * 16384
                             + (size_t)(qT & 1) * 8192;   // + h*16384 per head
    const char* ksrc = g_kext + (size_t)(b * 32 + kT) * 16384;
    const float* wsrc = g_w + (size_t)(b * T_ + q0) * H_;

    const uint32_t ksb = smem_u32(Ks);
    const uint32_t wsb_smem = smem_u32(w_s);
    uint32_t qbase[3];
#pragma unroll
    for (int s = 0; s < 3; s++) qbase[s] = smem_u32(Qb + s * 16384);

    // Q head-pair loader: 512 hi chunks (2 heads x 64 rows x 4 chunks)
    // ring slot layout: head half at hh*8192, local rows 0..63.
    auto load_qpair = [&](uint32_t qb, int p) {
#pragma unroll
        for (int j = 0; j < 2; j++) {
            const int idx = tid + j * 256;          // 0..511
            const int hh = idx >> 8;                // 0/1
            const int rem = idx & 255;              // row*4 + chunk
            const uint32_t off = sw128((uint32_t)((rem >> 2) * 128 + (rem & 3) * 16));
            cp16(qb + (uint32_t)hh * 8192u + off,
                 qsrc + (size_t)(p * 2 + hh) * 16384 + off);
        }
    };

    // prologue: G0 = {K hi, w, headpair 0}, G1 = {headpair 1}
#pragma unroll
    for (int j = 0; j < 2; j++) {
        const int idx = tid + j * 256;              // 0..511 K hi chunks
        const uint32_t off = sw128((uint32_t)((idx >> 2) * 128 + (idx & 3) * 16));
        cp16(ksb + off, ksrc + off);
    }
    cp16(wsb_smem + (uint32_t)tid * 16, (const char*)wsrc + (uint32_t)tid * 16);  // 4KB: 256 x 16B
    load_qpair(qbase[0], 0);
    CP_COMMIT();
    load_qpair(qbase[1], 1);
    CP_COMMIT();

    uint32_t aoff[2][2];
    uint32_t baddr[2][2];
    {
        const int arow = lane & 15, aseg = lane >> 4;
        const int brow = (lane & 7) + ((lane & 16) >> 1);
        const int bseg = (lane >> 3) & 1;
#pragma unroll
        for (int t = 0; t < 2; t++) {
#pragma unroll
            for (int ks = 0; ks < 2; ks++) {     // hi frags only, both sides
                aoff[t][ks] = sw128((uint32_t)((m0 + t * 16 + arow) * 128 +
                                               ks * 32 + aseg * 16));
                baddr[t][ks] = ksb + sw128((uint32_t)((n0 + t * 16 + brow) * 128 +
                                                      ks * 32 + bseg * 16));
            }
        }
    }

    float acc[2][4][4];
#pragma unroll
    for (int mt = 0; mt < 2; mt++)
#pragma unroll
        for (int nt = 0; nt < 4; nt++)
#pragma unroll
            for (int c = 0; c < 4; c++) acc[mt][nt][c] = 0.f;

    CP_WAIT(1);       // G0 done: K, w, headpair 0
    __syncthreads();

    // K hi fragments register-resident (this warp's 32 n-cols of 128)
    uint32_t bfr[2][2][4];
#pragma unroll
    for (int ntp = 0; ntp < 2; ntp++)
#pragma unroll
        for (int ks = 0; ks < 2; ks++) ldsm4(bfr[ntp][ks], baddr[ntp][ks]);

    const int wrow0 = m0 + (lane >> 2);

#pragma unroll 1
    for (int p = 0; p < H_ / 2; p++) {      // head pairs
        if (p > 0) {
            if (p == H_ / 2 - 1) CP_WAIT(0); else CP_WAIT(1);
            __syncthreads();
        }
        if (p + 2 < H_ / 2)
            load_qpair(qbase[(p + 2) % 3], p + 2);
        CP_COMMIT();

        const uint32_t qb = qbase[p % 3];
#pragma unroll
        for (int hh = 0; hh < 2; hh++) {
            const int h = p * 2 + hh;
            const uint32_t qbh = qb + (uint32_t)hh * 8192u;
#pragma unroll
            for (int mt = 0; mt < 2; mt++) {
                uint32_t af[2][4];
#pragma unroll
                for (int ks = 0; ks < 2; ks++) ldsm4(af[ks], qbh + aoff[mt][ks]);

                const float wv0 = w_s[(wrow0 + mt * 16) * H_ + h];
                const float wv1 = w_s[(wrow0 + mt * 16 + 8) * H_ + h];

                float s[2][2][4];
                mma_hh_x4_z(s[0][0], s[0][1], s[1][0], s[1][1],
                            af, bfr[0], bfr[1]);

#pragma unroll
                for (int ntp = 0; ntp < 2; ntp++)
#pragma unroll
                    for (int q = 0; q < 2; q++) {
                        float* a = acc[mt][ntp * 2 + q];
                        const float* sv = s[ntp][q];
                        a[0] += wv0 * fmaxf(sv[0], 0.f);
                        a[1] += wv0 * fmaxf(sv[1], 0.f);
                        a[2] += wv1 * fmaxf(sv[2], 0.f);
                        a[3] += wv1 * fmaxf(sv[3], 0.f);
                    }
            }
        }
    }

    // epilogue: 64 rows x 128 cols
#pragma unroll
    for (int mt = 0; mt < 2; mt++)
#pragma unroll
        for (int rp = 0; rp < 2; rp++) {
            const int row = q0 + m0 + mt * 16 + (lane >> 2) + rp * 8;
            float* op = out + (size_t)(b * T_ + row) * T_ + k0 + n0 + (lane & 3) * 2;
#pragma unroll
            for (int nt = 0; nt < 4; nt++)
                *(float2*)(op + nt * 8) =
                    make_float2(acc[mt][nt][rp * 2], acc[mt][nt][rp * 2 + 1]);
        }
}

// ===========================================================================
extern "C" void kernel_launch(void* const* d_in, const int* in_sizes, int n_in,
                              void* d_out, int out_size)
{
    (void)in_sizes; (void)n_in; (void)out_size;
    const float* x  = (const float*)d_in[0];
    const float* Wq = (const float*)d_in[1];
    const float* Wk = (const float*)d_in[2];
    const float* Ww = (const float*)d_in[3];
    float* out = (float*)d_out;

    static bool attr_done = false;
    if (!attr_done) {
        cudaFuncSetAttribute(proj_mma_kernel,
                             cudaFuncAttributeMaxDynamicSharedMemorySize, 99328);
        cudaFuncSetAttribute(fused_mma_kernel,
                             cudaFuncAttributeMaxDynamicSharedMemorySize, 70656);
        attr_done = true;
    }

    cvt_all_kernel<<<4416, 256>>>(x, Wq, Wk, Ww);
    proj_mma_kernel<<<dim3(9, 64), 256, 99328>>>();
    fused_mma_kernel<<<dim3(T_ / 128, T_ / 64, B_), 256, 70656>>>(out);
}